// round 1
// baseline (speedup 1.0000x reference)
#include <cuda_runtime.h>
#include <math.h>

#define H2   512
#define NB   8
#define TDEC 64
#define TENC 512
#define MDEC (NB*TDEC)   // 512 rows
#define MENC (NB*TENC)   // 4096 rows

// ---------------- scratch (device globals; no allocation allowed) ----------
__device__ float g_dp[MDEC*H2];     // dec @ W_dec^T
__device__ float g_ep[MENC*H2];     // enc @ W_enc^T
__device__ float g_A [MDEC*H2];     // exp(dp - mdp)
__device__ float g_E [MENC*H2];     // exp(ep + bias - mep)
__device__ float g_mdp[MDEC];
__device__ float g_mep[MENC];
__device__ float g_L [MDEC*TENC];   // [b, i, j] logsumexp values
__device__ float g_Senc[NB*H2];     // sum_j enc[b,j,d]
__device__ float g_Cc  [NB*H2];     // sum_j ep[b,j,d]*enc[b,j,d]

// ---------------------------------------------------------------------------
// C = A * B^T, A: MxK row-major (lda), B: NxK row-major (ldb), C row-major.
// 64x64 tile, BK=16, 256 threads, 4x4 per-thread microtile.
// EPI==0: plain store.  EPI==1: C = mrow[m] + mcol[n] + log(acc)  (for L).
// Batched over blockIdx.z with element strides.
// ---------------------------------------------------------------------------
template<int EPI>
__global__ void __launch_bounds__(256) gemm_tt(
    const float* __restrict__ A, int lda, long sA,
    const float* __restrict__ Bm, int ldb, long sB,
    float* __restrict__ Cm, int ldc, long sC,
    int K,
    const float* __restrict__ mrow, int sMr,
    const float* __restrict__ mcol, int sMc)
{
    const int bz = blockIdx.z;
    A  += (long)bz * sA;
    Bm += (long)bz * sB;
    Cm += (long)bz * sC;

    __shared__ float As[16][68];   // [k][m], +4 pad keeps 16B alignment
    __shared__ float Bs[16][68];   // [k][n]

    const int t  = threadIdx.x;
    const int tx = t & 15;         // column group
    const int ty = t >> 4;         // row group
    const int loadRow = t >> 2;            // 0..63
    const int loadK   = (t & 3) << 2;      // 0,4,8,12

    const float* Aload = A  + (long)(blockIdx.y*64 + loadRow)*lda + loadK;
    const float* Bload = Bm + (long)(blockIdx.x*64 + loadRow)*ldb + loadK;

    float acc[4][4];
#pragma unroll
    for (int i = 0; i < 4; i++)
#pragma unroll
        for (int j = 0; j < 4; j++) acc[i][j] = 0.f;

    for (int k0 = 0; k0 < K; k0 += 16) {
        float4 av = *(const float4*)(Aload + k0);
        float4 bv = *(const float4*)(Bload + k0);
        As[loadK+0][loadRow] = av.x; As[loadK+1][loadRow] = av.y;
        As[loadK+2][loadRow] = av.z; As[loadK+3][loadRow] = av.w;
        Bs[loadK+0][loadRow] = bv.x; Bs[loadK+1][loadRow] = bv.y;
        Bs[loadK+2][loadRow] = bv.z; Bs[loadK+3][loadRow] = bv.w;
        __syncthreads();
#pragma unroll
        for (int kk = 0; kk < 16; kk++) {
            float4 a = *(const float4*)&As[kk][ty*4];
            float4 b = *(const float4*)&Bs[kk][tx*4];
            acc[0][0] += a.x*b.x; acc[0][1] += a.x*b.y; acc[0][2] += a.x*b.z; acc[0][3] += a.x*b.w;
            acc[1][0] += a.y*b.x; acc[1][1] += a.y*b.y; acc[1][2] += a.y*b.z; acc[1][3] += a.y*b.w;
            acc[2][0] += a.z*b.x; acc[2][1] += a.z*b.y; acc[2][2] += a.z*b.z; acc[2][3] += a.z*b.w;
            acc[3][0] += a.w*b.x; acc[3][1] += a.w*b.y; acc[3][2] += a.w*b.z; acc[3][3] += a.w*b.w;
        }
        __syncthreads();
    }

    const int m0 = blockIdx.y*64 + ty*4;
    const int n0 = blockIdx.x*64 + tx*4;
#pragma unroll
    for (int i = 0; i < 4; i++) {
        float mr = 0.f;
        if (EPI == 1) mr = mrow[(long)bz*sMr + m0 + i];
#pragma unroll
        for (int j = 0; j < 4; j++) {
            float v = acc[i][j];
            if (EPI == 1) v = mr + mcol[(long)bz*sMc + n0 + j] + __logf(v);
            Cm[(long)(m0+i)*ldc + n0 + j] = v;
        }
    }
}

// ---------------------------------------------------------------------------
// Per-row max then exp: outE[r,o] = exp(in[r,o] (+bias[o]) - max_row),
// outM[r] = max_row.  512 cols, 256 threads (2 cols/thread), 1 block/row.
// ---------------------------------------------------------------------------
__global__ void __launch_bounds__(256) rowmax_exp(
    const float* __restrict__ in, const float* __restrict__ bias,
    float* __restrict__ outE, float* __restrict__ outM)
{
    const int r = blockIdx.x;
    const int t = threadIdx.x;
    float v0 = in[(long)r*H2 + t];
    float v1 = in[(long)r*H2 + t + 256];
    if (bias) { v0 += bias[t]; v1 += bias[t + 256]; }
    float m = fmaxf(v0, v1);
#pragma unroll
    for (int o = 16; o; o >>= 1) m = fmaxf(m, __shfl_xor_sync(0xffffffffu, m, o));
    __shared__ float sm[8];
    if ((t & 31) == 0) sm[t >> 5] = m;
    __syncthreads();
    float M = sm[0];
#pragma unroll
    for (int w = 1; w < 8; w++) M = fmaxf(M, sm[w]);
    outE[(long)r*H2 + t]       = __expf(v0 - M);
    outE[(long)r*H2 + t + 256] = __expf(v1 - M);
    if (t == 0) outM[r] = M;
}

// ---------------------------------------------------------------------------
// Per-batch column reductions over j: Senc[b,d] = sum_j enc, Cc[b,d] = sum_j ep*enc
// ---------------------------------------------------------------------------
__global__ void __launch_bounds__(256) batch_colreduce(
    const float* __restrict__ enc, const float* __restrict__ ep,
    float* __restrict__ Senc, float* __restrict__ Cc)
{
    const int b = blockIdx.y;
    const int d = blockIdx.x * 256 + threadIdx.x;
    const float* e = enc + (long)b*TENC*H2 + d;
    const float* p = ep  + (long)b*TENC*H2 + d;
    float s = 0.f, c = 0.f;
    for (int j = 0; j < TENC; j++) {
        float ev = e[(long)j*H2];
        s += ev;
        c += p[(long)j*H2] * ev;
    }
    Senc[(long)b*H2 + d] = s;
    Cc  [(long)b*H2 + d] = c;
}

// ---------------------------------------------------------------------------
// Final: out[b,i,d] = (dp[b,i,d]+bias[d])*Senc[b,d] + Cc[b,d] - sum_j L[b,i,j]*enc[b,j,d]
// NN GEMM per batch: L (64x512, j-contig) @ enc (512x512, d-contig).
// ---------------------------------------------------------------------------
__global__ void __launch_bounds__(256) gemm_nn_final(
    const float* __restrict__ Lm, const float* __restrict__ enc,
    const float* __restrict__ dp, const float* __restrict__ bias,
    const float* __restrict__ Senc, const float* __restrict__ Cc,
    float* __restrict__ out)
{
    const int bz = blockIdx.z;
    const float* Ab = Lm  + (long)bz*TDEC*TENC;   // 64 x 512
    const float* Bb = enc + (long)bz*TENC*H2;     // 512 x 512

    __shared__ float As[16][68];   // [k][m]
    __shared__ float Bs[16][68];   // [k][n]

    const int t  = threadIdx.x;
    const int tx = t & 15;
    const int ty = t >> 4;
    const int aRow = t >> 2;             // 0..63
    const int aK   = (t & 3) << 2;       // 0,4,8,12
    const int bK   = t >> 4;             // 0..15
    const int bCol = (t & 15) << 2;      // 0..60

    float acc[4][4];
#pragma unroll
    for (int i = 0; i < 4; i++)
#pragma unroll
        for (int j = 0; j < 4; j++) acc[i][j] = 0.f;

    const int nBase = blockIdx.x * 64;
    for (int k0 = 0; k0 < TENC; k0 += 16) {
        float4 av = *(const float4*)(Ab + (long)aRow*TENC + k0 + aK);
        float4 bv = *(const float4*)(Bb + (long)(k0 + bK)*H2 + nBase + bCol);
        As[aK+0][aRow] = av.x; As[aK+1][aRow] = av.y;
        As[aK+2][aRow] = av.z; As[aK+3][aRow] = av.w;
        *(float4*)&Bs[bK][bCol] = bv;
        __syncthreads();
#pragma unroll
        for (int kk = 0; kk < 16; kk++) {
            float4 a = *(const float4*)&As[kk][ty*4];
            float4 b = *(const float4*)&Bs[kk][tx*4];
            acc[0][0] += a.x*b.x; acc[0][1] += a.x*b.y; acc[0][2] += a.x*b.z; acc[0][3] += a.x*b.w;
            acc[1][0] += a.y*b.x; acc[1][1] += a.y*b.y; acc[1][2] += a.y*b.z; acc[1][3] += a.y*b.w;
            acc[2][0] += a.z*b.x; acc[2][1] += a.z*b.y; acc[2][2] += a.z*b.z; acc[2][3] += a.z*b.w;
            acc[3][0] += a.w*b.x; acc[3][1] += a.w*b.y; acc[3][2] += a.w*b.z; acc[3][3] += a.w*b.w;
        }
        __syncthreads();
    }

    const int i0 = ty*4;
    const int n0 = nBase + tx*4;
#pragma unroll
    for (int i = 0; i < 4; i++) {
        const int gr = bz*TDEC + i0 + i;          // global decoder row
#pragma unroll
        for (int j = 0; j < 4; j++) {
            const int d = n0 + j;
            float v = (dp[(long)gr*H2 + d] + bias[d]) * Senc[(long)bz*H2 + d]
                      + Cc[(long)bz*H2 + d] - acc[i][j];
            out[(long)gr*H2 + d] = v;
        }
    }
}

// ---------------------------------------------------------------------------
extern "C" void kernel_launch(void* const* d_in, const int* in_sizes, int n_in,
                              void* d_out, int out_size)
{
    const float* enc  = (const float*)d_in[0];   // (8, 512, 512)
    const float* dec  = (const float*)d_in[1];   // (8, 64, 512)
    const float* W    = (const float*)d_in[2];   // (512, 1024)
    const float* bias = (const float*)d_in[3];   // (512,)
    float* out = (float*)d_out;                  // (8, 64, 512)

    float *dp, *ep, *A, *E, *mdp, *mep, *L, *Senc, *Cc;
    cudaGetSymbolAddress((void**)&dp,   g_dp);
    cudaGetSymbolAddress((void**)&ep,   g_ep);
    cudaGetSymbolAddress((void**)&A,    g_A);
    cudaGetSymbolAddress((void**)&E,    g_E);
    cudaGetSymbolAddress((void**)&mdp,  g_mdp);
    cudaGetSymbolAddress((void**)&mep,  g_mep);
    cudaGetSymbolAddress((void**)&L,    g_L);
    cudaGetSymbolAddress((void**)&Senc, g_Senc);
    cudaGetSymbolAddress((void**)&Cc,   g_Cc);

    dim3 blk(256);

    // dp = dec @ W_dec^T   (512 x 512, K=512)
    gemm_tt<0><<<dim3(8, 8, 1), blk>>>(dec, H2, 0, W, 2*H2, 0, dp, H2, 0, H2,
                                       nullptr, 0, nullptr, 0);
    // ep = enc @ W_enc^T   (4096 x 512, K=512)
    gemm_tt<0><<<dim3(8, 64, 1), blk>>>(enc, H2, 0, W + H2, 2*H2, 0, ep, H2, 0, H2,
                                        nullptr, 0, nullptr, 0);
    // A = exp(dp - rowmax), E = exp(ep + bias - rowmax)
    rowmax_exp<<<MDEC, 256>>>(dp, nullptr, A, mdp);
    rowmax_exp<<<MENC, 256>>>(ep, bias, E, mep);
    // Senc, Cc column reductions
    batch_colreduce<<<dim3(2, NB), 256>>>(enc, ep, Senc, Cc);
    // L[b,i,j] = mdp + mep + log( A[b] @ E[b]^T )   (batched 64x512, K=512)
    gemm_tt<1><<<dim3(8, 1, NB), blk>>>(A, H2, (long)TDEC*H2,
                                        E, H2, (long)TENC*H2,
                                        L, TENC, (long)TDEC*TENC, H2,
                                        mdp, TDEC, mep, TENC);
    // context = (dp+bias)*Senc + Cc - L[b] @ enc[b]
    gemm_nn_final<<<dim3(8, 1, NB), blk>>>(L, enc, dp, bias, Senc, Cc, out);
}

// round 2
// speedup vs baseline: 1.3330x; 1.3330x over previous
#include <cuda_runtime.h>
#include <math.h>

#define H2   512
#define NB   8
#define TDEC 64
#define TENC 512
#define MDEC (NB*TDEC)   // 512
#define MENC (NB*TENC)   // 4096

// ---------------- scratch ----------------
__device__ float g_dp[MDEC*H2];
__device__ float g_ep[MENC*H2];
__device__ float g_A [MDEC*H2];
__device__ float g_E [MENC*H2];
__device__ float g_mdp[MDEC];
__device__ float g_mep[MENC];
__device__ float g_L [MDEC*TENC];
__device__ float g_Senc[NB*H2];
__device__ float g_Cc  [NB*H2];
__device__ float g_partS[NB*8*H2];
__device__ float g_partC[NB*8*H2];

// ---------------- f32x2 primitives ----------------
__device__ __forceinline__ void fma2(unsigned long long &d, unsigned long long a, unsigned long long b){
    asm("fma.rn.f32x2 %0, %1, %2, %0;" : "+l"(d) : "l"(a), "l"(b));
}
__device__ __forceinline__ unsigned long long packdup(float x){
    unsigned long long r; asm("mov.b64 %0, {%1, %1};" : "=l"(r) : "f"(x)); return r;
}
__device__ __forceinline__ float2 unpack2(unsigned long long v){
    float2 f; asm("mov.b64 {%0, %1}, %2;" : "=f"(f.x), "=f"(f.y) : "l"(v)); return f;
}
__device__ __forceinline__ unsigned long long d2u(double x){
    return (unsigned long long)__double_as_longlong(x);
}

// ---------------------------------------------------------------------------
// BIG GEMM: C = A * B^T, 128x128 tile, BK=16, 256 thr, 8x8 micro (f32x2),
// double-buffered smem. A: MxK (lda), B: NxK (ldb), C row-major.
// ---------------------------------------------------------------------------
__global__ void __launch_bounds__(256) gemm_big(
    const float* __restrict__ A, int lda,
    const float* __restrict__ B, int ldb,
    float* __restrict__ C, int ldc, int K)
{
    __shared__ float As[2][16][132];
    __shared__ float Bs[2][16][132];
    const int t  = threadIdx.x;
    const int tx = t & 15, ty = t >> 4;
    const int m0 = blockIdx.y * 128, n0 = blockIdx.x * 128;
    const int row0 = t >> 2;
    const int kq   = (t & 3) << 2;

    const float* Ap0 = A + (long)(m0 + row0     ) * lda + kq;
    const float* Ap1 = A + (long)(m0 + row0 + 64) * lda + kq;
    const float* Bp0 = B + (long)(n0 + row0     ) * ldb + kq;
    const float* Bp1 = B + (long)(n0 + row0 + 64) * ldb + kq;

    unsigned long long acc[8][4];
#pragma unroll
    for (int i = 0; i < 8; i++)
#pragma unroll
        for (int j = 0; j < 4; j++) acc[i][j] = 0ull;

    float4 ra0 = *(const float4*)Ap0;
    float4 ra1 = *(const float4*)Ap1;
    float4 rb0 = *(const float4*)Bp0;
    float4 rb1 = *(const float4*)Bp1;

    // store tile 0
    {
        As[0][kq+0][row0]=ra0.x; As[0][kq+1][row0]=ra0.y; As[0][kq+2][row0]=ra0.z; As[0][kq+3][row0]=ra0.w;
        As[0][kq+0][row0+64]=ra1.x; As[0][kq+1][row0+64]=ra1.y; As[0][kq+2][row0+64]=ra1.z; As[0][kq+3][row0+64]=ra1.w;
        Bs[0][kq+0][row0]=rb0.x; Bs[0][kq+1][row0]=rb0.y; Bs[0][kq+2][row0]=rb0.z; Bs[0][kq+3][row0]=rb0.w;
        Bs[0][kq+0][row0+64]=rb1.x; Bs[0][kq+1][row0+64]=rb1.y; Bs[0][kq+2][row0+64]=rb1.z; Bs[0][kq+3][row0+64]=rb1.w;
    }
    __syncthreads();

    int buf = 0;
    for (int k0 = 0; k0 < K; k0 += 16) {
        const bool more = (k0 + 16) < K;
        if (more) {
            ra0 = *(const float4*)(Ap0 + k0 + 16);
            ra1 = *(const float4*)(Ap1 + k0 + 16);
            rb0 = *(const float4*)(Bp0 + k0 + 16);
            rb1 = *(const float4*)(Bp1 + k0 + 16);
        }
#pragma unroll
        for (int kk = 0; kk < 16; kk++) {
            const float* as = &As[buf][kk][ty*8];
            float4 a0 = *(const float4*)as;
            float4 a1 = *(const float4*)(as + 4);
            double2 b01 = *(const double2*)&Bs[buf][kk][tx*8];
            double2 b23 = *(const double2*)&Bs[buf][kk][tx*8 + 4];
            unsigned long long bp[4] = { d2u(b01.x), d2u(b01.y), d2u(b23.x), d2u(b23.y) };
            unsigned long long ap[8] = { packdup(a0.x), packdup(a0.y), packdup(a0.z), packdup(a0.w),
                                         packdup(a1.x), packdup(a1.y), packdup(a1.z), packdup(a1.w) };
#pragma unroll
            for (int i = 0; i < 8; i++)
#pragma unroll
                for (int j = 0; j < 4; j++) fma2(acc[i][j], ap[i], bp[j]);
        }
        if (more) {
            const int nb = buf ^ 1;
            As[nb][kq+0][row0]=ra0.x; As[nb][kq+1][row0]=ra0.y; As[nb][kq+2][row0]=ra0.z; As[nb][kq+3][row0]=ra0.w;
            As[nb][kq+0][row0+64]=ra1.x; As[nb][kq+1][row0+64]=ra1.y; As[nb][kq+2][row0+64]=ra1.z; As[nb][kq+3][row0+64]=ra1.w;
            Bs[nb][kq+0][row0]=rb0.x; Bs[nb][kq+1][row0]=rb0.y; Bs[nb][kq+2][row0]=rb0.z; Bs[nb][kq+3][row0]=rb0.w;
            Bs[nb][kq+0][row0+64]=rb1.x; Bs[nb][kq+1][row0+64]=rb1.y; Bs[nb][kq+2][row0+64]=rb1.z; Bs[nb][kq+3][row0+64]=rb1.w;
            __syncthreads();
            buf = nb;
        }
    }

#pragma unroll
    for (int i = 0; i < 8; i++) {
        float* cr = C + (long)(m0 + ty*8 + i) * ldc + n0 + tx*8;
#pragma unroll
        for (int j = 0; j < 4; j++) {
            float2 v = unpack2(acc[i][j]);
            *(float2*)(cr + 2*j) = v;
        }
    }
}

// ---------------------------------------------------------------------------
// 64x64 TT GEMM (f32x2, 4x4 micro, double-buffered), batched via blockIdx.z.
// EPI==1: C = mrow[m] + mcol[n] + log(acc)
// ---------------------------------------------------------------------------
template<int EPI>
__global__ void __launch_bounds__(256) gemm_tt64(
    const float* __restrict__ A, int lda, long sA,
    const float* __restrict__ Bm, int ldb, long sB,
    float* __restrict__ Cm, int ldc, long sC, int K,
    const float* __restrict__ mrow, int sMr,
    const float* __restrict__ mcol, int sMc)
{
    const int bz = blockIdx.z;
    A  += (long)bz * sA;
    Bm += (long)bz * sB;
    Cm += (long)bz * sC;

    __shared__ float As[2][16][68];
    __shared__ float Bs[2][16][68];
    const int t  = threadIdx.x;
    const int tx = t & 15, ty = t >> 4;
    const int row0 = t >> 2;
    const int kq   = (t & 3) << 2;

    const float* Ap = A  + (long)(blockIdx.y*64 + row0) * lda + kq;
    const float* Bp = Bm + (long)(blockIdx.x*64 + row0) * ldb + kq;

    unsigned long long acc[4][2];
#pragma unroll
    for (int i = 0; i < 4; i++) { acc[i][0] = 0ull; acc[i][1] = 0ull; }

    float4 ra = *(const float4*)Ap;
    float4 rb = *(const float4*)Bp;
    As[0][kq+0][row0]=ra.x; As[0][kq+1][row0]=ra.y; As[0][kq+2][row0]=ra.z; As[0][kq+3][row0]=ra.w;
    Bs[0][kq+0][row0]=rb.x; Bs[0][kq+1][row0]=rb.y; Bs[0][kq+2][row0]=rb.z; Bs[0][kq+3][row0]=rb.w;
    __syncthreads();

    int buf = 0;
    for (int k0 = 0; k0 < K; k0 += 16) {
        const bool more = (k0 + 16) < K;
        if (more) {
            ra = *(const float4*)(Ap + k0 + 16);
            rb = *(const float4*)(Bp + k0 + 16);
        }
#pragma unroll
        for (int kk = 0; kk < 16; kk++) {
            float4 a = *(const float4*)&As[buf][kk][ty*4];
            double2 b = *(const double2*)&Bs[buf][kk][tx*4];
            unsigned long long bp0 = d2u(b.x), bp1 = d2u(b.y);
            unsigned long long ap0 = packdup(a.x), ap1 = packdup(a.y);
            unsigned long long ap2 = packdup(a.z), ap3 = packdup(a.w);
            fma2(acc[0][0], ap0, bp0); fma2(acc[0][1], ap0, bp1);
            fma2(acc[1][0], ap1, bp0); fma2(acc[1][1], ap1, bp1);
            fma2(acc[2][0], ap2, bp0); fma2(acc[2][1], ap2, bp1);
            fma2(acc[3][0], ap3, bp0); fma2(acc[3][1], ap3, bp1);
        }
        if (more) {
            const int nb = buf ^ 1;
            As[nb][kq+0][row0]=ra.x; As[nb][kq+1][row0]=ra.y; As[nb][kq+2][row0]=ra.z; As[nb][kq+3][row0]=ra.w;
            Bs[nb][kq+0][row0]=rb.x; Bs[nb][kq+1][row0]=rb.y; Bs[nb][kq+2][row0]=rb.z; Bs[nb][kq+3][row0]=rb.w;
            __syncthreads();
            buf = nb;
        }
    }

    const int m0  = blockIdx.y*64 + ty*4;
    const int n0g = blockIdx.x*64 + tx*4;
#pragma unroll
    for (int i = 0; i < 4; i++) {
        float mr = 0.f;
        if (EPI == 1) mr = mrow[(long)bz*sMr + m0 + i];
        float* cr = Cm + (long)(m0 + i) * ldc + n0g;
#pragma unroll
        for (int j = 0; j < 2; j++) {
            float2 v = unpack2(acc[i][j]);
            if (EPI == 1) {
                v.x = mr + mcol[(long)bz*sMc + n0g + 2*j    ] + __logf(v.x);
                v.y = mr + mcol[(long)bz*sMc + n0g + 2*j + 1] + __logf(v.y);
            }
            *(float2*)(cr + 2*j) = v;
        }
    }
}

// ---------------------------------------------------------------------------
// Final NN GEMM (f32x2): out = (dp+bias)*Senc + Cc - L @ enc, per batch.
// ---------------------------------------------------------------------------
__global__ void __launch_bounds__(256) gemm_nn_final(
    const float* __restrict__ Lm, const float* __restrict__ enc,
    const float* __restrict__ dp, const float* __restrict__ bias,
    const float* __restrict__ Senc, const float* __restrict__ Cc,
    float* __restrict__ out)
{
    const int bz = blockIdx.z;
    const float* Ab = Lm  + (long)bz*TDEC*TENC;
    const float* Bb = enc + (long)bz*TENC*H2;

    __shared__ float As[2][16][68];
    __shared__ float Bs[2][16][68];
    const int t  = threadIdx.x;
    const int tx = t & 15, ty = t >> 4;
    const int aRow = t >> 2, aK = (t & 3) << 2;
    const int bK = t >> 4, bCol = (t & 15) << 2;
    const int nBase = blockIdx.x * 64;

    const float* ApL = Ab + (long)aRow*TENC + aK;
    const float* BpL = Bb + (long)bK*H2 + nBase + bCol;

    unsigned long long acc[4][2];
#pragma unroll
    for (int i = 0; i < 4; i++) { acc[i][0] = 0ull; acc[i][1] = 0ull; }

    float4 ra = *(const float4*)ApL;
    float4 rb = *(const float4*)BpL;
    As[0][aK+0][aRow]=ra.x; As[0][aK+1][aRow]=ra.y; As[0][aK+2][aRow]=ra.z; As[0][aK+3][aRow]=ra.w;
    *(float4*)&Bs[0][bK][bCol] = rb;
    __syncthreads();

    int buf = 0;
    for (int k0 = 0; k0 < TENC; k0 += 16) {
        const bool more = (k0 + 16) < TENC;
        if (more) {
            ra = *(const float4*)(ApL + k0 + 16);
            rb = *(const float4*)(BpL + (long)(k0 + 16)*H2);
        }
#pragma unroll
        for (int kk = 0; kk < 16; kk++) {
            float4 a = *(const float4*)&As[buf][kk][ty*4];
            double2 b = *(const double2*)&Bs[buf][kk][tx*4];
            unsigned long long bp0 = d2u(b.x), bp1 = d2u(b.y);
            unsigned long long ap0 = packdup(a.x), ap1 = packdup(a.y);
            unsigned long long ap2 = packdup(a.z), ap3 = packdup(a.w);
            fma2(acc[0][0], ap0, bp0); fma2(acc[0][1], ap0, bp1);
            fma2(acc[1][0], ap1, bp0); fma2(acc[1][1], ap1, bp1);
            fma2(acc[2][0], ap2, bp0); fma2(acc[2][1], ap2, bp1);
            fma2(acc[3][0], ap3, bp0); fma2(acc[3][1], ap3, bp1);
        }
        if (more) {
            const int nb = buf ^ 1;
            As[nb][aK+0][aRow]=ra.x; As[nb][aK+1][aRow]=ra.y; As[nb][aK+2][aRow]=ra.z; As[nb][aK+3][aRow]=ra.w;
            *(float4*)&Bs[nb][bK][bCol] = rb;
            __syncthreads();
            buf = nb;
        }
    }

    const int i0 = ty*4;
    const int n0 = nBase + tx*4;
#pragma unroll
    for (int i = 0; i < 4; i++) {
        const int gr = bz*TDEC + i0 + i;
#pragma unroll
        for (int j = 0; j < 2; j++) {
            float2 v = unpack2(acc[i][j]);
            const int d0 = n0 + 2*j;
            float o0 = (dp[(long)gr*H2 + d0  ] + bias[d0  ]) * Senc[(long)bz*H2 + d0  ] + Cc[(long)bz*H2 + d0  ] - v.x;
            float o1 = (dp[(long)gr*H2 + d0+1] + bias[d0+1]) * Senc[(long)bz*H2 + d0+1] + Cc[(long)bz*H2 + d0+1] - v.y;
            float2 ov; ov.x = o0; ov.y = o1;
            *(float2*)(out + (long)gr*H2 + d0) = ov;
        }
    }
}

// ---------------------------------------------------------------------------
// rowmax + exp: 2 rows per 256-thread block, float4.
// ---------------------------------------------------------------------------
__global__ void __launch_bounds__(256) rowmax_exp2(
    const float* __restrict__ in, const float* __restrict__ bias,
    float* __restrict__ outE, float* __restrict__ outM)
{
    const int t = threadIdx.x;
    const int half = t >> 7;
    const int lane128 = t & 127;
    const long r = (long)blockIdx.x*2 + half;
    float4 v = *(const float4*)(in + r*H2 + lane128*4);
    if (bias) {
        float4 bv = *(const float4*)(bias + lane128*4);
        v.x += bv.x; v.y += bv.y; v.z += bv.z; v.w += bv.w;
    }
    float m = fmaxf(fmaxf(v.x, v.y), fmaxf(v.z, v.w));
#pragma unroll
    for (int o = 16; o; o >>= 1) m = fmaxf(m, __shfl_xor_sync(0xffffffffu, m, o));
    __shared__ float sm[8];
    if ((t & 31) == 0) sm[t >> 5] = m;
    __syncthreads();
    const int wb = half*4;
    float M = fmaxf(fmaxf(sm[wb], sm[wb+1]), fmaxf(sm[wb+2], sm[wb+3]));
    float4 e;
    e.x = __expf(v.x - M); e.y = __expf(v.y - M);
    e.z = __expf(v.z - M); e.w = __expf(v.w - M);
    *(float4*)(outE + r*H2 + lane128*4) = e;
    if (lane128 == 0) outM[r] = M;
}

// ---------------------------------------------------------------------------
// Column reductions: split over j (8 splits) then combine.
// ---------------------------------------------------------------------------
__global__ void __launch_bounds__(256) colreduce_part(
    const float* __restrict__ enc, const float* __restrict__ ep,
    float* __restrict__ partS, float* __restrict__ partC)
{
    const int b  = blockIdx.y;
    const int js = blockIdx.z;
    const int d  = blockIdx.x * 256 + threadIdx.x;
    const float* e = enc + (long)b*TENC*H2 + (long)js*64*H2 + d;
    const float* p = ep  + (long)b*TENC*H2 + (long)js*64*H2 + d;
    float s = 0.f, c = 0.f;
#pragma unroll 4
    for (int j = 0; j < 64; j++) {
        float ev = e[(long)j*H2];
        s += ev;
        c += p[(long)j*H2] * ev;
    }
    partS[((long)b*8 + js)*H2 + d] = s;
    partC[((long)b*8 + js)*H2 + d] = c;
}

__global__ void __launch_bounds__(256) colreduce_fin(
    const float* __restrict__ partS, const float* __restrict__ partC,
    float* __restrict__ Senc, float* __restrict__ Cc)
{
    const int idx = blockIdx.x * 256 + threadIdx.x;   // b*512 + d
    const int b = idx >> 9, d = idx & 511;
    float s = 0.f, c = 0.f;
#pragma unroll
    for (int js = 0; js < 8; js++) {
        s += partS[((long)b*8 + js)*H2 + d];
        c += partC[((long)b*8 + js)*H2 + d];
    }
    Senc[idx] = s;
    Cc[idx]   = c;
}

// ---------------------------------------------------------------------------
extern "C" void kernel_launch(void* const* d_in, const int* in_sizes, int n_in,
                              void* d_out, int out_size)
{
    const float* enc  = (const float*)d_in[0];
    const float* dec  = (const float*)d_in[1];
    const float* W    = (const float*)d_in[2];
    const float* bias = (const float*)d_in[3];
    float* out = (float*)d_out;

    float *dp, *ep, *A, *E, *mdp, *mep, *L, *Senc, *Cc, *pS, *pC;
    cudaGetSymbolAddress((void**)&dp,   g_dp);
    cudaGetSymbolAddress((void**)&ep,   g_ep);
    cudaGetSymbolAddress((void**)&A,    g_A);
    cudaGetSymbolAddress((void**)&E,    g_E);
    cudaGetSymbolAddress((void**)&mdp,  g_mdp);
    cudaGetSymbolAddress((void**)&mep,  g_mep);
    cudaGetSymbolAddress((void**)&L,    g_L);
    cudaGetSymbolAddress((void**)&Senc, g_Senc);
    cudaGetSymbolAddress((void**)&Cc,   g_Cc);
    cudaGetSymbolAddress((void**)&pS,   g_partS);
    cudaGetSymbolAddress((void**)&pC,   g_partC);

    // dp = dec @ W_dec^T  (512x512, K=512)
    gemm_tt64<0><<<dim3(8, 8, 1), 256>>>(dec, H2, 0, W, 2*H2, 0, dp, H2, 0, H2,
                                         nullptr, 0, nullptr, 0);
    // ep = enc @ W_enc^T  (4096x512, K=512) — big tile
    gemm_big<<<dim3(4, 32), 256>>>(enc, H2, W + H2, 2*H2, ep, H2, H2);
    // exp passes
    rowmax_exp2<<<MDEC/2, 256>>>(dp, nullptr, A, mdp);
    rowmax_exp2<<<MENC/2, 256>>>(ep, bias, E, mep);
    // column reductions (needs ep)
    colreduce_part<<<dim3(2, NB, 8), 256>>>(enc, ep, pS, pC);
    colreduce_fin<<<16, 256>>>(pS, pC, Senc, Cc);
    // L = mdp + mep + log(A @ E^T) per batch
    gemm_tt64<1><<<dim3(8, 1, NB), 256>>>(A, H2, (long)TDEC*H2,
                                          E, H2, (long)TENC*H2,
                                          L, TENC, (long)TDEC*TENC, H2,
                                          mdp, TDEC, mep, TENC);
    // context
    gemm_nn_final<<<dim3(8, 1, NB), 256>>>(L, enc, dp, bias, Senc, Cc, out);
}

// round 4
// speedup vs baseline: 1.5063x; 1.1300x over previous
#include <cuda_runtime.h>
#include <cuda_bf16.h>
#include <cstdint>
#include <math.h>

#define H2   512
#define NB   8
#define TDEC 64
#define TENC 512
#define MDEC (NB*TDEC)   // 512
#define MENC (NB*TENC)   // 4096

// ---------------- scratch ----------------
__device__ float g_dp[MDEC*H2];
__device__ float g_ep[MENC*H2];
__device__ float g_A [MDEC*H2];
__device__ float g_E [MENC*H2];
__device__ float g_mdp[MDEC];
__device__ float g_mep[MENC];
__device__ float g_L [MDEC*TENC];
__device__ float g_Senc[NB*H2];
__device__ float g_Cc  [NB*H2];
__device__ float g_partS[NB*8*H2];
__device__ float g_partC[NB*8*H2];
__device__ __nv_bfloat16 g_enc_hi[MENC*H2];
__device__ __nv_bfloat16 g_enc_lo[MENC*H2];
__device__ __nv_bfloat16 g_dec_hi[MDEC*H2];
__device__ __nv_bfloat16 g_dec_lo[MDEC*H2];
__device__ __nv_bfloat16 g_We_hi[H2*H2];
__device__ __nv_bfloat16 g_We_lo[H2*H2];
__device__ __nv_bfloat16 g_Wd_hi[H2*H2];
__device__ __nv_bfloat16 g_Wd_lo[H2*H2];

// ---------------- f32x2 primitives ----------------
__device__ __forceinline__ void fma2(unsigned long long &d, unsigned long long a, unsigned long long b){
    asm("fma.rn.f32x2 %0, %1, %2, %0;" : "+l"(d) : "l"(a), "l"(b));
}
__device__ __forceinline__ unsigned long long packdup(float x){
    unsigned long long r; asm("mov.b64 %0, {%1, %1};" : "=l"(r) : "f"(x)); return r;
}
__device__ __forceinline__ float2 unpack2(unsigned long long v){
    float2 f; asm("mov.b64 {%0, %1}, %2;" : "=f"(f.x), "=f"(f.y) : "l"(v)); return f;
}
__device__ __forceinline__ unsigned long long d2u(double x){
    return (unsigned long long)__double_as_longlong(x);
}

__device__ __forceinline__ uint32_t smem_to_u32(const void* p) {
    uint32_t a;
    asm("{ .reg .u64 tmp; cvta.to.shared.u64 tmp, %1; cvt.u32.u64 %0, tmp; }" : "=r"(a) : "l"(p));
    return a;
}

// ---------------- cp.async ----------------
#define CP_ASYNC16(s, g) asm volatile("cp.async.cg.shared.global [%0], [%1], 16;" :: "r"(s), "l"(g))
#define CP_COMMIT()      asm volatile("cp.async.commit_group;")
#define CP_WAIT0()       asm volatile("cp.async.wait_group 0;" ::: "memory")

// ---------------- mma / ldmatrix ----------------
#define LDSM_X4(r0,r1,r2,r3,addr) \
    asm volatile("ldmatrix.sync.aligned.m8n8.x4.shared.b16 {%0,%1,%2,%3}, [%4];" \
        : "=r"(r0), "=r"(r1), "=r"(r2), "=r"(r3) : "r"(addr))

#define MMA_BF16(ac, a, b0, b1) \
    asm volatile("mma.sync.aligned.m16n8k16.row.col.f32.bf16.bf16.f32 " \
        "{%0,%1,%2,%3}, {%4,%5,%6,%7}, {%8,%9}, {%0,%1,%2,%3};" \
        : "+f"((ac)[0]), "+f"((ac)[1]), "+f"((ac)[2]), "+f"((ac)[3]) \
        : "r"((a)[0]), "r"((a)[1]), "r"((a)[2]), "r"((a)[3]), "r"(b0), "r"(b1))

// ---------------------------------------------------------------------------
// Split conversions: fp32 -> (hi, lo) bf16 pair
// ---------------------------------------------------------------------------
__device__ __forceinline__ void split2(float a, float b, uint32_t& hi, uint32_t& lo){
    __nv_bfloat16 ha = __float2bfloat16(a), hb = __float2bfloat16(b);
    __nv_bfloat16 la = __float2bfloat16(a - __bfloat162float(ha));
    __nv_bfloat16 lb = __float2bfloat16(b - __bfloat162float(hb));
    hi = ((uint32_t)__bfloat16_as_ushort(hb) << 16) | __bfloat16_as_ushort(ha);
    lo = ((uint32_t)__bfloat16_as_ushort(lb) << 16) | __bfloat16_as_ushort(la);
}

__global__ void __launch_bounds__(256) conv_pair(
    const float* __restrict__ x, __nv_bfloat16* __restrict__ hi,
    __nv_bfloat16* __restrict__ lo)
{
    const int i = blockIdx.x*256 + threadIdx.x;       // x4 elems
    float4 v = ((const float4*)x)[i];
    uint2 h, l;
    split2(v.x, v.y, h.x, l.x);
    split2(v.z, v.w, h.y, l.y);
    ((uint2*)hi)[i] = h;
    ((uint2*)lo)[i] = l;
}

// W half [o, d] = W[o*1024 + colOff + d] -> hi/lo arrays 512x512
__global__ void __launch_bounds__(256) conv_W(
    const float* __restrict__ W, int colOff,
    __nv_bfloat16* __restrict__ hi, __nv_bfloat16* __restrict__ lo)
{
    const int i = blockIdx.x*256 + threadIdx.x;       // over 512*128
    const int o = i >> 7, c4 = i & 127;
    float4 v = *(const float4*)(W + (long)o*1024 + colOff + c4*4);
    uint2 h, l;
    split2(v.x, v.y, h.x, l.x);
    split2(v.z, v.w, h.y, l.y);
    ((uint2*)(hi + (long)o*512))[c4] = h;
    ((uint2*)(lo + (long)o*512))[c4] = l;
}

// ---------------------------------------------------------------------------
// Tensor-core GEMM: C = A * B^T, bf16 hi/lo split (3 HMMA terms), fp32 acc.
// A: Mx512 (hi/lo), B: Nx512 (hi/lo), C row-major ldc=512.
// CTA tile 128x128, 8 warps (4 m-warps x 2 n-warps), warp tile 32x64.
// K chunk = 32, double-buffered cp.async smem, row pitch 40 bf16 (80 B)
// => ldmatrix conflict-free (5*r mod 8 permutes 16B chunks).
// ---------------------------------------------------------------------------
#define ARR_PITCH 10240            // 128 rows * 80 B
#define BUF_PITCH (4*ARR_PITCH)    // Ahi, Alo, Bhi, Blo
#define MMA_SMEM  (2*BUF_PITCH)    // 81920 B

__global__ void __launch_bounds__(256, 1) gemm_mma(
    const __nv_bfloat16* __restrict__ Ahi, const __nv_bfloat16* __restrict__ Alo,
    const __nv_bfloat16* __restrict__ Bhi, const __nv_bfloat16* __restrict__ Blo,
    float* __restrict__ C)
{
    extern __shared__ char smem[];
    const uint32_t sb = smem_to_u32(smem);
    const int tid  = threadIdx.x;
    const int lane = tid & 31, wid = tid >> 5;
    const int warp_m = wid & 3, warp_n = wid >> 2;
    const int m0 = blockIdx.y * 128, n0 = blockIdx.x * 128;

    // cp.async load indices: 2 chunks per thread per array
    const int ch0row = tid >> 2, ch0cc = (tid & 3);             // chunk tid
    const int ch1row = (tid + 256) >> 2, ch1cc = ch0cc;         // chunk tid+256
    const long gA0 = (long)(m0 + ch0row)*H2 + ch0cc*8;
    const long gA1 = (long)(m0 + ch1row)*H2 + ch1cc*8;
    const long gB0 = (long)(n0 + ch0row)*H2 + ch0cc*8;
    const long gB1 = (long)(n0 + ch1row)*H2 + ch1cc*8;
    const uint32_t s0 = ch0row*80 + ch0cc*16;
    const uint32_t s1 = ch1row*80 + ch1cc*16;

    // ldmatrix per-lane offsets
    const int lrow = lane & 15;
    const int lk   = (lane >> 4) * 8;
    uint32_t aOff[2], bOff[4];
#pragma unroll
    for (int t = 0; t < 2; t++)
        aOff[t] = (uint32_t)(((warp_m*32 + t*16 + lrow)*40 + lk)*2);
#pragma unroll
    for (int g = 0; g < 4; g++)
        bOff[g] = (uint32_t)(((warp_n*64 + g*16 + lrow)*40 + lk)*2);

    float acc[2][8][4];
#pragma unroll
    for (int t = 0; t < 2; t++)
#pragma unroll
        for (int n = 0; n < 8; n++)
#pragma unroll
            for (int q = 0; q < 4; q++) acc[t][n][q] = 0.f;

    // preload chunk 0 into buf 0
    {
        const long gk = 0;
        CP_ASYNC16(sb + s0,                (const char*)(Ahi + gA0 + gk));
        CP_ASYNC16(sb + s1,                (const char*)(Ahi + gA1 + gk));
        CP_ASYNC16(sb + ARR_PITCH   + s0,  (const char*)(Alo + gA0 + gk));
        CP_ASYNC16(sb + ARR_PITCH   + s1,  (const char*)(Alo + gA1 + gk));
        CP_ASYNC16(sb + 2*ARR_PITCH + s0,  (const char*)(Bhi + gB0 + gk));
        CP_ASYNC16(sb + 2*ARR_PITCH + s1,  (const char*)(Bhi + gB1 + gk));
        CP_ASYNC16(sb + 3*ARR_PITCH + s0,  (const char*)(Blo + gB0 + gk));
        CP_ASYNC16(sb + 3*ARR_PITCH + s1,  (const char*)(Blo + gB1 + gk));
        CP_COMMIT();
        CP_WAIT0();
    }
    __syncthreads();

    int buf = 0;
    for (int kc = 0; kc < 16; kc++) {
        const bool more = (kc + 1) < 16;
        if (more) {
            const uint32_t db = sb + (buf ^ 1)*BUF_PITCH;
            const long gk = (kc + 1)*32;
            CP_ASYNC16(db + s0,                (const char*)(Ahi + gA0 + gk));
            CP_ASYNC16(db + s1,                (const char*)(Ahi + gA1 + gk));
            CP_ASYNC16(db + ARR_PITCH   + s0,  (const char*)(Alo + gA0 + gk));
            CP_ASYNC16(db + ARR_PITCH   + s1,  (const char*)(Alo + gA1 + gk));
            CP_ASYNC16(db + 2*ARR_PITCH + s0,  (const char*)(Bhi + gB0 + gk));
            CP_ASYNC16(db + 2*ARR_PITCH + s1,  (const char*)(Bhi + gB1 + gk));
            CP_ASYNC16(db + 3*ARR_PITCH + s0,  (const char*)(Blo + gB0 + gk));
            CP_ASYNC16(db + 3*ARR_PITCH + s1,  (const char*)(Blo + gB1 + gk));
            CP_COMMIT();
        }
        const uint32_t cb = sb + buf*BUF_PITCH;
#pragma unroll
        for (int kk = 0; kk < 2; kk++) {
            const uint32_t ko = kk*32;   // 16 elems * 2 B
            uint32_t ah[2][4], al[2][4];
#pragma unroll
            for (int t = 0; t < 2; t++) {
                LDSM_X4(ah[t][0], ah[t][1], ah[t][2], ah[t][3], cb + aOff[t] + ko);
                LDSM_X4(al[t][0], al[t][1], al[t][2], al[t][3], cb + ARR_PITCH + aOff[t] + ko);
            }
#pragma unroll
            for (int g = 0; g < 4; g++) {
                uint32_t bh0, bh1, bh2, bh3, bl0, bl1, bl2, bl3;
                LDSM_X4(bh0, bh1, bh2, bh3, cb + 2*ARR_PITCH + bOff[g] + ko);
                LDSM_X4(bl0, bl1, bl2, bl3, cb + 3*ARR_PITCH + bOff[g] + ko);
#pragma unroll
                for (int t = 0; t < 2; t++) {
                    MMA_BF16(acc[t][2*g],   ah[t], bh0, bh2);
                    MMA_BF16(acc[t][2*g],   ah[t], bl0, bl2);
                    MMA_BF16(acc[t][2*g],   al[t], bh0, bh2);
                    MMA_BF16(acc[t][2*g+1], ah[t], bh1, bh3);
                    MMA_BF16(acc[t][2*g+1], ah[t], bl1, bl3);
                    MMA_BF16(acc[t][2*g+1], al[t], bh1, bh3);
                }
            }
        }
        if (more) {
            CP_WAIT0();
            __syncthreads();
            buf ^= 1;
        }
    }

    // epilogue: direct fp32 stores
    const int rbase = m0 + warp_m*32 + (lane >> 2);
    const int cbase = n0 + warp_n*64 + (lane & 3)*2;
#pragma unroll
    for (int t = 0; t < 2; t++) {
#pragma unroll
        for (int n = 0; n < 8; n++) {
            const int r = rbase + t*16;
            const int c = cbase + n*8;
            float2 v0; v0.x = acc[t][n][0]; v0.y = acc[t][n][1];
            float2 v1; v1.x = acc[t][n][2]; v1.y = acc[t][n][3];
            *(float2*)(C + (long)r*H2 + c)       = v0;
            *(float2*)(C + (long)(r + 8)*H2 + c) = v1;
        }
    }
}

// ---------------------------------------------------------------------------
// 64x64 TT GEMM (f32x2), batched. EPI==1: C = mrow + mcol + log(acc)
// ---------------------------------------------------------------------------
template<int EPI>
__global__ void __launch_bounds__(256) gemm_tt64(
    const float* __restrict__ A, int lda, long sA,
    const float* __restrict__ Bm, int ldb, long sB,
    float* __restrict__ Cm, int ldc, long sC, int K,
    const float* __restrict__ mrow, int sMr,
    const float* __restrict__ mcol, int sMc)
{
    const int bz = blockIdx.z;
    A  += (long)bz * sA;
    Bm += (long)bz * sB;
    Cm += (long)bz * sC;

    __shared__ float As[2][16][68];
    __shared__ float Bs[2][16][68];
    const int t  = threadIdx.x;
    const int tx = t & 15, ty = t >> 4;
    const int row0 = t >> 2;
    const int kq   = (t & 3) << 2;

    const float* Ap = A  + (long)(blockIdx.y*64 + row0) * lda + kq;
    const float* Bp = Bm + (long)(blockIdx.x*64 + row0) * ldb + kq;

    unsigned long long acc[4][2];
#pragma unroll
    for (int i = 0; i < 4; i++) { acc[i][0] = 0ull; acc[i][1] = 0ull; }

    float4 ra = *(const float4*)Ap;
    float4 rb = *(const float4*)Bp;
    As[0][kq+0][row0]=ra.x; As[0][kq+1][row0]=ra.y; As[0][kq+2][row0]=ra.z; As[0][kq+3][row0]=ra.w;
    Bs[0][kq+0][row0]=rb.x; Bs[0][kq+1][row0]=rb.y; Bs[0][kq+2][row0]=rb.z; Bs[0][kq+3][row0]=rb.w;
    __syncthreads();

    int buf = 0;
    for (int k0 = 0; k0 < K; k0 += 16) {
        const bool more = (k0 + 16) < K;
        if (more) {
            ra = *(const float4*)(Ap + k0 + 16);
            rb = *(const float4*)(Bp + k0 + 16);
        }
#pragma unroll
        for (int kk = 0; kk < 16; kk++) {
            float4 a = *(const float4*)&As[buf][kk][ty*4];
            double2 b = *(const double2*)&Bs[buf][kk][tx*4];
            unsigned long long bp0 = d2u(b.x), bp1 = d2u(b.y);
            unsigned long long ap0 = packdup(a.x), ap1 = packdup(a.y);
            unsigned long long ap2 = packdup(a.z), ap3 = packdup(a.w);
            fma2(acc[0][0], ap0, bp0); fma2(acc[0][1], ap0, bp1);
            fma2(acc[1][0], ap1, bp0); fma2(acc[1][1], ap1, bp1);
            fma2(acc[2][0], ap2, bp0); fma2(acc[2][1], ap2, bp1);
            fma2(acc[3][0], ap3, bp0); fma2(acc[3][1], ap3, bp1);
        }
        if (more) {
            const int nb = buf ^ 1;
            As[nb][kq+0][row0]=ra.x; As[nb][kq+1][row0]=ra.y; As[nb][kq+2][row0]=ra.z; As[nb][kq+3][row0]=ra.w;
            Bs[nb][kq+0][row0]=rb.x; Bs[nb][kq+1][row0]=rb.y; Bs[nb][kq+2][row0]=rb.z; Bs[nb][kq+3][row0]=rb.w;
            __syncthreads();
            buf = nb;
        }
    }

    const int m0  = blockIdx.y*64 + ty*4;
    const int n0g = blockIdx.x*64 + tx*4;
#pragma unroll
    for (int i = 0; i < 4; i++) {
        float mr = 0.f;
        if (EPI == 1) mr = mrow[(long)bz*sMr + m0 + i];
        float* cr = Cm + (long)(m0 + i) * ldc + n0g;
#pragma unroll
        for (int j = 0; j < 2; j++) {
            float2 v = unpack2(acc[i][j]);
            if (EPI == 1) {
                v.x = mr + mcol[(long)bz*sMc + n0g + 2*j    ] + __logf(v.x);
                v.y = mr + mcol[(long)bz*sMc + n0g + 2*j + 1] + __logf(v.y);
            }
            *(float2*)(cr + 2*j) = v;
        }
    }
}

// ---------------------------------------------------------------------------
// Final NN GEMM (f32x2): out = (dp+bias)*Senc + Cc - L @ enc, per batch.
// ---------------------------------------------------------------------------
__global__ void __launch_bounds__(256) gemm_nn_final(
    const float* __restrict__ Lm, const float* __restrict__ enc,
    const float* __restrict__ dp, const float* __restrict__ bias,
    const float* __restrict__ Senc, const float* __restrict__ Cc,
    float* __restrict__ out)
{
    const int bz = blockIdx.z;
    const float* Ab = Lm  + (long)bz*TDEC*TENC;
    const float* Bb = enc + (long)bz*TENC*H2;

    __shared__ float As[2][16][68];
    __shared__ float Bs[2][16][68];
    const int t  = threadIdx.x;
    const int tx = t & 15, ty = t >> 4;
    const int aRow = t >> 2, aK = (t & 3) << 2;
    const int bK = t >> 4, bCol = (t & 15) << 2;
    const int nBase = blockIdx.x * 64;

    const float* ApL = Ab + (long)aRow*TENC + aK;
    const float* BpL = Bb + (long)bK*H2 + nBase + bCol;

    unsigned long long acc[4][2];
#pragma unroll
    for (int i = 0; i < 4; i++) { acc[i][0] = 0ull; acc[i][1] = 0ull; }

    float4 ra = *(const float4*)ApL;
    float4 rb = *(const float4*)BpL;
    As[0][aK+0][aRow]=ra.x; As[0][aK+1][aRow]=ra.y; As[0][aK+2][aRow]=ra.z; As[0][aK+3][aRow]=ra.w;
    *(float4*)&Bs[0][bK][bCol] = rb;
    __syncthreads();

    int buf = 0;
    for (int k0 = 0; k0 < TENC; k0 += 16) {
        const bool more = (k0 + 16) < TENC;
        if (more) {
            ra = *(const float4*)(ApL + k0 + 16);
            rb = *(const float4*)(BpL + (long)(k0 + 16)*H2);
        }
#pragma unroll
        for (int kk = 0; kk < 16; kk++) {
            float4 a = *(const float4*)&As[buf][kk][ty*4];
            double2 b = *(const double2*)&Bs[buf][kk][tx*4];
            unsigned long long bp0 = d2u(b.x), bp1 = d2u(b.y);
            unsigned long long ap0 = packdup(a.x), ap1 = packdup(a.y);
            unsigned long long ap2 = packdup(a.z), ap3 = packdup(a.w);
            fma2(acc[0][0], ap0, bp0); fma2(acc[0][1], ap0, bp1);
            fma2(acc[1][0], ap1, bp0); fma2(acc[1][1], ap1, bp1);
            fma2(acc[2][0], ap2, bp0); fma2(acc[2][1], ap2, bp1);
            fma2(acc[3][0], ap3, bp0); fma2(acc[3][1], ap3, bp1);
        }
        if (more) {
            const int nb = buf ^ 1;
            As[nb][aK+0][aRow]=ra.x; As[nb][aK+1][aRow]=ra.y; As[nb][aK+2][aRow]=ra.z; As[nb][aK+3][aRow]=ra.w;
            *(float4*)&Bs[nb][bK][bCol] = rb;
            __syncthreads();
            buf = nb;
        }
    }

    const int i0 = ty*4;
    const int n0 = nBase + tx*4;
#pragma unroll
    for (int i = 0; i < 4; i++) {
        const int gr = bz*TDEC + i0 + i;
#pragma unroll
        for (int j = 0; j < 2; j++) {
            float2 v = unpack2(acc[i][j]);
            const int d0 = n0 + 2*j;
            float o0 = (dp[(long)gr*H2 + d0  ] + bias[d0  ]) * Senc[(long)bz*H2 + d0  ] + Cc[(long)bz*H2 + d0  ] - v.x;
            float o1 = (dp[(long)gr*H2 + d0+1] + bias[d0+1]) * Senc[(long)bz*H2 + d0+1] + Cc[(long)bz*H2 + d0+1] - v.y;
            float2 ov; ov.x = o0; ov.y = o1;
            *(float2*)(out + (long)gr*H2 + d0) = ov;
        }
    }
}

// ---------------------------------------------------------------------------
// rowmax + exp: 2 rows per 256-thread block, float4.
// ---------------------------------------------------------------------------
__global__ void __launch_bounds__(256) rowmax_exp2(
    const float* __restrict__ in, const float* __restrict__ bias,
    float* __restrict__ outE, float* __restrict__ outM)
{
    const int t = threadIdx.x;
    const int half = t >> 7;
    const int lane128 = t & 127;
    const long r = (long)blockIdx.x*2 + half;
    float4 v = *(const float4*)(in + r*H2 + lane128*4);
    if (bias) {
        float4 bv = *(const float4*)(bias + lane128*4);
        v.x += bv.x; v.y += bv.y; v.z += bv.z; v.w += bv.w;
    }
    float m = fmaxf(fmaxf(v.x, v.y), fmaxf(v.z, v.w));
#pragma unroll
    for (int o = 16; o; o >>= 1) m = fmaxf(m, __shfl_xor_sync(0xffffffffu, m, o));
    __shared__ float sm[8];
    if ((t & 31) == 0) sm[t >> 5] = m;
    __syncthreads();
    const int wb = half*4;
    float M = fmaxf(fmaxf(sm[wb], sm[wb+1]), fmaxf(sm[wb+2], sm[wb+3]));
    float4 e;
    e.x = __expf(v.x - M); e.y = __expf(v.y - M);
    e.z = __expf(v.z - M); e.w = __expf(v.w - M);
    *(float4*)(outE + r*H2 + lane128*4) = e;
    if (lane128 == 0) outM[r] = M;
}

// ---------------------------------------------------------------------------
// Column reductions
// ---------------------------------------------------------------------------
__global__ void __launch_bounds__(256) colreduceS_part(
    const float* __restrict__ enc, float* __restrict__ partS)
{
    const int b  = blockIdx.y;
    const int js = blockIdx.z;
    const int d  = blockIdx.x * 256 + threadIdx.x;
    const float* e = enc + (long)b*TENC*H2 + (long)js*64*H2 + d;
    float s = 0.f;
#pragma unroll 4
    for (int j = 0; j < 64; j++) s += e[(long)j*H2];
    partS[((long)b*8 + js)*H2 + d] = s;
}

__global__ void __launch_bounds__(256) colreduceC_part(
    const float* __restrict__ enc, const float* __restrict__ ep,
    float* __restrict__ partC)
{
    const int b  = blockIdx.y;
    const int js = blockIdx.z;
    const int d  = blockIdx.x * 256 + threadIdx.x;
    const float* e = enc + (long)b*TENC*H2 + (long)js*64*H2 + d;
    const float* p = ep  + (long)b*TENC*H2 + (long)js*64*H2 + d;
    float c = 0.f;
#pragma unroll 4
    for (int j = 0; j < 64; j++) c += p[(long)j*H2] * e[(long)j*H2];
    partC[((long)b*8 + js)*H2 + d] = c;
}

__global__ void __launch_bounds__(256) colreduce_fin(
    const float* __restrict__ partS, const float* __restrict__ partC,
    float* __restrict__ Senc, float* __restrict__ Cc)
{
    const int idx = blockIdx.x * 256 + threadIdx.x;
    const int b = idx >> 9, d = idx & 511;
    float s = 0.f, c = 0.f;
#pragma unroll
    for (int js = 0; js < 8; js++) {
        s += partS[((long)b*8 + js)*H2 + d];
        c += partC[((long)b*8 + js)*H2 + d];
    }
    Senc[idx] = s;
    Cc[idx]   = c;
}

// ---------------------------------------------------------------------------
extern "C" void kernel_launch(void* const* d_in, const int* in_sizes, int n_in,
                              void* d_out, int out_size)
{
    const float* enc  = (const float*)d_in[0];
    const float* dec  = (const float*)d_in[1];
    const float* W    = (const float*)d_in[2];
    const float* bias = (const float*)d_in[3];
    float* out = (float*)d_out;

    float *dp, *ep, *A, *E, *mdp, *mep, *L, *Senc, *Cc, *pS, *pC;
    __nv_bfloat16 *ehi, *elo, *dhi, *dlo, *wehi, *welo, *wdhi, *wdlo;
    cudaGetSymbolAddress((void**)&dp,   g_dp);
    cudaGetSymbolAddress((void**)&ep,   g_ep);
    cudaGetSymbolAddress((void**)&A,    g_A);
    cudaGetSymbolAddress((void**)&E,    g_E);
    cudaGetSymbolAddress((void**)&mdp,  g_mdp);
    cudaGetSymbolAddress((void**)&mep,  g_mep);
    cudaGetSymbolAddress((void**)&L,    g_L);
    cudaGetSymbolAddress((void**)&Senc, g_Senc);
    cudaGetSymbolAddress((void**)&Cc,   g_Cc);
    cudaGetSymbolAddress((void**)&pS,   g_partS);
    cudaGetSymbolAddress((void**)&pC,   g_partC);
    cudaGetSymbolAddress((void**)&ehi,  g_enc_hi);
    cudaGetSymbolAddress((void**)&elo,  g_enc_lo);
    cudaGetSymbolAddress((void**)&dhi,  g_dec_hi);
    cudaGetSymbolAddress((void**)&dlo,  g_dec_lo);
    cudaGetSymbolAddress((void**)&wehi, g_We_hi);
    cudaGetSymbolAddress((void**)&welo, g_We_lo);
    cudaGetSymbolAddress((void**)&wdhi, g_Wd_hi);
    cudaGetSymbolAddress((void**)&wdlo, g_Wd_lo);

    cudaFuncSetAttribute(gemm_mma, cudaFuncAttributeMaxDynamicSharedMemorySize, MMA_SMEM);

    // 0: enc -> bf16 hi/lo
    conv_pair<<<MENC*H2/1024, 256>>>(enc, ehi, elo);
    // 1: dec -> bf16 hi/lo
    conv_pair<<<MDEC*H2/1024, 256>>>(dec, dhi, dlo);
    // 2: W_dec half -> bf16 hi/lo
    conv_W<<<H2*H2/1024, 256>>>(W, 0, wdhi, wdlo);
    // 3: W_enc half -> bf16 hi/lo
    conv_W<<<H2*H2/1024, 256>>>(W, 512, wehi, welo);
    // 4: Senc partial (enc only)
    colreduceS_part<<<dim3(2, NB, 8), 256>>>(enc, pS);
    // 5: ep = enc @ W_enc^T  (bf16 hi/lo HMMA)  <-- profiled by -s 5 -c 1
    gemm_mma<<<dim3(4, 32), 256, MMA_SMEM>>>(ehi, elo, wehi, welo, ep);
    // 6: dp = dec @ W_dec^T
    gemm_mma<<<dim3(4, 4), 256, MMA_SMEM>>>(dhi, dlo, wdhi, wdlo, dp);
    // 7: A = exp(dp - rowmax)
    rowmax_exp2<<<MDEC/2, 256>>>(dp, nullptr, A, mdp);
    // 8: E = exp(ep + bias - rowmax)
    rowmax_exp2<<<MENC/2, 256>>>(ep, bias, E, mep);
    // 9: Cc partial (needs ep)
    colreduceC_part<<<dim3(2, NB, 8), 256>>>(enc, ep, pC);
    // 10: finalize Senc, Cc
    colreduce_fin<<<16, 256>>>(pS, pC, Senc, Cc);
    // 11: L = mdp + mep + log(A @ E^T) per batch
    gemm_tt64<1><<<dim3(8, 1, NB), 256>>>(A, H2, (long)TDEC*H2,
                                          E, H2, (long)TENC*H2,
                                          L, TENC, (long)TDEC*TENC, H2,
                                          mdp, TDEC, mep, TENC);
    // 12: context
    gemm_nn_final<<<dim3(8, 1, NB), 256>>>(L, enc, dp, bias, Senc, Cc, out);
}

// round 5
// speedup vs baseline: 1.5644x; 1.0386x over previous
#include <cuda_runtime.h>
#include <cuda_bf16.h>
#include <cstdint>
#include <math.h>

#define H2   512
#define NB   8
#define TDEC 64
#define TENC 512
#define MDEC (NB*TDEC)   // 512
#define MENC (NB*TENC)   // 4096

// ---------------- scratch ----------------
__device__ float g_dp[MDEC*H2];
__device__ float g_ep[MENC*H2];
__device__ float g_mdp[MDEC];
__device__ float g_mep[MENC];
__device__ float g_Senc[NB*H2];
__device__ float g_Cc  [NB*H2];
__device__ float g_partS[NB*8*H2];
__device__ float g_partC[NB*8*H2];
__device__ __nv_bfloat16 g_enc_hi[MENC*H2];
__device__ __nv_bfloat16 g_enc_lo[MENC*H2];
__device__ __nv_bfloat16 g_encT_hi[MENC*H2];
__device__ __nv_bfloat16 g_encT_lo[MENC*H2];
__device__ __nv_bfloat16 g_dec_hi[MDEC*H2];
__device__ __nv_bfloat16 g_dec_lo[MDEC*H2];
__device__ __nv_bfloat16 g_We_hi[H2*H2];
__device__ __nv_bfloat16 g_We_lo[H2*H2];
__device__ __nv_bfloat16 g_Wd_hi[H2*H2];
__device__ __nv_bfloat16 g_Wd_lo[H2*H2];
__device__ __nv_bfloat16 g_Ahi[MDEC*H2];
__device__ __nv_bfloat16 g_Alo[MDEC*H2];
__device__ __nv_bfloat16 g_Ehi[MENC*H2];
__device__ __nv_bfloat16 g_Elo[MENC*H2];
__device__ __nv_bfloat16 g_Lhi[MDEC*TENC];
__device__ __nv_bfloat16 g_Llo[MDEC*TENC];

__device__ __forceinline__ uint32_t smem_to_u32(const void* p) {
    uint32_t a;
    asm("{ .reg .u64 tmp; cvta.to.shared.u64 tmp, %1; cvt.u32.u64 %0, tmp; }" : "=r"(a) : "l"(p));
    return a;
}

// ---------------- cp.async ----------------
#define CP_ASYNC16(s, g) asm volatile("cp.async.cg.shared.global [%0], [%1], 16;" :: "r"(s), "l"(g))
#define CP_COMMIT()      asm volatile("cp.async.commit_group;")
#define CP_WAIT0()       asm volatile("cp.async.wait_group 0;" ::: "memory")

// ---------------- mma / ldmatrix ----------------
#define LDSM_X4(r0,r1,r2,r3,addr) \
    asm volatile("ldmatrix.sync.aligned.m8n8.x4.shared.b16 {%0,%1,%2,%3}, [%4];" \
        : "=r"(r0), "=r"(r1), "=r"(r2), "=r"(r3) : "r"(addr))

#define MMA_BF16(ac, a, b0, b1) \
    asm volatile("mma.sync.aligned.m16n8k16.row.col.f32.bf16.bf16.f32 " \
        "{%0,%1,%2,%3}, {%4,%5,%6,%7}, {%8,%9}, {%0,%1,%2,%3};" \
        : "+f"((ac)[0]), "+f"((ac)[1]), "+f"((ac)[2]), "+f"((ac)[3]) \
        : "r"((a)[0]), "r"((a)[1]), "r"((a)[2]), "r"((a)[3]), "r"(b0), "r"(b1))

// ---------------- hi/lo split ----------------
__device__ __forceinline__ void split2(float a, float b, uint32_t& hi, uint32_t& lo){
    __nv_bfloat16 ha = __float2bfloat16(a), hb = __float2bfloat16(b);
    __nv_bfloat16 la = __float2bfloat16(a - __bfloat162float(ha));
    __nv_bfloat16 lb = __float2bfloat16(b - __bfloat162float(hb));
    hi = ((uint32_t)__bfloat16_as_ushort(hb) << 16) | __bfloat16_as_ushort(ha);
    lo = ((uint32_t)__bfloat16_as_ushort(lb) << 16) | __bfloat16_as_ushort(la);
}

__global__ void __launch_bounds__(256) conv_pair(
    const float* __restrict__ x, __nv_bfloat16* __restrict__ hi,
    __nv_bfloat16* __restrict__ lo)
{
    const int i = blockIdx.x*256 + threadIdx.x;
    float4 v = ((const float4*)x)[i];
    uint2 h, l;
    split2(v.x, v.y, h.x, l.x);
    split2(v.z, v.w, h.y, l.y);
    ((uint2*)hi)[i] = h;
    ((uint2*)lo)[i] = l;
}

// Both W halves in one kernel: W row-major [o][1024]; q<128 -> dec, else enc.
__global__ void __launch_bounds__(256) conv_Wboth(
    const float* __restrict__ W,
    __nv_bfloat16* __restrict__ wdhi, __nv_bfloat16* __restrict__ wdlo,
    __nv_bfloat16* __restrict__ wehi, __nv_bfloat16* __restrict__ welo)
{
    const int i = blockIdx.x*256 + threadIdx.x;   // over 512*256 float4s
    const int o = i >> 8, q = i & 255;
    float4 v = *(const float4*)(W + (long)o*1024 + q*4);
    uint2 h, l;
    split2(v.x, v.y, h.x, l.x);
    split2(v.z, v.w, h.y, l.y);
    const int c = q & 127;
    __nv_bfloat16* dh = (q < 128) ? wdhi : wehi;
    __nv_bfloat16* dl = (q < 128) ? wdlo : welo;
    ((uint2*)(dh + (long)o*512))[c] = h;
    ((uint2*)(dl + (long)o*512))[c] = l;
}

// transpose enc hi/lo per batch: [b][j][d] -> [b][d][j]
__global__ void conv_encT(
    const __nv_bfloat16* __restrict__ hi, const __nv_bfloat16* __restrict__ lo,
    __nv_bfloat16* __restrict__ hiT, __nv_bfloat16* __restrict__ loT)
{
    __shared__ unsigned short sh[32][33], sl[32][33];
    const int b = blockIdx.z;
    const int jT = blockIdx.y * 32, dT = blockIdx.x * 32;
    const int x = threadIdx.x, y = threadIdx.y;     // (32, 8)
#pragma unroll
    for (int k = 0; k < 4; k++) {
        const int row = y + k*8;
        const long src = ((long)b*512 + jT + row)*512 + dT + x;
        sh[row][x] = ((const unsigned short*)hi)[src];
        sl[row][x] = ((const unsigned short*)lo)[src];
    }
    __syncthreads();
#pragma unroll
    for (int k = 0; k < 4; k++) {
        const int row = y + k*8;
        const long dst = ((long)b*512 + dT + row)*512 + jT + x;
        ((unsigned short*)hiT)[dst] = sh[x][row];
        ((unsigned short*)loT)[dst] = sl[x][row];
    }
}

// ---------------------------------------------------------------------------
// 128x128 HMMA GEMM: C = A*B^T, bf16 hi/lo (3 terms), fp32 out.
// ---------------------------------------------------------------------------
#define ARR_PITCH 10240            // 128 rows * 80 B
#define BUF_PITCH (4*ARR_PITCH)
#define MMA_SMEM  (2*BUF_PITCH)    // 81920 B

__global__ void __launch_bounds__(256, 1) gemm_mma(
    const __nv_bfloat16* __restrict__ Ahi, const __nv_bfloat16* __restrict__ Alo,
    const __nv_bfloat16* __restrict__ Bhi, const __nv_bfloat16* __restrict__ Blo,
    float* __restrict__ C)
{
    extern __shared__ char smem[];
    const uint32_t sb = smem_to_u32(smem);
    const int tid  = threadIdx.x;
    const int lane = tid & 31, wid = tid >> 5;
    const int warp_m = wid & 3, warp_n = wid >> 2;
    const int m0 = blockIdx.y * 128, n0 = blockIdx.x * 128;

    const int ch0row = tid >> 2, ch0cc = (tid & 3);
    const int ch1row = (tid + 256) >> 2, ch1cc = ch0cc;
    const long gA0 = (long)(m0 + ch0row)*H2 + ch0cc*8;
    const long gA1 = (long)(m0 + ch1row)*H2 + ch1cc*8;
    const long gB0 = (long)(n0 + ch0row)*H2 + ch0cc*8;
    const long gB1 = (long)(n0 + ch1row)*H2 + ch1cc*8;
    const uint32_t s0 = ch0row*80 + ch0cc*16;
    const uint32_t s1 = ch1row*80 + ch1cc*16;

    const int lrow = lane & 15;
    const int lk   = (lane >> 4) * 8;
    uint32_t aOff[2], bOff[4];
#pragma unroll
    for (int t = 0; t < 2; t++)
        aOff[t] = (uint32_t)(((warp_m*32 + t*16 + lrow)*40 + lk)*2);
#pragma unroll
    for (int g = 0; g < 4; g++)
        bOff[g] = (uint32_t)(((warp_n*64 + g*16 + lrow)*40 + lk)*2);

    float acc[2][8][4];
#pragma unroll
    for (int t = 0; t < 2; t++)
#pragma unroll
        for (int n = 0; n < 8; n++)
#pragma unroll
            for (int q = 0; q < 4; q++) acc[t][n][q] = 0.f;

    {
        CP_ASYNC16(sb + s0,                (const char*)(Ahi + gA0));
        CP_ASYNC16(sb + s1,                (const char*)(Ahi + gA1));
        CP_ASYNC16(sb + ARR_PITCH   + s0,  (const char*)(Alo + gA0));
        CP_ASYNC16(sb + ARR_PITCH   + s1,  (const char*)(Alo + gA1));
        CP_ASYNC16(sb + 2*ARR_PITCH + s0,  (const char*)(Bhi + gB0));
        CP_ASYNC16(sb + 2*ARR_PITCH + s1,  (const char*)(Bhi + gB1));
        CP_ASYNC16(sb + 3*ARR_PITCH + s0,  (const char*)(Blo + gB0));
        CP_ASYNC16(sb + 3*ARR_PITCH + s1,  (const char*)(Blo + gB1));
        CP_COMMIT();
        CP_WAIT0();
    }
    __syncthreads();

    int buf = 0;
    for (int kc = 0; kc < 16; kc++) {
        const bool more = (kc + 1) < 16;
        if (more) {
            const uint32_t db = sb + (buf ^ 1)*BUF_PITCH;
            const long gk = (kc + 1)*32;
            CP_ASYNC16(db + s0,                (const char*)(Ahi + gA0 + gk));
            CP_ASYNC16(db + s1,                (const char*)(Ahi + gA1 + gk));
            CP_ASYNC16(db + ARR_PITCH   + s0,  (const char*)(Alo + gA0 + gk));
            CP_ASYNC16(db + ARR_PITCH   + s1,  (const char*)(Alo + gA1 + gk));
            CP_ASYNC16(db + 2*ARR_PITCH + s0,  (const char*)(Bhi + gB0 + gk));
            CP_ASYNC16(db + 2*ARR_PITCH + s1,  (const char*)(Bhi + gB1 + gk));
            CP_ASYNC16(db + 3*ARR_PITCH + s0,  (const char*)(Blo + gB0 + gk));
            CP_ASYNC16(db + 3*ARR_PITCH + s1,  (const char*)(Blo + gB1 + gk));
            CP_COMMIT();
        }
        const uint32_t cb = sb + buf*BUF_PITCH;
#pragma unroll
        for (int kk = 0; kk < 2; kk++) {
            const uint32_t ko = kk*32;
            uint32_t ah[2][4], al[2][4];
#pragma unroll
            for (int t = 0; t < 2; t++) {
                LDSM_X4(ah[t][0], ah[t][1], ah[t][2], ah[t][3], cb + aOff[t] + ko);
                LDSM_X4(al[t][0], al[t][1], al[t][2], al[t][3], cb + ARR_PITCH + aOff[t] + ko);
            }
#pragma unroll
            for (int g = 0; g < 4; g++) {
                uint32_t bh0, bh1, bh2, bh3, bl0, bl1, bl2, bl3;
                LDSM_X4(bh0, bh1, bh2, bh3, cb + 2*ARR_PITCH + bOff[g] + ko);
                LDSM_X4(bl0, bl1, bl2, bl3, cb + 3*ARR_PITCH + bOff[g] + ko);
#pragma unroll
                for (int t = 0; t < 2; t++) {
                    MMA_BF16(acc[t][2*g],   ah[t], bh0, bh2);
                    MMA_BF16(acc[t][2*g],   ah[t], bl0, bl2);
                    MMA_BF16(acc[t][2*g],   al[t], bh0, bh2);
                    MMA_BF16(acc[t][2*g+1], ah[t], bh1, bh3);
                    MMA_BF16(acc[t][2*g+1], ah[t], bl1, bl3);
                    MMA_BF16(acc[t][2*g+1], al[t], bh1, bh3);
                }
            }
        }
        if (more) {
            CP_WAIT0();
            __syncthreads();
            buf ^= 1;
        }
    }

    const int rbase = m0 + warp_m*32 + (lane >> 2);
    const int cbase = n0 + warp_n*64 + (lane & 3)*2;
#pragma unroll
    for (int t = 0; t < 2; t++) {
#pragma unroll
        for (int n = 0; n < 8; n++) {
            const int r = rbase + t*16;
            const int c = cbase + n*8;
            float2 v0; v0.x = acc[t][n][0]; v0.y = acc[t][n][1];
            float2 v1; v1.x = acc[t][n][2]; v1.y = acc[t][n][3];
            *(float2*)(C + (long)r*H2 + c)       = v0;
            *(float2*)(C + (long)(r + 8)*H2 + c) = v1;
        }
    }
}

// ---------------------------------------------------------------------------
// 64x128 batched HMMA GEMM, C = A*B^T per batch (bz), K=512.
// EPI==1: v = mrow[gr] + mcol[bz*512+c] + log(acc) -> hi/lo bf16 out
// EPI==2: out = (dp+bias)*Senc + Cc - acc          -> fp32 out
// ---------------------------------------------------------------------------
#define A64_HI 0
#define A64_LO 5120
#define B64_HI 10240
#define B64_LO 20480
#define BUF64  30720
#define SMEM64 61440

template<int EPI>
__global__ void __launch_bounds__(256, 1) mma64(
    const __nv_bfloat16* __restrict__ Ahi, const __nv_bfloat16* __restrict__ Alo, long sA,
    const __nv_bfloat16* __restrict__ Bhi, const __nv_bfloat16* __restrict__ Blo, long sB,
    const float* __restrict__ mrow, const float* __restrict__ mcol,
    __nv_bfloat16* __restrict__ oHi, __nv_bfloat16* __restrict__ oLo,
    const float* __restrict__ dp, const float* __restrict__ bias,
    const float* __restrict__ Senc, const float* __restrict__ Cc,
    float* __restrict__ out)
{
    extern __shared__ char smem[];
    const uint32_t sb = smem_to_u32(smem);
    const int tid  = threadIdx.x;
    const int lane = tid & 31, wid = tid >> 5;
    const int warp_m = wid & 1, warp_n = wid >> 1;   // 2 x 4
    const int bz = blockIdx.z;
    const int n0 = blockIdx.x * 128;

    const __nv_bfloat16* Ah = Ahi + (long)bz*sA;
    const __nv_bfloat16* Al = Alo + (long)bz*sA;
    const __nv_bfloat16* Bh = Bhi + (long)bz*sB;
    const __nv_bfloat16* Bl = Blo + (long)bz*sB;

    // A: 256 chunks (64 rows x 4); B: 512 chunks (128 rows x 4)
    const int rowA = tid >> 2, cc = tid & 3;
    const int rowB0 = tid >> 2, rowB1 = (tid + 256) >> 2;
    const long gA  = (long)rowA*H2 + cc*8;
    const long gB0 = (long)(n0 + rowB0)*H2 + cc*8;
    const long gB1 = (long)(n0 + rowB1)*H2 + cc*8;
    const uint32_t sA0 = rowA*80 + cc*16;
    const uint32_t sB0 = rowB0*80 + cc*16;
    const uint32_t sB1 = rowB1*80 + cc*16;

    const int lrow = lane & 15;
    const int lk   = (lane >> 4) * 8;
    uint32_t aOff[2], bOff[2];
#pragma unroll
    for (int t = 0; t < 2; t++)
        aOff[t] = (uint32_t)(((warp_m*32 + t*16 + lrow)*40 + lk)*2);
#pragma unroll
    for (int g = 0; g < 2; g++)
        bOff[g] = (uint32_t)(((warp_n*32 + g*16 + lrow)*40 + lk)*2);

    float acc[2][4][4];
#pragma unroll
    for (int t = 0; t < 2; t++)
#pragma unroll
        for (int n = 0; n < 4; n++)
#pragma unroll
            for (int q = 0; q < 4; q++) acc[t][n][q] = 0.f;

    {
        CP_ASYNC16(sb + A64_HI + sA0, (const char*)(Ah + gA));
        CP_ASYNC16(sb + A64_LO + sA0, (const char*)(Al + gA));
        CP_ASYNC16(sb + B64_HI + sB0, (const char*)(Bh + gB0));
        CP_ASYNC16(sb + B64_HI + sB1, (const char*)(Bh + gB1));
        CP_ASYNC16(sb + B64_LO + sB0, (const char*)(Bl + gB0));
        CP_ASYNC16(sb + B64_LO + sB1, (const char*)(Bl + gB1));
        CP_COMMIT();
        CP_WAIT0();
    }
    __syncthreads();

    int buf = 0;
    for (int kc = 0; kc < 16; kc++) {
        const bool more = (kc + 1) < 16;
        if (more) {
            const uint32_t db = sb + (buf ^ 1)*BUF64;
            const long gk = (kc + 1)*32;
            CP_ASYNC16(db + A64_HI + sA0, (const char*)(Ah + gA + gk));
            CP_ASYNC16(db + A64_LO + sA0, (const char*)(Al + gA + gk));
            CP_ASYNC16(db + B64_HI + sB0, (const char*)(Bh + gB0 + gk));
            CP_ASYNC16(db + B64_HI + sB1, (const char*)(Bh + gB1 + gk));
            CP_ASYNC16(db + B64_LO + sB0, (const char*)(Bl + gB0 + gk));
            CP_ASYNC16(db + B64_LO + sB1, (const char*)(Bl + gB1 + gk));
            CP_COMMIT();
        }
        const uint32_t cb = sb + buf*BUF64;
#pragma unroll
        for (int kk = 0; kk < 2; kk++) {
            const uint32_t ko = kk*32;
            uint32_t ah[2][4], al[2][4];
#pragma unroll
            for (int t = 0; t < 2; t++) {
                LDSM_X4(ah[t][0], ah[t][1], ah[t][2], ah[t][3], cb + A64_HI + aOff[t] + ko);
                LDSM_X4(al[t][0], al[t][1], al[t][2], al[t][3], cb + A64_LO + aOff[t] + ko);
            }
#pragma unroll
            for (int g = 0; g < 2; g++) {
                uint32_t bh0, bh1, bh2, bh3, bl0, bl1, bl2, bl3;
                LDSM_X4(bh0, bh1, bh2, bh3, cb + B64_HI + bOff[g] + ko);
                LDSM_X4(bl0, bl1, bl2, bl3, cb + B64_LO + bOff[g] + ko);
#pragma unroll
                for (int t = 0; t < 2; t++) {
                    MMA_BF16(acc[t][2*g],   ah[t], bh0, bh2);
                    MMA_BF16(acc[t][2*g],   ah[t], bl0, bl2);
                    MMA_BF16(acc[t][2*g],   al[t], bh0, bh2);
                    MMA_BF16(acc[t][2*g+1], ah[t], bh1, bh3);
                    MMA_BF16(acc[t][2*g+1], ah[t], bl1, bl3);
                    MMA_BF16(acc[t][2*g+1], al[t], bh1, bh3);
                }
            }
        }
        if (more) {
            CP_WAIT0();
            __syncthreads();
            buf ^= 1;
        }
    }

    const int rbase = warp_m*32 + (lane >> 2);
    const int cbase = n0 + warp_n*32 + (lane & 3)*2;
#pragma unroll
    for (int t = 0; t < 2; t++) {
#pragma unroll
        for (int n = 0; n < 4; n++) {
#pragma unroll
            for (int h = 0; h < 2; h++) {
                const int r  = rbase + t*16 + h*8;
                const int gr = bz*TDEC + r;
                const int c  = cbase + n*8;
                const float a0 = acc[t][n][2*h], a1 = acc[t][n][2*h+1];
                if (EPI == 1) {
                    float mr = mrow[gr];
                    float v0 = mr + mcol[(long)bz*TENC + c]     + __logf(a0);
                    float v1 = mr + mcol[(long)bz*TENC + c + 1] + __logf(a1);
                    uint32_t hh, ll;
                    split2(v0, v1, hh, ll);
                    *(uint32_t*)(oHi + (long)gr*TENC + c) = hh;
                    *(uint32_t*)(oLo + (long)gr*TENC + c) = ll;
                } else {
                    const long ib = (long)bz*H2 + c;
                    float o0 = (dp[(long)gr*H2 + c]   + bias[c])   * Senc[ib]   + Cc[ib]   - a0;
                    float o1 = (dp[(long)gr*H2 + c+1] + bias[c+1]) * Senc[ib+1] + Cc[ib+1] - a1;
                    float2 ov; ov.x = o0; ov.y = o1;
                    *(float2*)(out + (long)gr*H2 + c) = ov;
                }
            }
        }
    }
}

// ---------------------------------------------------------------------------
// rowmax + exp -> bf16 hi/lo: 2 rows per 256-thread block.
// ---------------------------------------------------------------------------
__global__ void __launch_bounds__(256) rowmax_exp_bf(
    const float* __restrict__ in, const float* __restrict__ bias,
    __nv_bfloat16* __restrict__ outHi, __nv_bfloat16* __restrict__ outLo,
    float* __restrict__ outM)
{
    const int t = threadIdx.x;
    const int half = t >> 7;
    const int lane128 = t & 127;
    const long r = (long)blockIdx.x*2 + half;
    float4 v = *(const float4*)(in + r*H2 + lane128*4);
    if (bias) {
        float4 bv = *(const float4*)(bias + lane128*4);
        v.x += bv.x; v.y += bv.y; v.z += bv.z; v.w += bv.w;
    }
    float m = fmaxf(fmaxf(v.x, v.y), fmaxf(v.z, v.w));
#pragma unroll
    for (int o = 16; o; o >>= 1) m = fmaxf(m, __shfl_xor_sync(0xffffffffu, m, o));
    __shared__ float sm[8];
    if ((t & 31) == 0) sm[t >> 5] = m;
    __syncthreads();
    const int wb = half*4;
    float M = fmaxf(fmaxf(sm[wb], sm[wb+1]), fmaxf(sm[wb+2], sm[wb+3]));
    float e0 = __expf(v.x - M), e1 = __expf(v.y - M);
    float e2 = __expf(v.z - M), e3 = __expf(v.w - M);
    uint2 h, l;
    split2(e0, e1, h.x, l.x);
    split2(e2, e3, h.y, l.y);
    ((uint2*)(outHi + r*H2))[lane128] = h;
    ((uint2*)(outLo + r*H2))[lane128] = l;
    if (lane128 == 0) outM[r] = M;
}

// ---------------------------------------------------------------------------
// Column reductions
// ---------------------------------------------------------------------------
__global__ void __launch_bounds__(256) colreduceS_part(
    const float* __restrict__ enc, float* __restrict__ partS)
{
    const int b  = blockIdx.y;
    const int js = blockIdx.z;
    const int d  = blockIdx.x * 256 + threadIdx.x;
    const float* e = enc + (long)b*TENC*H2 + (long)js*64*H2 + d;
    float s = 0.f;
#pragma unroll 4
    for (int j = 0; j < 64; j++) s += e[(long)j*H2];
    partS[((long)b*8 + js)*H2 + d] = s;
}

__global__ void __launch_bounds__(256) colreduceC_part(
    const float* __restrict__ enc, const float* __restrict__ ep,
    float* __restrict__ partC)
{
    const int b  = blockIdx.y;
    const int js = blockIdx.z;
    const int d  = blockIdx.x * 256 + threadIdx.x;
    const float* e = enc + (long)b*TENC*H2 + (long)js*64*H2 + d;
    const float* p = ep  + (long)b*TENC*H2 + (long)js*64*H2 + d;
    float c = 0.f;
#pragma unroll 4
    for (int j = 0; j < 64; j++) c += p[(long)j*H2] * e[(long)j*H2];
    partC[((long)b*8 + js)*H2 + d] = c;
}

__global__ void __launch_bounds__(256) colreduce_fin(
    const float* __restrict__ partS, const float* __restrict__ partC,
    float* __restrict__ Senc, float* __restrict__ Cc)
{
    const int idx = blockIdx.x * 256 + threadIdx.x;
    const int b = idx >> 9, d = idx & 511;
    float s = 0.f, c = 0.f;
#pragma unroll
    for (int js = 0; js < 8; js++) {
        s += partS[((long)b*8 + js)*H2 + d];
        c += partC[((long)b*8 + js)*H2 + d];
    }
    Senc[idx] = s;
    Cc[idx]   = c;
}

// ---------------------------------------------------------------------------
extern "C" void kernel_launch(void* const* d_in, const int* in_sizes, int n_in,
                              void* d_out, int out_size)
{
    const float* enc  = (const float*)d_in[0];
    const float* dec  = (const float*)d_in[1];
    const float* W    = (const float*)d_in[2];
    const float* bias = (const float*)d_in[3];
    float* out = (float*)d_out;

    float *dp, *ep, *mdp, *mep, *Senc, *Cc, *pS, *pC;
    __nv_bfloat16 *ehi, *elo, *ethi, *etlo, *dhi, *dlo, *wehi, *welo, *wdhi, *wdlo;
    __nv_bfloat16 *Ahi, *Alo, *Ehi, *Elo, *Lhi, *Llo;
    cudaGetSymbolAddress((void**)&dp,   g_dp);
    cudaGetSymbolAddress((void**)&ep,   g_ep);
    cudaGetSymbolAddress((void**)&mdp,  g_mdp);
    cudaGetSymbolAddress((void**)&mep,  g_mep);
    cudaGetSymbolAddress((void**)&Senc, g_Senc);
    cudaGetSymbolAddress((void**)&Cc,   g_Cc);
    cudaGetSymbolAddress((void**)&pS,   g_partS);
    cudaGetSymbolAddress((void**)&pC,   g_partC);
    cudaGetSymbolAddress((void**)&ehi,  g_enc_hi);
    cudaGetSymbolAddress((void**)&elo,  g_enc_lo);
    cudaGetSymbolAddress((void**)&ethi, g_encT_hi);
    cudaGetSymbolAddress((void**)&etlo, g_encT_lo);
    cudaGetSymbolAddress((void**)&dhi,  g_dec_hi);
    cudaGetSymbolAddress((void**)&dlo,  g_dec_lo);
    cudaGetSymbolAddress((void**)&wehi, g_We_hi);
    cudaGetSymbolAddress((void**)&welo, g_We_lo);
    cudaGetSymbolAddress((void**)&wdhi, g_Wd_hi);
    cudaGetSymbolAddress((void**)&wdlo, g_Wd_lo);
    cudaGetSymbolAddress((void**)&Ahi,  g_Ahi);
    cudaGetSymbolAddress((void**)&Alo,  g_Alo);
    cudaGetSymbolAddress((void**)&Ehi,  g_Ehi);
    cudaGetSymbolAddress((void**)&Elo,  g_Elo);
    cudaGetSymbolAddress((void**)&Lhi,  g_Lhi);
    cudaGetSymbolAddress((void**)&Llo,  g_Llo);

    cudaFuncSetAttribute(gemm_mma, cudaFuncAttributeMaxDynamicSharedMemorySize, MMA_SMEM);
    cudaFuncSetAttribute(mma64<1>, cudaFuncAttributeMaxDynamicSharedMemorySize, SMEM64);
    cudaFuncSetAttribute(mma64<2>, cudaFuncAttributeMaxDynamicSharedMemorySize, SMEM64);

    // 0: enc -> bf16 hi/lo
    conv_pair<<<MENC*H2/1024, 256>>>(enc, ehi, elo);
    // 1: dec -> bf16 hi/lo
    conv_pair<<<MDEC*H2/1024, 256>>>(dec, dhi, dlo);
    // 2: W both halves -> bf16 hi/lo
    conv_Wboth<<<H2*1024/4/256, 256>>>(W, wdhi, wdlo, wehi, welo);
    // 3: enc^T hi/lo (for final GEMM B operand)
    conv_encT<<<dim3(16, 16, 8), dim3(32, 8)>>>(ehi, elo, ethi, etlo);
    // 4: Senc partial
    colreduceS_part<<<dim3(2, NB, 8), 256>>>(enc, pS);
    // 5: ep = enc @ W_enc^T  (HMMA)  <-- profiled
    gemm_mma<<<dim3(4, 32), 256, MMA_SMEM>>>(ehi, elo, wehi, welo, ep);
    // 6: dp = dec @ W_dec^T
    gemm_mma<<<dim3(4, 4), 256, MMA_SMEM>>>(dhi, dlo, wdhi, wdlo, dp);
    // 7: A = exp(dp - rowmax) -> hi/lo
    rowmax_exp_bf<<<MDEC/2, 256>>>(dp, nullptr, Ahi, Alo, mdp);
    // 8: E = exp(ep + bias - rowmax) -> hi/lo
    rowmax_exp_bf<<<MENC/2, 256>>>(ep, bias, Ehi, Elo, mep);
    // 9: Cc partial
    colreduceC_part<<<dim3(2, NB, 8), 256>>>(enc, ep, pC);
    // 10: finalize Senc, Cc
    colreduce_fin<<<16, 256>>>(pS, pC, Senc, Cc);
    // 11: L = mdp + mep + log(A @ E^T) -> hi/lo   (HMMA)
    mma64<1><<<dim3(4, 1, NB), 256, SMEM64>>>(
        Ahi, Alo, (long)TDEC*H2, Ehi, Elo, (long)TENC*H2,
        mdp, mep, Lhi, Llo, nullptr, nullptr, nullptr, nullptr, nullptr);
    // 12: context = (dp+bias)*Senc + Cc - L @ enc   (HMMA, B = enc^T)
    mma64<2><<<dim3(4, 1, NB), 256, SMEM64>>>(
        Lhi, Llo, (long)TDEC*TENC, ethi, etlo, (long)H2*TENC,
        nullptr, nullptr, nullptr, nullptr, dp, bias, Senc, Cc, out);
}

// round 6
// speedup vs baseline: 2.2680x; 1.4497x over previous
#include <cuda_runtime.h>
#include <cuda_bf16.h>
#include <cstdint>
#include <math.h>

#define H2   512
#define NB   8
#define TDEC 64
#define TENC 512
#define MDEC (NB*TDEC)   // 512
#define MENC (NB*TENC)   // 4096

// ---------------- scratch ----------------
__device__ float g_dp[MDEC*H2];
__device__ float g_ep[MENC*H2];
__device__ float g_mdp[MDEC];
__device__ float g_mep[MENC];
__device__ float g_Senc[NB*H2];
__device__ float g_partS[NB*16*H2];
__device__ float g_partC[NB*8*H2];
__device__ __nv_bfloat16 g_enc_hi[MENC*H2];
__device__ __nv_bfloat16 g_enc_lo[MENC*H2];
__device__ __nv_bfloat16 g_encT_hi[MENC*H2];
__device__ __nv_bfloat16 g_encT_lo[MENC*H2];
__device__ __nv_bfloat16 g_dec_hi[MDEC*H2];
__device__ __nv_bfloat16 g_dec_lo[MDEC*H2];
__device__ __nv_bfloat16 g_We_hi[H2*H2];
__device__ __nv_bfloat16 g_We_lo[H2*H2];
__device__ __nv_bfloat16 g_Wd_hi[H2*H2];
__device__ __nv_bfloat16 g_Wd_lo[H2*H2];
__device__ __nv_bfloat16 g_Ahi[MDEC*H2];
__device__ __nv_bfloat16 g_Alo[MDEC*H2];
__device__ __nv_bfloat16 g_Ehi[MENC*H2];
__device__ __nv_bfloat16 g_Elo[MENC*H2];
__device__ __nv_bfloat16 g_Lhi[MDEC*TENC];
__device__ __nv_bfloat16 g_Llo[MDEC*TENC];

__device__ __forceinline__ uint32_t smem_to_u32(const void* p) {
    uint32_t a;
    asm("{ .reg .u64 tmp; cvta.to.shared.u64 tmp, %1; cvt.u32.u64 %0, tmp; }" : "=r"(a) : "l"(p));
    return a;
}

// ---------------- cp.async ----------------
#define CP_ASYNC16(s, g) asm volatile("cp.async.cg.shared.global [%0], [%1], 16;" :: "r"(s), "l"(g))
#define CP_COMMIT()      asm volatile("cp.async.commit_group;")
#define CP_WAIT0()       asm volatile("cp.async.wait_group 0;" ::: "memory")

// ---------------- mma / ldmatrix ----------------
#define LDSM_X4(r0,r1,r2,r3,addr) \
    asm volatile("ldmatrix.sync.aligned.m8n8.x4.shared.b16 {%0,%1,%2,%3}, [%4];" \
        : "=r"(r0), "=r"(r1), "=r"(r2), "=r"(r3) : "r"(addr))

#define MMA_BF16(ac, a, b0, b1) \
    asm volatile("mma.sync.aligned.m16n8k16.row.col.f32.bf16.bf16.f32 " \
        "{%0,%1,%2,%3}, {%4,%5,%6,%7}, {%8,%9}, {%0,%1,%2,%3};" \
        : "+f"((ac)[0]), "+f"((ac)[1]), "+f"((ac)[2]), "+f"((ac)[3]) \
        : "r"((a)[0]), "r"((a)[1]), "r"((a)[2]), "r"((a)[3]), "r"(b0), "r"(b1))

// ---------------- hi/lo split ----------------
__device__ __forceinline__ void split2(float a, float b, uint32_t& hi, uint32_t& lo){
    __nv_bfloat16 ha = __float2bfloat16(a), hb = __float2bfloat16(b);
    __nv_bfloat16 la = __float2bfloat16(a - __bfloat162float(ha));
    __nv_bfloat16 lb = __float2bfloat16(b - __bfloat162float(hb));
    hi = ((uint32_t)__bfloat16_as_ushort(hb) << 16) | __bfloat16_as_ushort(ha);
    lo = ((uint32_t)__bfloat16_as_ushort(lb) << 16) | __bfloat16_as_ushort(la);
}
__device__ __forceinline__ void split1(float a, unsigned short& hi, unsigned short& lo){
    __nv_bfloat16 ha = __float2bfloat16(a);
    __nv_bfloat16 la = __float2bfloat16(a - __bfloat162float(ha));
    hi = __bfloat16_as_ushort(ha);
    lo = __bfloat16_as_ushort(la);
}

// ---------------------------------------------------------------------------
// conv_all: one launch does
//   [blocks 0..2047]   enc 32x32 tiles: fp32 -> hi/lo (row-major AND transposed)
//                      + column partial sums partS[(b*16+jt)*512 + d]
//   [blocks 2048..2303] dec -> hi/lo
//   [blocks 2304..2815] W -> Wd hi/lo, We hi/lo
// ---------------------------------------------------------------------------
__global__ void __launch_bounds__(256) conv_all(
    const float* __restrict__ enc, const float* __restrict__ dec,
    const float* __restrict__ W,
    __nv_bfloat16* __restrict__ ehi, __nv_bfloat16* __restrict__ elo,
    __nv_bfloat16* __restrict__ ethi, __nv_bfloat16* __restrict__ etlo,
    __nv_bfloat16* __restrict__ dhi, __nv_bfloat16* __restrict__ dlo,
    __nv_bfloat16* __restrict__ wdhi, __nv_bfloat16* __restrict__ wdlo,
    __nv_bfloat16* __restrict__ wehi, __nv_bfloat16* __restrict__ welo,
    float* __restrict__ partS)
{
    const int bid = blockIdx.x;
    const int tid = threadIdx.x;
    if (bid < 2048) {
        // enc tile task
        __shared__ unsigned short sh[32][33], sl[32][33];
        __shared__ float ssum[8][32];
        const int b  = bid >> 8;
        const int jt = (bid >> 4) & 15;
        const int dT = (bid & 15) * 32;
        const int jT = jt * 32;
        const int x = tid & 31, y = tid >> 5;
        float csum = 0.f;
#pragma unroll
        for (int k = 0; k < 4; k++) {
            const int row = y + k*8;
            const long src = ((long)b*512 + jT + row)*512 + dT + x;
            float v = enc[src];
            csum += v;
            unsigned short h, l;
            split1(v, h, l);
            sh[row][x] = h; sl[row][x] = l;
            ((unsigned short*)ehi)[src] = h;
            ((unsigned short*)elo)[src] = l;
        }
        ssum[y][x] = csum;
        __syncthreads();
#pragma unroll
        for (int k = 0; k < 4; k++) {
            const int row = y + k*8;
            const long dst = ((long)b*512 + dT + row)*512 + jT + x;
            ((unsigned short*)ethi)[dst] = sh[x][row];
            ((unsigned short*)etlo)[dst] = sl[x][row];
        }
        if (y == 0) {
            float s = ssum[0][x];
#pragma unroll
            for (int w = 1; w < 8; w++) s += ssum[w][x];
            partS[((long)b*16 + jt)*512 + dT + x] = s;
        }
    } else if (bid < 2304) {
        const int i = (bid - 2048)*256 + tid;   // float4 idx over dec
        float4 v = ((const float4*)dec)[i];
        uint2 h, l;
        split2(v.x, v.y, h.x, l.x);
        split2(v.z, v.w, h.y, l.y);
        ((uint2*)dhi)[i] = h;
        ((uint2*)dlo)[i] = l;
    } else {
        const int i = (bid - 2304)*256 + tid;   // float4 idx over W
        const int o = i >> 8, q = i & 255;
        float4 v = *(const float4*)(W + (long)o*1024 + q*4);
        uint2 h, l;
        split2(v.x, v.y, h.x, l.x);
        split2(v.z, v.w, h.y, l.y);
        const int c = q & 127;
        __nv_bfloat16* ph = (q < 128) ? wdhi : wehi;
        __nv_bfloat16* pl = (q < 128) ? wdlo : welo;
        ((uint2*)(ph + (long)o*512))[c] = h;
        ((uint2*)(pl + (long)o*512))[c] = l;
    }
}

// ---------------------------------------------------------------------------
// 128x128 HMMA GEMM (dual): blockIdx.y < 32 -> ep (enc@We^T), else dp (dec@Wd^T)
// ---------------------------------------------------------------------------
#define ARR_PITCH 10240            // 128 rows * 80 B
#define BUF_PITCH (4*ARR_PITCH)
#define MMA_SMEM  (2*BUF_PITCH)    // 81920 B

__global__ void __launch_bounds__(256, 1) gemm_mma_dual(
    const __nv_bfloat16* __restrict__ eAhi, const __nv_bfloat16* __restrict__ eAlo,
    const __nv_bfloat16* __restrict__ eBhi, const __nv_bfloat16* __restrict__ eBlo,
    float* __restrict__ eC,
    const __nv_bfloat16* __restrict__ dAhi, const __nv_bfloat16* __restrict__ dAlo,
    const __nv_bfloat16* __restrict__ dBhi, const __nv_bfloat16* __restrict__ dBlo,
    float* __restrict__ dC)
{
    extern __shared__ char smem[];
    const uint32_t sb = smem_to_u32(smem);
    const int tid  = threadIdx.x;
    const int lane = tid & 31, wid = tid >> 5;
    const int warp_m = wid & 3, warp_n = wid >> 2;
    const bool isEp = blockIdx.y < 32;
    const int m0 = (isEp ? blockIdx.y : blockIdx.y - 32) * 128;
    const int n0 = blockIdx.x * 128;
    const __nv_bfloat16* Ahi = isEp ? eAhi : dAhi;
    const __nv_bfloat16* Alo = isEp ? eAlo : dAlo;
    const __nv_bfloat16* Bhi = isEp ? eBhi : dBhi;
    const __nv_bfloat16* Blo = isEp ? eBlo : dBlo;
    float* C = isEp ? eC : dC;

    const int ch0row = tid >> 2, ch0cc = (tid & 3);
    const int ch1row = (tid + 256) >> 2, ch1cc = ch0cc;
    const long gA0 = (long)(m0 + ch0row)*H2 + ch0cc*8;
    const long gA1 = (long)(m0 + ch1row)*H2 + ch1cc*8;
    const long gB0 = (long)(n0 + ch0row)*H2 + ch0cc*8;
    const long gB1 = (long)(n0 + ch1row)*H2 + ch1cc*8;
    const uint32_t s0 = ch0row*80 + ch0cc*16;
    const uint32_t s1 = ch1row*80 + ch1cc*16;

    const int lrow = lane & 15;
    const int lk   = (lane >> 4) * 8;
    uint32_t aOff[2], bOff[4];
#pragma unroll
    for (int t = 0; t < 2; t++)
        aOff[t] = (uint32_t)(((warp_m*32 + t*16 + lrow)*40 + lk)*2);
#pragma unroll
    for (int g = 0; g < 4; g++)
        bOff[g] = (uint32_t)(((warp_n*64 + g*16 + lrow)*40 + lk)*2);

    float acc[2][8][4];
#pragma unroll
    for (int t = 0; t < 2; t++)
#pragma unroll
        for (int n = 0; n < 8; n++)
#pragma unroll
            for (int q = 0; q < 4; q++) acc[t][n][q] = 0.f;

    {
        CP_ASYNC16(sb + s0,                (const char*)(Ahi + gA0));
        CP_ASYNC16(sb + s1,                (const char*)(Ahi + gA1));
        CP_ASYNC16(sb + ARR_PITCH   + s0,  (const char*)(Alo + gA0));
        CP_ASYNC16(sb + ARR_PITCH   + s1,  (const char*)(Alo + gA1));
        CP_ASYNC16(sb + 2*ARR_PITCH + s0,  (const char*)(Bhi + gB0));
        CP_ASYNC16(sb + 2*ARR_PITCH + s1,  (const char*)(Bhi + gB1));
        CP_ASYNC16(sb + 3*ARR_PITCH + s0,  (const char*)(Blo + gB0));
        CP_ASYNC16(sb + 3*ARR_PITCH + s1,  (const char*)(Blo + gB1));
        CP_COMMIT();
        CP_WAIT0();
    }
    __syncthreads();

    int buf = 0;
    for (int kc = 0; kc < 16; kc++) {
        const bool more = (kc + 1) < 16;
        if (more) {
            const uint32_t db = sb + (buf ^ 1)*BUF_PITCH;
            const long gk = (kc + 1)*32;
            CP_ASYNC16(db + s0,                (const char*)(Ahi + gA0 + gk));
            CP_ASYNC16(db + s1,                (const char*)(Ahi + gA1 + gk));
            CP_ASYNC16(db + ARR_PITCH   + s0,  (const char*)(Alo + gA0 + gk));
            CP_ASYNC16(db + ARR_PITCH   + s1,  (const char*)(Alo + gA1 + gk));
            CP_ASYNC16(db + 2*ARR_PITCH + s0,  (const char*)(Bhi + gB0 + gk));
            CP_ASYNC16(db + 2*ARR_PITCH + s1,  (const char*)(Bhi + gB1 + gk));
            CP_ASYNC16(db + 3*ARR_PITCH + s0,  (const char*)(Blo + gB0 + gk));
            CP_ASYNC16(db + 3*ARR_PITCH + s1,  (const char*)(Blo + gB1 + gk));
            CP_COMMIT();
        }
        const uint32_t cb = sb + buf*BUF_PITCH;
#pragma unroll
        for (int kk = 0; kk < 2; kk++) {
            const uint32_t ko = kk*32;
            uint32_t ah[2][4], al[2][4];
#pragma unroll
            for (int t = 0; t < 2; t++) {
                LDSM_X4(ah[t][0], ah[t][1], ah[t][2], ah[t][3], cb + aOff[t] + ko);
                LDSM_X4(al[t][0], al[t][1], al[t][2], al[t][3], cb + ARR_PITCH + aOff[t] + ko);
            }
#pragma unroll
            for (int g = 0; g < 4; g++) {
                uint32_t bh0, bh1, bh2, bh3, bl0, bl1, bl2, bl3;
                LDSM_X4(bh0, bh1, bh2, bh3, cb + 2*ARR_PITCH + bOff[g] + ko);
                LDSM_X4(bl0, bl1, bl2, bl3, cb + 3*ARR_PITCH + bOff[g] + ko);
#pragma unroll
                for (int t = 0; t < 2; t++) {
                    MMA_BF16(acc[t][2*g],   ah[t], bh0, bh2);
                    MMA_BF16(acc[t][2*g],   ah[t], bl0, bl2);
                    MMA_BF16(acc[t][2*g],   al[t], bh0, bh2);
                    MMA_BF16(acc[t][2*g+1], ah[t], bh1, bh3);
                    MMA_BF16(acc[t][2*g+1], ah[t], bl1, bl3);
                    MMA_BF16(acc[t][2*g+1], al[t], bh1, bh3);
                }
            }
        }
        if (more) {
            CP_WAIT0();
            __syncthreads();
            buf ^= 1;
        }
    }

    const int rbase = m0 + warp_m*32 + (lane >> 2);
    const int cbase = n0 + warp_n*64 + (lane & 3)*2;
#pragma unroll
    for (int t = 0; t < 2; t++) {
#pragma unroll
        for (int n = 0; n < 8; n++) {
            const int r = rbase + t*16;
            const int c = cbase + n*8;
            float2 v0; v0.x = acc[t][n][0]; v0.y = acc[t][n][1];
            float2 v1; v1.x = acc[t][n][2]; v1.y = acc[t][n][3];
            *(float2*)(C + (long)r*H2 + c)       = v0;
            *(float2*)(C + (long)(r + 8)*H2 + c) = v1;
        }
    }
}

// ---------------------------------------------------------------------------
// rowmax + exp -> bf16 hi/lo. blocks 0..2047: E from ep (+bias); rest: A from dp.
// ---------------------------------------------------------------------------
__global__ void __launch_bounds__(256) rowmax_both(
    const float* __restrict__ ep, const float* __restrict__ dp,
    const float* __restrict__ bias,
    __nv_bfloat16* __restrict__ Ehi, __nv_bfloat16* __restrict__ Elo, float* __restrict__ mep,
    __nv_bfloat16* __restrict__ Ahi, __nv_bfloat16* __restrict__ Alo, float* __restrict__ mdp)
{
    const int bid = blockIdx.x;
    const int t = threadIdx.x;
    const int half = t >> 7;
    const int lane128 = t & 127;
    const bool isE = bid < 2048;
    const long r = (long)(isE ? bid : bid - 2048)*2 + half;
    const float* in = isE ? ep : dp;
    __nv_bfloat16* oh = isE ? Ehi : Ahi;
    __nv_bfloat16* ol = isE ? Elo : Alo;
    float* om = isE ? mep : mdp;

    float4 v = *(const float4*)(in + r*H2 + lane128*4);
    if (isE) {
        float4 bv = *(const float4*)(bias + lane128*4);
        v.x += bv.x; v.y += bv.y; v.z += bv.z; v.w += bv.w;
    }
    float m = fmaxf(fmaxf(v.x, v.y), fmaxf(v.z, v.w));
#pragma unroll
    for (int o = 16; o; o >>= 1) m = fmaxf(m, __shfl_xor_sync(0xffffffffu, m, o));
    __shared__ float sm[8];
    if ((t & 31) == 0) sm[t >> 5] = m;
    __syncthreads();
    const int wb = half*4;
    float M = fmaxf(fmaxf(sm[wb], sm[wb+1]), fmaxf(sm[wb+2], sm[wb+3]));
    float e0 = __expf(v.x - M), e1 = __expf(v.y - M);
    float e2 = __expf(v.z - M), e3 = __expf(v.w - M);
    uint2 h, l;
    split2(e0, e1, h.x, l.x);
    split2(e2, e3, h.y, l.y);
    ((uint2*)(oh + r*H2))[lane128] = h;
    ((uint2*)(ol + r*H2))[lane128] = l;
    if (lane128 == 0) om[r] = M;
}

// ---------------------------------------------------------------------------
// colreduceC (+ Senc finalize on js==0 blocks)
// ---------------------------------------------------------------------------
__global__ void __launch_bounds__(256) colreduceC_plus(
    const float* __restrict__ enc, const float* __restrict__ ep,
    float* __restrict__ partC,
    const float* __restrict__ partS, float* __restrict__ Senc)
{
    const int b  = blockIdx.y;
    const int js = blockIdx.z;
    const int d  = blockIdx.x * 256 + threadIdx.x;
    const float* e = enc + (long)b*TENC*H2 + (long)js*64*H2 + d;
    const float* p = ep  + (long)b*TENC*H2 + (long)js*64*H2 + d;
    float c = 0.f;
#pragma unroll 4
    for (int j = 0; j < 64; j++) c += p[(long)j*H2] * e[(long)j*H2];
    partC[((long)b*8 + js)*H2 + d] = c;
    if (js == 0) {
        float s = 0.f;
#pragma unroll
        for (int q = 0; q < 16; q++) s += partS[((long)b*16 + q)*H2 + d];
        Senc[(long)b*H2 + d] = s;
    }
}

// ---------------------------------------------------------------------------
// 64x128 batched HMMA GEMM, C = A*B^T per batch (bz), K=512.
// EPI==1: v = mrow[gr] + mcol[bz*512+c] + log(acc) -> hi/lo bf16 out
// EPI==2: out = (dp+bias)*Senc + sum8(partC) - acc -> fp32 out
// ---------------------------------------------------------------------------
#define A64_HI 0
#define A64_LO 5120
#define B64_HI 10240
#define B64_LO 20480
#define BUF64  30720
#define SMEM64 61440

template<int EPI>
__global__ void __launch_bounds__(256, 1) mma64(
    const __nv_bfloat16* __restrict__ Ahi, const __nv_bfloat16* __restrict__ Alo, long sA,
    const __nv_bfloat16* __restrict__ Bhi, const __nv_bfloat16* __restrict__ Blo, long sB,
    const float* __restrict__ mrow, const float* __restrict__ mcol,
    __nv_bfloat16* __restrict__ oHi, __nv_bfloat16* __restrict__ oLo,
    const float* __restrict__ dp, const float* __restrict__ bias,
    const float* __restrict__ Senc, const float* __restrict__ partC,
    float* __restrict__ out)
{
    extern __shared__ char smem[];
    const uint32_t sb = smem_to_u32(smem);
    const int tid  = threadIdx.x;
    const int lane = tid & 31, wid = tid >> 5;
    const int warp_m = wid & 1, warp_n = wid >> 1;   // 2 x 4
    const int bz = blockIdx.z;
    const int n0 = blockIdx.x * 128;

    const __nv_bfloat16* Ah = Ahi + (long)bz*sA;
    const __nv_bfloat16* Al = Alo + (long)bz*sA;
    const __nv_bfloat16* Bh = Bhi + (long)bz*sB;
    const __nv_bfloat16* Bl = Blo + (long)bz*sB;

    const int rowA = tid >> 2, cc = tid & 3;
    const int rowB0 = tid >> 2, rowB1 = (tid + 256) >> 2;
    const long gA  = (long)rowA*H2 + cc*8;
    const long gB0 = (long)(n0 + rowB0)*H2 + cc*8;
    const long gB1 = (long)(n0 + rowB1)*H2 + cc*8;
    const uint32_t sA0 = rowA*80 + cc*16;
    const uint32_t sB0 = rowB0*80 + cc*16;
    const uint32_t sB1 = rowB1*80 + cc*16;

    const int lrow = lane & 15;
    const int lk   = (lane >> 4) * 8;
    uint32_t aOff[2], bOff[2];
#pragma unroll
    for (int t = 0; t < 2; t++)
        aOff[t] = (uint32_t)(((warp_m*32 + t*16 + lrow)*40 + lk)*2);
#pragma unroll
    for (int g = 0; g < 2; g++)
        bOff[g] = (uint32_t)(((warp_n*32 + g*16 + lrow)*40 + lk)*2);

    float acc[2][4][4];
#pragma unroll
    for (int t = 0; t < 2; t++)
#pragma unroll
        for (int n = 0; n < 4; n++)
#pragma unroll
            for (int q = 0; q < 4; q++) acc[t][n][q] = 0.f;

    {
        CP_ASYNC16(sb + A64_HI + sA0, (const char*)(Ah + gA));
        CP_ASYNC16(sb + A64_LO + sA0, (const char*)(Al + gA));
        CP_ASYNC16(sb + B64_HI + sB0, (const char*)(Bh + gB0));
        CP_ASYNC16(sb + B64_HI + sB1, (const char*)(Bh + gB1));
        CP_ASYNC16(sb + B64_LO + sB0, (const char*)(Bl + gB0));
        CP_ASYNC16(sb + B64_LO + sB1, (const char*)(Bl + gB1));
        CP_COMMIT();
        CP_WAIT0();
    }
    __syncthreads();

    int buf = 0;
    for (int kc = 0; kc < 16; kc++) {
        const bool more = (kc + 1) < 16;
        if (more) {
            const uint32_t db = sb + (buf ^ 1)*BUF64;
            const long gk = (kc + 1)*32;
            CP_ASYNC16(db + A64_HI + sA0, (const char*)(Ah + gA + gk));
            CP_ASYNC16(db + A64_LO + sA0, (const char*)(Al + gA + gk));
            CP_ASYNC16(db + B64_HI + sB0, (const char*)(Bh + gB0 + gk));
            CP_ASYNC16(db + B64_HI + sB1, (const char*)(Bh + gB1 + gk));
            CP_ASYNC16(db + B64_LO + sB0, (const char*)(Bl + gB0 + gk));
            CP_ASYNC16(db + B64_LO + sB1, (const char*)(Bl + gB1 + gk));
            CP_COMMIT();
        }
        const uint32_t cb = sb + buf*BUF64;
#pragma unroll
        for (int kk = 0; kk < 2; kk++) {
            const uint32_t ko = kk*32;
            uint32_t ah[2][4], al[2][4];
#pragma unroll
            for (int t = 0; t < 2; t++) {
                LDSM_X4(ah[t][0], ah[t][1], ah[t][2], ah[t][3], cb + A64_HI + aOff[t] + ko);
                LDSM_X4(al[t][0], al[t][1], al[t][2], al[t][3], cb + A64_LO + aOff[t] + ko);
            }
#pragma unroll
            for (int g = 0; g < 2; g++) {
                uint32_t bh0, bh1, bh2, bh3, bl0, bl1, bl2, bl3;
                LDSM_X4(bh0, bh1, bh2, bh3, cb + B64_HI + bOff[g] + ko);
                LDSM_X4(bl0, bl1, bl2, bl3, cb + B64_LO + bOff[g] + ko);
#pragma unroll
                for (int t = 0; t < 2; t++) {
                    MMA_BF16(acc[t][2*g],   ah[t], bh0, bh2);
                    MMA_BF16(acc[t][2*g],   ah[t], bl0, bl2);
                    MMA_BF16(acc[t][2*g],   al[t], bh0, bh2);
                    MMA_BF16(acc[t][2*g+1], ah[t], bh1, bh3);
                    MMA_BF16(acc[t][2*g+1], ah[t], bl1, bl3);
                    MMA_BF16(acc[t][2*g+1], al[t], bh1, bh3);
                }
            }
        }
        if (more) {
            CP_WAIT0();
            __syncthreads();
            buf ^= 1;
        }
    }

    const int rbase = warp_m*32 + (lane >> 2);
    const int cbase = n0 + warp_n*32 + (lane & 3)*2;
#pragma unroll
    for (int t = 0; t < 2; t++) {
#pragma unroll
        for (int n = 0; n < 4; n++) {
#pragma unroll
            for (int h = 0; h < 2; h++) {
                const int r  = rbase + t*16 + h*8;
                const int gr = bz*TDEC + r;
                const int c  = cbase + n*8;
                const float a0 = acc[t][n][2*h], a1 = acc[t][n][2*h+1];
                if (EPI == 1) {
                    float mr = mrow[gr];
                    float v0 = mr + mcol[(long)bz*TENC + c]     + __logf(a0);
                    float v1 = mr + mcol[(long)bz*TENC + c + 1] + __logf(a1);
                    uint32_t hh, ll;
                    split2(v0, v1, hh, ll);
                    *(uint32_t*)(oHi + (long)gr*TENC + c) = hh;
                    *(uint32_t*)(oLo + (long)gr*TENC + c) = ll;
                } else {
                    const long ib = (long)bz*H2 + c;
                    float cc0 = 0.f, cc1 = 0.f;
#pragma unroll
                    for (int js = 0; js < 8; js++) {
                        cc0 += partC[((long)bz*8 + js)*H2 + c];
                        cc1 += partC[((long)bz*8 + js)*H2 + c + 1];
                    }
                    float o0 = (dp[(long)gr*H2 + c]   + bias[c])   * Senc[ib]   + cc0 - a0;
                    float o1 = (dp[(long)gr*H2 + c+1] + bias[c+1]) * Senc[ib+1] + cc1 - a1;
                    float2 ov; ov.x = o0; ov.y = o1;
                    *(float2*)(out + (long)gr*H2 + c) = ov;
                }
            }
        }
    }
}

// ---------------------------------------------------------------------------
extern "C" void kernel_launch(void* const* d_in, const int* in_sizes, int n_in,
                              void* d_out, int out_size)
{
    const float* enc  = (const float*)d_in[0];
    const float* dec  = (const float*)d_in[1];
    const float* W    = (const float*)d_in[2];
    const float* bias = (const float*)d_in[3];
    float* out = (float*)d_out;

    float *dp, *ep, *mdp, *mep, *Senc, *pS, *pC;
    __nv_bfloat16 *ehi, *elo, *ethi, *etlo, *dhi, *dlo, *wehi, *welo, *wdhi, *wdlo;
    __nv_bfloat16 *Ahi, *Alo, *Ehi, *Elo, *Lhi, *Llo;
    cudaGetSymbolAddress((void**)&dp,   g_dp);
    cudaGetSymbolAddress((void**)&ep,   g_ep);
    cudaGetSymbolAddress((void**)&mdp,  g_mdp);
    cudaGetSymbolAddress((void**)&mep,  g_mep);
    cudaGetSymbolAddress((void**)&Senc, g_Senc);
    cudaGetSymbolAddress((void**)&pS,   g_partS);
    cudaGetSymbolAddress((void**)&pC,   g_partC);
    cudaGetSymbolAddress((void**)&ehi,  g_enc_hi);
    cudaGetSymbolAddress((void**)&elo,  g_enc_lo);
    cudaGetSymbolAddress((void**)&ethi, g_encT_hi);
    cudaGetSymbolAddress((void**)&etlo, g_encT_lo);
    cudaGetSymbolAddress((void**)&dhi,  g_dec_hi);
    cudaGetSymbolAddress((void**)&dlo,  g_dec_lo);
    cudaGetSymbolAddress((void**)&wehi, g_We_hi);
    cudaGetSymbolAddress((void**)&welo, g_We_lo);
    cudaGetSymbolAddress((void**)&wdhi, g_Wd_hi);
    cudaGetSymbolAddress((void**)&wdlo, g_Wd_lo);
    cudaGetSymbolAddress((void**)&Ahi,  g_Ahi);
    cudaGetSymbolAddress((void**)&Alo,  g_Alo);
    cudaGetSymbolAddress((void**)&Ehi,  g_Ehi);
    cudaGetSymbolAddress((void**)&Elo,  g_Elo);
    cudaGetSymbolAddress((void**)&Lhi,  g_Lhi);
    cudaGetSymbolAddress((void**)&Llo,  g_Llo);

    cudaFuncSetAttribute(gemm_mma_dual, cudaFuncAttributeMaxDynamicSharedMemorySize, MMA_SMEM);
    cudaFuncSetAttribute(mma64<1>, cudaFuncAttributeMaxDynamicSharedMemorySize, SMEM64);
    cudaFuncSetAttribute(mma64<2>, cudaFuncAttributeMaxDynamicSharedMemorySize, SMEM64);

    // 0: all conversions + encT + partS in one launch
    conv_all<<<2816, 256>>>(enc, dec, W, ehi, elo, ethi, etlo,
                            dhi, dlo, wdhi, wdlo, wehi, welo, pS);
    // 1: ep and dp GEMMs in one launch (144 CTAs ~ one wave)
    gemm_mma_dual<<<dim3(4, 36), 256, MMA_SMEM>>>(
        ehi, elo, wehi, welo, ep, dhi, dlo, wdhi, wdlo, dp);
    // 2: E and A rowmax+exp in one launch
    rowmax_both<<<2304, 256>>>(ep, dp, bias, Ehi, Elo, mep, Ahi, Alo, mdp);
    // 3: partC + Senc finalize
    colreduceC_plus<<<dim3(2, NB, 8), 256>>>(enc, ep, pC, pS, Senc);
    // 4: L = mdp + mep + log(A @ E^T) -> hi/lo
    mma64<1><<<dim3(4, 1, NB), 256, SMEM64>>>(
        Ahi, Alo, (long)TDEC*H2, Ehi, Elo, (long)TENC*H2,
        mdp, mep, Lhi, Llo, nullptr, nullptr, nullptr, nullptr, nullptr);
    // 5: context = (dp+bias)*Senc + sum(partC) - L @ enc
    mma64<2><<<dim3(4, 1, NB), 256, SMEM64>>>(
        Lhi, Llo, (long)TDEC*TENC, ethi, etlo, (long)H2*TENC,
        nullptr, nullptr, nullptr, nullptr, dp, bias, Senc, pC, out);
}

// round 7
// speedup vs baseline: 2.8295x; 1.2476x over previous
#include <cuda_runtime.h>
#include <cuda_bf16.h>
#include <cstdint>
#include <math.h>

#define H2   512
#define NB   8
#define TDEC 64
#define TENC 512
#define MDEC (NB*TDEC)   // 512
#define MENC (NB*TENC)   // 4096

// ---------------- scratch ----------------
__device__ float g_dp[MDEC*H2];
__device__ float g_ep[MENC*H2];
__device__ float g_mdp[MDEC];
__device__ float g_mep[MENC];
__device__ float g_Senc[NB*H2];
__device__ float g_partS[NB*16*H2];
__device__ float g_partC[NB*32*H2];
__device__ __nv_bfloat16 g_enc_hi[MENC*H2];
__device__ __nv_bfloat16 g_enc_lo[MENC*H2];
__device__ __nv_bfloat16 g_encT_hi[MENC*H2];
__device__ __nv_bfloat16 g_encT_lo[MENC*H2];
__device__ __nv_bfloat16 g_dec_hi[MDEC*H2];
__device__ __nv_bfloat16 g_dec_lo[MDEC*H2];
__device__ __nv_bfloat16 g_We_hi[H2*H2];
__device__ __nv_bfloat16 g_We_lo[H2*H2];
__device__ __nv_bfloat16 g_Wd_hi[H2*H2];
__device__ __nv_bfloat16 g_Wd_lo[H2*H2];
__device__ __nv_bfloat16 g_Ahi[MDEC*H2];
__device__ __nv_bfloat16 g_Alo[MDEC*H2];
__device__ __nv_bfloat16 g_Ehi[MENC*H2];
__device__ __nv_bfloat16 g_Elo[MENC*H2];
__device__ __nv_bfloat16 g_Lhi[MDEC*TENC];
__device__ __nv_bfloat16 g_Llo[MDEC*TENC];

__device__ __forceinline__ uint32_t smem_to_u32(const void* p) {
    uint32_t a;
    asm("{ .reg .u64 tmp; cvta.to.shared.u64 tmp, %1; cvt.u32.u64 %0, tmp; }" : "=r"(a) : "l"(p));
    return a;
}

// ---------------- cp.async ----------------
#define CP_ASYNC16(s, g) asm volatile("cp.async.cg.shared.global [%0], [%1], 16;" :: "r"(s), "l"(g))
#define CP_COMMIT()      asm volatile("cp.async.commit_group;")
#define CP_WAIT0()       asm volatile("cp.async.wait_group 0;" ::: "memory")

// ---------------- mma / ldmatrix ----------------
#define LDSM_X4(r0,r1,r2,r3,addr) \
    asm volatile("ldmatrix.sync.aligned.m8n8.x4.shared.b16 {%0,%1,%2,%3}, [%4];" \
        : "=r"(r0), "=r"(r1), "=r"(r2), "=r"(r3) : "r"(addr))

#define MMA_BF16(ac, a, b0, b1) \
    asm volatile("mma.sync.aligned.m16n8k16.row.col.f32.bf16.bf16.f32 " \
        "{%0,%1,%2,%3}, {%4,%5,%6,%7}, {%8,%9}, {%0,%1,%2,%3};" \
        : "+f"((ac)[0]), "+f"((ac)[1]), "+f"((ac)[2]), "+f"((ac)[3]) \
        : "r"((a)[0]), "r"((a)[1]), "r"((a)[2]), "r"((a)[3]), "r"(b0), "r"(b1))

// ---------------- hi/lo split ----------------
__device__ __forceinline__ void split2(float a, float b, uint32_t& hi, uint32_t& lo){
    __nv_bfloat16 ha = __float2bfloat16(a), hb = __float2bfloat16(b);
    __nv_bfloat16 la = __float2bfloat16(a - __bfloat162float(ha));
    __nv_bfloat16 lb = __float2bfloat16(b - __bfloat162float(hb));
    hi = ((uint32_t)__bfloat16_as_ushort(hb) << 16) | __bfloat16_as_ushort(ha);
    lo = ((uint32_t)__bfloat16_as_ushort(lb) << 16) | __bfloat16_as_ushort(la);
}
__device__ __forceinline__ void split1(float a, unsigned short& hi, unsigned short& lo){
    __nv_bfloat16 ha = __float2bfloat16(a);
    __nv_bfloat16 la = __float2bfloat16(a - __bfloat162float(ha));
    hi = __bfloat16_as_ushort(ha);
    lo = __bfloat16_as_ushort(la);
}

// ---------------------------------------------------------------------------
// conv_all (unchanged): enc hi/lo + encT + partS; dec hi/lo; W hi/lo.
// ---------------------------------------------------------------------------
__global__ void __launch_bounds__(256) conv_all(
    const float* __restrict__ enc, const float* __restrict__ dec,
    const float* __restrict__ W,
    __nv_bfloat16* __restrict__ ehi, __nv_bfloat16* __restrict__ elo,
    __nv_bfloat16* __restrict__ ethi, __nv_bfloat16* __restrict__ etlo,
    __nv_bfloat16* __restrict__ dhi, __nv_bfloat16* __restrict__ dlo,
    __nv_bfloat16* __restrict__ wdhi, __nv_bfloat16* __restrict__ wdlo,
    __nv_bfloat16* __restrict__ wehi, __nv_bfloat16* __restrict__ welo,
    float* __restrict__ partS)
{
    const int bid = blockIdx.x;
    const int tid = threadIdx.x;
    if (bid < 2048) {
        __shared__ unsigned short sh[32][33], sl[32][33];
        __shared__ float ssum[8][32];
        const int b  = bid >> 8;
        const int jt = (bid >> 4) & 15;
        const int dT = (bid & 15) * 32;
        const int jT = jt * 32;
        const int x = tid & 31, y = tid >> 5;
        float csum = 0.f;
#pragma unroll
        for (int k = 0; k < 4; k++) {
            const int row = y + k*8;
            const long src = ((long)b*512 + jT + row)*512 + dT + x;
            float v = enc[src];
            csum += v;
            unsigned short h, l;
            split1(v, h, l);
            sh[row][x] = h; sl[row][x] = l;
            ((unsigned short*)ehi)[src] = h;
            ((unsigned short*)elo)[src] = l;
        }
        ssum[y][x] = csum;
        __syncthreads();
#pragma unroll
        for (int k = 0; k < 4; k++) {
            const int row = y + k*8;
            const long dst = ((long)b*512 + dT + row)*512 + jT + x;
            ((unsigned short*)ethi)[dst] = sh[x][row];
            ((unsigned short*)etlo)[dst] = sl[x][row];
        }
        if (y == 0) {
            float s = ssum[0][x];
#pragma unroll
            for (int w = 1; w < 8; w++) s += ssum[w][x];
            partS[((long)b*16 + jt)*512 + dT + x] = s;
        }
    } else if (bid < 2304) {
        const int i = (bid - 2048)*256 + tid;
        float4 v = ((const float4*)dec)[i];
        uint2 h, l;
        split2(v.x, v.y, h.x, l.x);
        split2(v.z, v.w, h.y, l.y);
        ((uint2*)dhi)[i] = h;
        ((uint2*)dlo)[i] = l;
    } else {
        const int i = (bid - 2304)*256 + tid;
        const int o = i >> 8, q = i & 255;
        float4 v = *(const float4*)(W + (long)o*1024 + q*4);
        uint2 h, l;
        split2(v.x, v.y, h.x, l.x);
        split2(v.z, v.w, h.y, l.y);
        const int c = q & 127;
        __nv_bfloat16* ph = (q < 128) ? wdhi : wehi;
        __nv_bfloat16* pl = (q < 128) ? wdlo : welo;
        ((uint2*)(ph + (long)o*512))[c] = h;
        ((uint2*)(pl + (long)o*512))[c] = l;
    }
}

// ---------------------------------------------------------------------------
// 128x128 HMMA GEMM (dual): blockIdx.y < 32 -> ep, else dp
// ---------------------------------------------------------------------------
#define ARR_PITCH 10240            // 128 rows * 80 B
#define BUF_PITCH (4*ARR_PITCH)
#define MMA_SMEM  (2*BUF_PITCH)    // 81920 B

__global__ void __launch_bounds__(256, 1) gemm_mma_dual(
    const __nv_bfloat16* __restrict__ eAhi, const __nv_bfloat16* __restrict__ eAlo,
    const __nv_bfloat16* __restrict__ eBhi, const __nv_bfloat16* __restrict__ eBlo,
    float* __restrict__ eC,
    const __nv_bfloat16* __restrict__ dAhi, const __nv_bfloat16* __restrict__ dAlo,
    const __nv_bfloat16* __restrict__ dBhi, const __nv_bfloat16* __restrict__ dBlo,
    float* __restrict__ dC)
{
    extern __shared__ char smem[];
    const uint32_t sb = smem_to_u32(smem);
    const int tid  = threadIdx.x;
    const int lane = tid & 31, wid = tid >> 5;
    const int warp_m = wid & 3, warp_n = wid >> 2;
    const bool isEp = blockIdx.y < 32;
    const int m0 = (isEp ? blockIdx.y : blockIdx.y - 32) * 128;
    const int n0 = blockIdx.x * 128;
    const __nv_bfloat16* Ahi = isEp ? eAhi : dAhi;
    const __nv_bfloat16* Alo = isEp ? eAlo : dAlo;
    const __nv_bfloat16* Bhi = isEp ? eBhi : dBhi;
    const __nv_bfloat16* Blo = isEp ? eBlo : dBlo;
    float* C = isEp ? eC : dC;

    const int ch0row = tid >> 2, ch0cc = (tid & 3);
    const int ch1row = (tid + 256) >> 2, ch1cc = ch0cc;
    const long gA0 = (long)(m0 + ch0row)*H2 + ch0cc*8;
    const long gA1 = (long)(m0 + ch1row)*H2 + ch1cc*8;
    const long gB0 = (long)(n0 + ch0row)*H2 + ch0cc*8;
    const long gB1 = (long)(n0 + ch1row)*H2 + ch1cc*8;
    const uint32_t s0 = ch0row*80 + ch0cc*16;
    const uint32_t s1 = ch1row*80 + ch1cc*16;

    const int lrow = lane & 15;
    const int lk   = (lane >> 4) * 8;
    uint32_t aOff[2], bOff[4];
#pragma unroll
    for (int t = 0; t < 2; t++)
        aOff[t] = (uint32_t)(((warp_m*32 + t*16 + lrow)*40 + lk)*2);
#pragma unroll
    for (int g = 0; g < 4; g++)
        bOff[g] = (uint32_t)(((warp_n*64 + g*16 + lrow)*40 + lk)*2);

    float acc[2][8][4];
#pragma unroll
    for (int t = 0; t < 2; t++)
#pragma unroll
        for (int n = 0; n < 8; n++)
#pragma unroll
            for (int q = 0; q < 4; q++) acc[t][n][q] = 0.f;

    {
        CP_ASYNC16(sb + s0,                (const char*)(Ahi + gA0));
        CP_ASYNC16(sb + s1,                (const char*)(Ahi + gA1));
        CP_ASYNC16(sb + ARR_PITCH   + s0,  (const char*)(Alo + gA0));
        CP_ASYNC16(sb + ARR_PITCH   + s1,  (const char*)(Alo + gA1));
        CP_ASYNC16(sb + 2*ARR_PITCH + s0,  (const char*)(Bhi + gB0));
        CP_ASYNC16(sb + 2*ARR_PITCH + s1,  (const char*)(Bhi + gB1));
        CP_ASYNC16(sb + 3*ARR_PITCH + s0,  (const char*)(Blo + gB0));
        CP_ASYNC16(sb + 3*ARR_PITCH + s1,  (const char*)(Blo + gB1));
        CP_COMMIT();
        CP_WAIT0();
    }
    __syncthreads();

    int buf = 0;
    for (int kc = 0; kc < 16; kc++) {
        const bool more = (kc + 1) < 16;
        if (more) {
            const uint32_t db = sb + (buf ^ 1)*BUF_PITCH;
            const long gk = (kc + 1)*32;
            CP_ASYNC16(db + s0,                (const char*)(Ahi + gA0 + gk));
            CP_ASYNC16(db + s1,                (const char*)(Ahi + gA1 + gk));
            CP_ASYNC16(db + ARR_PITCH   + s0,  (const char*)(Alo + gA0 + gk));
            CP_ASYNC16(db + ARR_PITCH   + s1,  (const char*)(Alo + gA1 + gk));
            CP_ASYNC16(db + 2*ARR_PITCH + s0,  (const char*)(Bhi + gB0 + gk));
            CP_ASYNC16(db + 2*ARR_PITCH + s1,  (const char*)(Bhi + gB1 + gk));
            CP_ASYNC16(db + 3*ARR_PITCH + s0,  (const char*)(Blo + gB0 + gk));
            CP_ASYNC16(db + 3*ARR_PITCH + s1,  (const char*)(Blo + gB1 + gk));
            CP_COMMIT();
        }
        const uint32_t cb = sb + buf*BUF_PITCH;
#pragma unroll
        for (int kk = 0; kk < 2; kk++) {
            const uint32_t ko = kk*32;
            uint32_t ah[2][4], al[2][4];
#pragma unroll
            for (int t = 0; t < 2; t++) {
                LDSM_X4(ah[t][0], ah[t][1], ah[t][2], ah[t][3], cb + aOff[t] + ko);
                LDSM_X4(al[t][0], al[t][1], al[t][2], al[t][3], cb + ARR_PITCH + aOff[t] + ko);
            }
#pragma unroll
            for (int g = 0; g < 4; g++) {
                uint32_t bh0, bh1, bh2, bh3, bl0, bl1, bl2, bl3;
                LDSM_X4(bh0, bh1, bh2, bh3, cb + 2*ARR_PITCH + bOff[g] + ko);
                LDSM_X4(bl0, bl1, bl2, bl3, cb + 3*ARR_PITCH + bOff[g] + ko);
#pragma unroll
                for (int t = 0; t < 2; t++) {
                    MMA_BF16(acc[t][2*g],   ah[t], bh0, bh2);
                    MMA_BF16(acc[t][2*g],   ah[t], bl0, bl2);
                    MMA_BF16(acc[t][2*g],   al[t], bh0, bh2);
                    MMA_BF16(acc[t][2*g+1], ah[t], bh1, bh3);
                    MMA_BF16(acc[t][2*g+1], ah[t], bl1, bl3);
                    MMA_BF16(acc[t][2*g+1], al[t], bh1, bh3);
                }
            }
        }
        if (more) {
            CP_WAIT0();
            __syncthreads();
            buf ^= 1;
        }
    }

    const int rbase = m0 + warp_m*32 + (lane >> 2);
    const int cbase = n0 + warp_n*64 + (lane & 3)*2;
#pragma unroll
    for (int t = 0; t < 2; t++) {
#pragma unroll
        for (int n = 0; n < 8; n++) {
            const int r = rbase + t*16;
            const int c = cbase + n*8;
            float2 v0; v0.x = acc[t][n][0]; v0.y = acc[t][n][1];
            float2 v1; v1.x = acc[t][n][2]; v1.y = acc[t][n][3];
            *(float2*)(C + (long)r*H2 + c)       = v0;
            *(float2*)(C + (long)(r + 8)*H2 + c) = v1;
        }
    }
}

// ---------------------------------------------------------------------------
// rowmax + exp -> bf16 hi/lo (unchanged)
// ---------------------------------------------------------------------------
__global__ void __launch_bounds__(256) rowmax_both(
    const float* __restrict__ ep, const float* __restrict__ dp,
    const float* __restrict__ bias,
    __nv_bfloat16* __restrict__ Ehi, __nv_bfloat16* __restrict__ Elo, float* __restrict__ mep,
    __nv_bfloat16* __restrict__ Ahi, __nv_bfloat16* __restrict__ Alo, float* __restrict__ mdp)
{
    const int bid = blockIdx.x;
    const int t = threadIdx.x;
    const int half = t >> 7;
    const int lane128 = t & 127;
    const bool isE = bid < 2048;
    const long r = (long)(isE ? bid : bid - 2048)*2 + half;
    const float* in = isE ? ep : dp;
    __nv_bfloat16* oh = isE ? Ehi : Ahi;
    __nv_bfloat16* ol = isE ? Elo : Alo;
    float* om = isE ? mep : mdp;

    float4 v = *(const float4*)(in + r*H2 + lane128*4);
    if (isE) {
        float4 bv = *(const float4*)(bias + lane128*4);
        v.x += bv.x; v.y += bv.y; v.z += bv.z; v.w += bv.w;
    }
    float m = fmaxf(fmaxf(v.x, v.y), fmaxf(v.z, v.w));
#pragma unroll
    for (int o = 16; o; o >>= 1) m = fmaxf(m, __shfl_xor_sync(0xffffffffu, m, o));
    __shared__ float sm[8];
    if ((t & 31) == 0) sm[t >> 5] = m;
    __syncthreads();
    const int wb = half*4;
    float M = fmaxf(fmaxf(sm[wb], sm[wb+1]), fmaxf(sm[wb+2], sm[wb+3]));
    float e0 = __expf(v.x - M), e1 = __expf(v.y - M);
    float e2 = __expf(v.z - M), e3 = __expf(v.w - M);
    uint2 h, l;
    split2(e0, e1, h.x, l.x);
    split2(e2, e3, h.y, l.y);
    ((uint2*)(oh + r*H2))[lane128] = h;
    ((uint2*)(ol + r*H2))[lane128] = l;
    if (lane128 == 0) om[r] = M;
}

// ---------------------------------------------------------------------------
// colreduceC: 32 j-splits of 16 rows -> 512 CTAs. js==0 finalizes Senc.
// ---------------------------------------------------------------------------
__global__ void __launch_bounds__(256) colreduceC_plus(
    const float* __restrict__ enc, const float* __restrict__ ep,
    float* __restrict__ partC,
    const float* __restrict__ partS, float* __restrict__ Senc)
{
    const int b  = blockIdx.y;
    const int js = blockIdx.z;
    const int d  = blockIdx.x * 256 + threadIdx.x;
    const float* e = enc + (long)b*TENC*H2 + (long)js*16*H2 + d;
    const float* p = ep  + (long)b*TENC*H2 + (long)js*16*H2 + d;
    float c = 0.f;
#pragma unroll
    for (int j = 0; j < 16; j++) c += p[(long)j*H2] * e[(long)j*H2];
    partC[((long)b*32 + js)*H2 + d] = c;
    if (js == 0) {
        float s = 0.f;
#pragma unroll
        for (int q = 0; q < 16; q++) s += partS[((long)b*16 + q)*H2 + d];
        Senc[(long)b*H2 + d] = s;
    }
}

// ---------------------------------------------------------------------------
// 64x64 batched HMMA GEMM, C = A*B^T per batch (bz), K=512. Grid (8,1,8).
// EPI==1: v = mrow[gr] + mcol[bz*512+c] + log(acc) -> hi/lo bf16 out
// EPI==2: out = (dp+bias)*Senc + Cc(smem) - acc    -> fp32 out
// ---------------------------------------------------------------------------
#define A64_HI 0
#define A64_LO 5120
#define B64_HI 10240
#define B64_LO 15360
#define BUF64  20480
#define SMEM64 40960

template<int EPI>
__global__ void __launch_bounds__(256, 1) mma64(
    const __nv_bfloat16* __restrict__ Ahi, const __nv_bfloat16* __restrict__ Alo, long sA,
    const __nv_bfloat16* __restrict__ Bhi, const __nv_bfloat16* __restrict__ Blo, long sB,
    const float* __restrict__ mrow, const float* __restrict__ mcol,
    __nv_bfloat16* __restrict__ oHi, __nv_bfloat16* __restrict__ oLo,
    const float* __restrict__ dp, const float* __restrict__ bias,
    const float* __restrict__ Senc, const float* __restrict__ partC,
    float* __restrict__ out)
{
    extern __shared__ char smem[];
    __shared__ float sCc[64];
    const uint32_t sb = smem_to_u32(smem);
    const int tid  = threadIdx.x;
    const int lane = tid & 31, wid = tid >> 5;
    const int warp_m = wid & 1, warp_n = wid >> 1;   // 2 x 4
    const int bz = blockIdx.z;
    const int n0 = blockIdx.x * 64;

    const __nv_bfloat16* Ah = Ahi + (long)bz*sA;
    const __nv_bfloat16* Al = Alo + (long)bz*sA;
    const __nv_bfloat16* Bh = Bhi + (long)bz*sB;
    const __nv_bfloat16* Bl = Blo + (long)bz*sB;

    const int rowA = tid >> 2, cc = tid & 3;
    const long gA = (long)rowA*H2 + cc*8;
    const long gB = (long)(n0 + rowA)*H2 + cc*8;
    const uint32_t sOff = rowA*80 + cc*16;

    const int lrow = lane & 15;
    const int lk   = (lane >> 4) * 8;
    uint32_t aOff[2];
#pragma unroll
    for (int t = 0; t < 2; t++)
        aOff[t] = (uint32_t)(((warp_m*32 + t*16 + lrow)*40 + lk)*2);
    const uint32_t bOff = (uint32_t)(((warp_n*16 + lrow)*40 + lk)*2);

    float acc[2][2][4];
#pragma unroll
    for (int t = 0; t < 2; t++)
#pragma unroll
        for (int n = 0; n < 2; n++)
#pragma unroll
            for (int q = 0; q < 4; q++) acc[t][n][q] = 0.f;

    {
        CP_ASYNC16(sb + A64_HI + sOff, (const char*)(Ah + gA));
        CP_ASYNC16(sb + A64_LO + sOff, (const char*)(Al + gA));
        CP_ASYNC16(sb + B64_HI + sOff, (const char*)(Bh + gB));
        CP_ASYNC16(sb + B64_LO + sOff, (const char*)(Bl + gB));
        CP_COMMIT();
    }
    // overlap: finalize Cc for this CTA's 64 columns while loads fly
    if (EPI == 2 && tid < 64) {
        float s = 0.f;
#pragma unroll
        for (int js = 0; js < 32; js++)
            s += partC[((long)bz*32 + js)*H2 + n0 + tid];
        sCc[tid] = s;
    }
    CP_WAIT0();
    __syncthreads();

    int buf = 0;
    for (int kc = 0; kc < 16; kc++) {
        const bool more = (kc + 1) < 16;
        if (more) {
            const uint32_t db = sb + (buf ^ 1)*BUF64;
            const long gk = (kc + 1)*32;
            CP_ASYNC16(db + A64_HI + sOff, (const char*)(Ah + gA + gk));
            CP_ASYNC16(db + A64_LO + sOff, (const char*)(Al + gA + gk));
            CP_ASYNC16(db + B64_HI + sOff, (const char*)(Bh + gB + gk));
            CP_ASYNC16(db + B64_LO + sOff, (const char*)(Bl + gB + gk));
            CP_COMMIT();
        }
        const uint32_t cb = sb + buf*BUF64;
#pragma unroll
        for (int kk = 0; kk < 2; kk++) {
            const uint32_t ko = kk*32;
            uint32_t ah[2][4], al[2][4];
#pragma unroll
            for (int t = 0; t < 2; t++) {
                LDSM_X4(ah[t][0], ah[t][1], ah[t][2], ah[t][3], cb + A64_HI + aOff[t] + ko);
                LDSM_X4(al[t][0], al[t][1], al[t][2], al[t][3], cb + A64_LO + aOff[t] + ko);
            }
            uint32_t bh0, bh1, bh2, bh3, bl0, bl1, bl2, bl3;
            LDSM_X4(bh0, bh1, bh2, bh3, cb + B64_HI + bOff + ko);
            LDSM_X4(bl0, bl1, bl2, bl3, cb + B64_LO + bOff + ko);
#pragma unroll
            for (int t = 0; t < 2; t++) {
                MMA_BF16(acc[t][0], ah[t], bh0, bh2);
                MMA_BF16(acc[t][0], ah[t], bl0, bl2);
                MMA_BF16(acc[t][0], al[t], bh0, bh2);
                MMA_BF16(acc[t][1], ah[t], bh1, bh3);
                MMA_BF16(acc[t][1], ah[t], bl1, bl3);
                MMA_BF16(acc[t][1], al[t], bh1, bh3);
            }
        }
        if (more) {
            CP_WAIT0();
            __syncthreads();
            buf ^= 1;
        }
    }

    const int rbase = warp_m*32 + (lane >> 2);
    const int cbase = n0 + warp_n*16 + (lane & 3)*2;
#pragma unroll
    for (int t = 0; t < 2; t++) {
#pragma unroll
        for (int n = 0; n < 2; n++) {
#pragma unroll
            for (int h = 0; h < 2; h++) {
                const int r  = rbase + t*16 + h*8;
                const int gr = bz*TDEC + r;
                const int c  = cbase + n*8;
                const float a0 = acc[t][n][2*h], a1 = acc[t][n][2*h+1];
                if (EPI == 1) {
                    float mr = mrow[gr];
                    float v0 = mr + mcol[(long)bz*TENC + c]     + __logf(a0);
                    float v1 = mr + mcol[(long)bz*TENC + c + 1] + __logf(a1);
                    uint32_t hh, ll;
                    split2(v0, v1, hh, ll);
                    *(uint32_t*)(oHi + (long)gr*TENC + c) = hh;
                    *(uint32_t*)(oLo + (long)gr*TENC + c) = ll;
                } else {
                    const long ib = (long)bz*H2 + c;
                    float o0 = (dp[(long)gr*H2 + c]   + bias[c])   * Senc[ib]   + sCc[c - n0]     - a0;
                    float o1 = (dp[(long)gr*H2 + c+1] + bias[c+1]) * Senc[ib+1] + sCc[c - n0 + 1] - a1;
                    float2 ov; ov.x = o0; ov.y = o1;
                    *(float2*)(out + (long)gr*H2 + c) = ov;
                }
            }
        }
    }
}

// ---------------------------------------------------------------------------
extern "C" void kernel_launch(void* const* d_in, const int* in_sizes, int n_in,
                              void* d_out, int out_size)
{
    const float* enc  = (const float*)d_in[0];
    const float* dec  = (const float*)d_in[1];
    const float* W    = (const float*)d_in[2];
    const float* bias = (const float*)d_in[3];
    float* out = (float*)d_out;

    float *dp, *ep, *mdp, *mep, *Senc, *pS, *pC;
    __nv_bfloat16 *ehi, *elo, *ethi, *etlo, *dhi, *dlo, *wehi, *welo, *wdhi, *wdlo;
    __nv_bfloat16 *Ahi, *Alo, *Ehi, *Elo, *Lhi, *Llo;
    cudaGetSymbolAddress((void**)&dp,   g_dp);
    cudaGetSymbolAddress((void**)&ep,   g_ep);
    cudaGetSymbolAddress((void**)&mdp,  g_mdp);
    cudaGetSymbolAddress((void**)&mep,  g_mep);
    cudaGetSymbolAddress((void**)&Senc, g_Senc);
    cudaGetSymbolAddress((void**)&pS,   g_partS);
    cudaGetSymbolAddress((void**)&pC,   g_partC);
    cudaGetSymbolAddress((void**)&ehi,  g_enc_hi);
    cudaGetSymbolAddress((void**)&elo,  g_enc_lo);
    cudaGetSymbolAddress((void**)&ethi, g_encT_hi);
    cudaGetSymbolAddress((void**)&etlo, g_encT_lo);
    cudaGetSymbolAddress((void**)&dhi,  g_dec_hi);
    cudaGetSymbolAddress((void**)&dlo,  g_dec_lo);
    cudaGetSymbolAddress((void**)&wehi, g_We_hi);
    cudaGetSymbolAddress((void**)&welo, g_We_lo);
    cudaGetSymbolAddress((void**)&wdhi, g_Wd_hi);
    cudaGetSymbolAddress((void**)&wdlo, g_Wd_lo);
    cudaGetSymbolAddress((void**)&Ahi,  g_Ahi);
    cudaGetSymbolAddress((void**)&Alo,  g_Alo);
    cudaGetSymbolAddress((void**)&Ehi,  g_Ehi);
    cudaGetSymbolAddress((void**)&Elo,  g_Elo);
    cudaGetSymbolAddress((void**)&Lhi,  g_Lhi);
    cudaGetSymbolAddress((void**)&Llo,  g_Llo);

    cudaFuncSetAttribute(gemm_mma_dual, cudaFuncAttributeMaxDynamicSharedMemorySize, MMA_SMEM);
    cudaFuncSetAttribute(mma64<1>, cudaFuncAttributeMaxDynamicSharedMemorySize, SMEM64);
    cudaFuncSetAttribute(mma64<2>, cudaFuncAttributeMaxDynamicSharedMemorySize, SMEM64);

    // 0: all conversions + encT + partS
    conv_all<<<2816, 256>>>(enc, dec, W, ehi, elo, ethi, etlo,
                            dhi, dlo, wdhi, wdlo, wehi, welo, pS);
    // 1: ep + dp GEMMs
    gemm_mma_dual<<<dim3(4, 36), 256, MMA_SMEM>>>(
        ehi, elo, wehi, welo, ep, dhi, dlo, wdhi, wdlo, dp);
    // 2: E + A rowmax+exp
    rowmax_both<<<2304, 256>>>(ep, dp, bias, Ehi, Elo, mep, Ahi, Alo, mdp);
    // 3: partC (32 splits) + Senc finalize
    colreduceC_plus<<<dim3(2, NB, 32), 256>>>(enc, ep, pC, pS, Senc);
    // 4: L = mdp + mep + log(A @ E^T) -> hi/lo
    mma64<1><<<dim3(8, 1, NB), 256, SMEM64>>>(
        Ahi, Alo, (long)TDEC*H2, Ehi, Elo, (long)TENC*H2,
        mdp, mep, Lhi, Llo, nullptr, nullptr, nullptr, nullptr, nullptr);
    // 5: context = (dp+bias)*Senc + Cc - L @ enc
    mma64<2><<<dim3(8, 1, NB), 256, SMEM64>>>(
        Lhi, Llo, (long)TDEC*TENC, ethi, etlo, (long)H2*TENC,
        nullptr, nullptr, nullptr, nullptr, dp, bias, Senc, pC, out);
}

// round 8
// speedup vs baseline: 2.9215x; 1.0325x over previous
#include <cuda_runtime.h>
#include <cuda_bf16.h>
#include <cstdint>
#include <math.h>

#define H2   512
#define NB   8
#define TDEC 64
#define TENC 512
#define MDEC (NB*TDEC)   // 512
#define MENC (NB*TENC)   // 4096

// ---------------- scratch ----------------
__device__ float g_dp[MDEC*H2];
__device__ float g_ep[MENC*H2];
__device__ float g_mdp[MDEC];
__device__ float g_mep[MENC];
__device__ float g_Senc[NB*H2];
__device__ float g_partS[NB*16*H2];
__device__ float g_partC[NB*64*H2];
__device__ __nv_bfloat16 g_enc_hi[MENC*H2];
__device__ __nv_bfloat16 g_enc_lo[MENC*H2];
__device__ __nv_bfloat16 g_encT_hi[MENC*H2];
__device__ __nv_bfloat16 g_encT_lo[MENC*H2];
__device__ __nv_bfloat16 g_dec_hi[MDEC*H2];
__device__ __nv_bfloat16 g_dec_lo[MDEC*H2];
__device__ __nv_bfloat16 g_We_hi[H2*H2];
__device__ __nv_bfloat16 g_We_lo[H2*H2];
__device__ __nv_bfloat16 g_Wd_hi[H2*H2];
__device__ __nv_bfloat16 g_Wd_lo[H2*H2];
__device__ __nv_bfloat16 g_Ahi[MDEC*H2];
__device__ __nv_bfloat16 g_Alo[MDEC*H2];
__device__ __nv_bfloat16 g_Ehi[MENC*H2];
__device__ __nv_bfloat16 g_Elo[MENC*H2];
__device__ __nv_bfloat16 g_Lhi[MDEC*TENC];
__device__ __nv_bfloat16 g_Llo[MDEC*TENC];

__device__ __forceinline__ uint32_t smem_to_u32(const void* p) {
    uint32_t a;
    asm("{ .reg .u64 tmp; cvta.to.shared.u64 tmp, %1; cvt.u32.u64 %0, tmp; }" : "=r"(a) : "l"(p));
    return a;
}

// ---------------- cp.async ----------------
#define CP_ASYNC16(s, g) asm volatile("cp.async.cg.shared.global [%0], [%1], 16;" :: "r"(s), "l"(g))
#define CP_COMMIT()      asm volatile("cp.async.commit_group;")
#define CP_WAIT0()       asm volatile("cp.async.wait_group 0;" ::: "memory")

// ---------------- mma / ldmatrix ----------------
#define LDSM_X4(r0,r1,r2,r3,addr) \
    asm volatile("ldmatrix.sync.aligned.m8n8.x4.shared.b16 {%0,%1,%2,%3}, [%4];" \
        : "=r"(r0), "=r"(r1), "=r"(r2), "=r"(r3) : "r"(addr))

#define MMA_BF16(ac, a, b0, b1) \
    asm volatile("mma.sync.aligned.m16n8k16.row.col.f32.bf16.bf16.f32 " \
        "{%0,%1,%2,%3}, {%4,%5,%6,%7}, {%8,%9}, {%0,%1,%2,%3};" \
        : "+f"((ac)[0]), "+f"((ac)[1]), "+f"((ac)[2]), "+f"((ac)[3]) \
        : "r"((a)[0]), "r"((a)[1]), "r"((a)[2]), "r"((a)[3]), "r"(b0), "r"(b1))

// ---------------- hi/lo split ----------------
__device__ __forceinline__ void split2(float a, float b, uint32_t& hi, uint32_t& lo){
    __nv_bfloat16 ha = __float2bfloat16(a), hb = __float2bfloat16(b);
    __nv_bfloat16 la = __float2bfloat16(a - __bfloat162float(ha));
    __nv_bfloat16 lb = __float2bfloat16(b - __bfloat162float(hb));
    hi = ((uint32_t)__bfloat16_as_ushort(hb) << 16) | __bfloat16_as_ushort(ha);
    lo = ((uint32_t)__bfloat16_as_ushort(lb) << 16) | __bfloat16_as_ushort(la);
}
__device__ __forceinline__ void split1(float a, unsigned short& hi, unsigned short& lo){
    __nv_bfloat16 ha = __float2bfloat16(a);
    __nv_bfloat16 la = __float2bfloat16(a - __bfloat162float(ha));
    hi = __bfloat16_as_ushort(ha);
    lo = __bfloat16_as_ushort(la);
}

// ---------------------------------------------------------------------------
// conv_all: enc hi/lo + encT + partS; dec hi/lo; W hi/lo.
// ---------------------------------------------------------------------------
__global__ void __launch_bounds__(256) conv_all(
    const float* __restrict__ enc, const float* __restrict__ dec,
    const float* __restrict__ W,
    __nv_bfloat16* __restrict__ ehi, __nv_bfloat16* __restrict__ elo,
    __nv_bfloat16* __restrict__ ethi, __nv_bfloat16* __restrict__ etlo,
    __nv_bfloat16* __restrict__ dhi, __nv_bfloat16* __restrict__ dlo,
    __nv_bfloat16* __restrict__ wdhi, __nv_bfloat16* __restrict__ wdlo,
    __nv_bfloat16* __restrict__ wehi, __nv_bfloat16* __restrict__ welo,
    float* __restrict__ partS)
{
    const int bid = blockIdx.x;
    const int tid = threadIdx.x;
    if (bid < 2048) {
        __shared__ unsigned short sh[32][33], sl[32][33];
        __shared__ float ssum[8][32];
        const int b  = bid >> 8;
        const int jt = (bid >> 4) & 15;
        const int dT = (bid & 15) * 32;
        const int jT = jt * 32;
        const int x = tid & 31, y = tid >> 5;
        float csum = 0.f;
#pragma unroll
        for (int k = 0; k < 4; k++) {
            const int row = y + k*8;
            const long src = ((long)b*512 + jT + row)*512 + dT + x;
            float v = enc[src];
            csum += v;
            unsigned short h, l;
            split1(v, h, l);
            sh[row][x] = h; sl[row][x] = l;
            ((unsigned short*)ehi)[src] = h;
            ((unsigned short*)elo)[src] = l;
        }
        ssum[y][x] = csum;
        __syncthreads();
#pragma unroll
        for (int k = 0; k < 4; k++) {
            const int row = y + k*8;
            const long dst = ((long)b*512 + dT + row)*512 + jT + x;
            ((unsigned short*)ethi)[dst] = sh[x][row];
            ((unsigned short*)etlo)[dst] = sl[x][row];
        }
        if (y == 0) {
            float s = ssum[0][x];
#pragma unroll
            for (int w = 1; w < 8; w++) s += ssum[w][x];
            partS[((long)b*16 + jt)*512 + dT + x] = s;
        }
    } else if (bid < 2304) {
        const int i = (bid - 2048)*256 + tid;
        float4 v = ((const float4*)dec)[i];
        uint2 h, l;
        split2(v.x, v.y, h.x, l.x);
        split2(v.z, v.w, h.y, l.y);
        ((uint2*)dhi)[i] = h;
        ((uint2*)dlo)[i] = l;
    } else {
        const int i = (bid - 2304)*256 + tid;
        const int o = i >> 8, q = i & 255;
        float4 v = *(const float4*)(W + (long)o*1024 + q*4);
        uint2 h, l;
        split2(v.x, v.y, h.x, l.x);
        split2(v.z, v.w, h.y, l.y);
        const int c = q & 127;
        __nv_bfloat16* ph = (q < 128) ? wdhi : wehi;
        __nv_bfloat16* pl = (q < 128) ? wdlo : welo;
        ((uint2*)(ph + (long)o*512))[c] = h;
        ((uint2*)(pl + (long)o*512))[c] = l;
    }
}

// ---------------------------------------------------------------------------
// 128x128 HMMA GEMM (dual): blockIdx.y < 32 -> ep, else dp
// ---------------------------------------------------------------------------
#define ARR_PITCH 10240            // 128 rows * 80 B
#define BUF_PITCH (4*ARR_PITCH)
#define MMA_SMEM  (2*BUF_PITCH)    // 81920 B

__global__ void __launch_bounds__(256, 1) gemm_mma_dual(
    const __nv_bfloat16* __restrict__ eAhi, const __nv_bfloat16* __restrict__ eAlo,
    const __nv_bfloat16* __restrict__ eBhi, const __nv_bfloat16* __restrict__ eBlo,
    float* __restrict__ eC,
    const __nv_bfloat16* __restrict__ dAhi, const __nv_bfloat16* __restrict__ dAlo,
    const __nv_bfloat16* __restrict__ dBhi, const __nv_bfloat16* __restrict__ dBlo,
    float* __restrict__ dC)
{
    extern __shared__ char smem[];
    const uint32_t sb = smem_to_u32(smem);
    const int tid  = threadIdx.x;
    const int lane = tid & 31, wid = tid >> 5;
    const int warp_m = wid & 3, warp_n = wid >> 2;
    const bool isEp = blockIdx.y < 32;
    const int m0 = (isEp ? blockIdx.y : blockIdx.y - 32) * 128;
    const int n0 = blockIdx.x * 128;
    const __nv_bfloat16* Ahi = isEp ? eAhi : dAhi;
    const __nv_bfloat16* Alo = isEp ? eAlo : dAlo;
    const __nv_bfloat16* Bhi = isEp ? eBhi : dBhi;
    const __nv_bfloat16* Blo = isEp ? eBlo : dBlo;
    float* C = isEp ? eC : dC;

    const int ch0row = tid >> 2, ch0cc = (tid & 3);
    const int ch1row = (tid + 256) >> 2, ch1cc = ch0cc;
    const long gA0 = (long)(m0 + ch0row)*H2 + ch0cc*8;
    const long gA1 = (long)(m0 + ch1row)*H2 + ch1cc*8;
    const long gB0 = (long)(n0 + ch0row)*H2 + ch0cc*8;
    const long gB1 = (long)(n0 + ch1row)*H2 + ch1cc*8;
    const uint32_t s0 = ch0row*80 + ch0cc*16;
    const uint32_t s1 = ch1row*80 + ch1cc*16;

    const int lrow = lane & 15;
    const int lk   = (lane >> 4) * 8;
    uint32_t aOff[2], bOff[4];
#pragma unroll
    for (int t = 0; t < 2; t++)
        aOff[t] = (uint32_t)(((warp_m*32 + t*16 + lrow)*40 + lk)*2);
#pragma unroll
    for (int g = 0; g < 4; g++)
        bOff[g] = (uint32_t)(((warp_n*64 + g*16 + lrow)*40 + lk)*2);

    float acc[2][8][4];
#pragma unroll
    for (int t = 0; t < 2; t++)
#pragma unroll
        for (int n = 0; n < 8; n++)
#pragma unroll
            for (int q = 0; q < 4; q++) acc[t][n][q] = 0.f;

    {
        CP_ASYNC16(sb + s0,                (const char*)(Ahi + gA0));
        CP_ASYNC16(sb + s1,                (const char*)(Ahi + gA1));
        CP_ASYNC16(sb + ARR_PITCH   + s0,  (const char*)(Alo + gA0));
        CP_ASYNC16(sb + ARR_PITCH   + s1,  (const char*)(Alo + gA1));
        CP_ASYNC16(sb + 2*ARR_PITCH + s0,  (const char*)(Bhi + gB0));
        CP_ASYNC16(sb + 2*ARR_PITCH + s1,  (const char*)(Bhi + gB1));
        CP_ASYNC16(sb + 3*ARR_PITCH + s0,  (const char*)(Blo + gB0));
        CP_ASYNC16(sb + 3*ARR_PITCH + s1,  (const char*)(Blo + gB1));
        CP_COMMIT();
        CP_WAIT0();
    }
    __syncthreads();

    int buf = 0;
    for (int kc = 0; kc < 16; kc++) {
        const bool more = (kc + 1) < 16;
        if (more) {
            const uint32_t db = sb + (buf ^ 1)*BUF_PITCH;
            const long gk = (kc + 1)*32;
            CP_ASYNC16(db + s0,                (const char*)(Ahi + gA0 + gk));
            CP_ASYNC16(db + s1,                (const char*)(Ahi + gA1 + gk));
            CP_ASYNC16(db + ARR_PITCH   + s0,  (const char*)(Alo + gA0 + gk));
            CP_ASYNC16(db + ARR_PITCH   + s1,  (const char*)(Alo + gA1 + gk));
            CP_ASYNC16(db + 2*ARR_PITCH + s0,  (const char*)(Bhi + gB0 + gk));
            CP_ASYNC16(db + 2*ARR_PITCH + s1,  (const char*)(Bhi + gB1 + gk));
            CP_ASYNC16(db + 3*ARR_PITCH + s0,  (const char*)(Blo + gB0 + gk));
            CP_ASYNC16(db + 3*ARR_PITCH + s1,  (const char*)(Blo + gB1 + gk));
            CP_COMMIT();
        }
        const uint32_t cb = sb + buf*BUF_PITCH;
#pragma unroll
        for (int kk = 0; kk < 2; kk++) {
            const uint32_t ko = kk*32;
            uint32_t ah[2][4], al[2][4];
#pragma unroll
            for (int t = 0; t < 2; t++) {
                LDSM_X4(ah[t][0], ah[t][1], ah[t][2], ah[t][3], cb + aOff[t] + ko);
                LDSM_X4(al[t][0], al[t][1], al[t][2], al[t][3], cb + ARR_PITCH + aOff[t] + ko);
            }
#pragma unroll
            for (int g = 0; g < 4; g++) {
                uint32_t bh0, bh1, bh2, bh3, bl0, bl1, bl2, bl3;
                LDSM_X4(bh0, bh1, bh2, bh3, cb + 2*ARR_PITCH + bOff[g] + ko);
                LDSM_X4(bl0, bl1, bl2, bl3, cb + 3*ARR_PITCH + bOff[g] + ko);
#pragma unroll
                for (int t = 0; t < 2; t++) {
                    MMA_BF16(acc[t][2*g],   ah[t], bh0, bh2);
                    MMA_BF16(acc[t][2*g],   ah[t], bl0, bl2);
                    MMA_BF16(acc[t][2*g],   al[t], bh0, bh2);
                    MMA_BF16(acc[t][2*g+1], ah[t], bh1, bh3);
                    MMA_BF16(acc[t][2*g+1], ah[t], bl1, bl3);
                    MMA_BF16(acc[t][2*g+1], al[t], bh1, bh3);
                }
            }
        }
        if (more) {
            CP_WAIT0();
            __syncthreads();
            buf ^= 1;
        }
    }

    const int rbase = m0 + warp_m*32 + (lane >> 2);
    const int cbase = n0 + warp_n*64 + (lane & 3)*2;
#pragma unroll
    for (int t = 0; t < 2; t++) {
#pragma unroll
        for (int n = 0; n < 8; n++) {
            const int r = rbase + t*16;
            const int c = cbase + n*8;
            float2 v0; v0.x = acc[t][n][0]; v0.y = acc[t][n][1];
            float2 v1; v1.x = acc[t][n][2]; v1.y = acc[t][n][3];
            *(float2*)(C + (long)r*H2 + c)       = v0;
            *(float2*)(C + (long)(r + 8)*H2 + c) = v1;
        }
    }
}

// ---------------------------------------------------------------------------
// fused_mid: blocks 0..2303 = rowmax+exp (E then A); blocks 2304..3327 =
// colreduceC (64 j-splits of 8 rows) + Senc finalize on js==0.
// ---------------------------------------------------------------------------
__global__ void __launch_bounds__(256) fused_mid(
    const float* __restrict__ ep, const float* __restrict__ dp,
    const float* __restrict__ enc, const float* __restrict__ bias,
    __nv_bfloat16* __restrict__ Ehi, __nv_bfloat16* __restrict__ Elo, float* __restrict__ mep,
    __nv_bfloat16* __restrict__ Ahi, __nv_bfloat16* __restrict__ Alo, float* __restrict__ mdp,
    float* __restrict__ partC, const float* __restrict__ partS, float* __restrict__ Senc)
{
    const int bid = blockIdx.x;
    const int t = threadIdx.x;
    if (bid < 2304) {
        const int half = t >> 7;
        const int lane128 = t & 127;
        const bool isE = bid < 2048;
        const long r = (long)(isE ? bid : bid - 2048)*2 + half;
        const float* in = isE ? ep : dp;
        __nv_bfloat16* oh = isE ? Ehi : Ahi;
        __nv_bfloat16* ol = isE ? Elo : Alo;
        float* om = isE ? mep : mdp;

        float4 v = *(const float4*)(in + r*H2 + lane128*4);
        if (isE) {
            float4 bv = *(const float4*)(bias + lane128*4);
            v.x += bv.x; v.y += bv.y; v.z += bv.z; v.w += bv.w;
        }
        float m = fmaxf(fmaxf(v.x, v.y), fmaxf(v.z, v.w));
#pragma unroll
        for (int o = 16; o; o >>= 1) m = fmaxf(m, __shfl_xor_sync(0xffffffffu, m, o));
        __shared__ float sm[8];
        if ((t & 31) == 0) sm[t >> 5] = m;
        __syncthreads();
        const int wb = half*4;
        float M = fmaxf(fmaxf(sm[wb], sm[wb+1]), fmaxf(sm[wb+2], sm[wb+3]));
        float e0 = __expf(v.x - M), e1 = __expf(v.y - M);
        float e2 = __expf(v.z - M), e3 = __expf(v.w - M);
        uint2 h, l;
        split2(e0, e1, h.x, l.x);
        split2(e2, e3, h.y, l.y);
        ((uint2*)(oh + r*H2))[lane128] = h;
        ((uint2*)(ol + r*H2))[lane128] = l;
        if (lane128 == 0) om[r] = M;
    } else {
        const int bid2 = bid - 2304;        // 1024 blocks: db(1b) | b(3b) | js(6b)
        const int db = bid2 & 1;
        const int b  = (bid2 >> 1) & 7;
        const int js = bid2 >> 4;           // 0..63
        const int d  = db*256 + t;
        const float* e = enc + (long)b*TENC*H2 + (long)js*8*H2 + d;
        const float* p = ep  + (long)b*TENC*H2 + (long)js*8*H2 + d;
        float c = 0.f;
#pragma unroll
        for (int j = 0; j < 8; j++) c += p[(long)j*H2] * e[(long)j*H2];
        partC[((long)b*64 + js)*H2 + d] = c;
        if (js == 0) {
            float s = 0.f;
#pragma unroll
            for (int q = 0; q < 16; q++) s += partS[((long)b*16 + q)*H2 + d];
            Senc[(long)b*H2 + d] = s;
        }
    }
}

// ---------------------------------------------------------------------------
// 64x64 batched HMMA GEMM, C = A*B^T per batch (bz), K=512. Grid (8,1,8).
// EPI==1: v = mrow[gr] + mcol[bz*512+c] + log(acc) -> hi/lo bf16 out
// EPI==2: out = (dp+bias)*Senc + Cc(smem) - acc    -> fp32 out
// ---------------------------------------------------------------------------
#define A64_HI 0
#define A64_LO 5120
#define B64_HI 10240
#define B64_LO 15360
#define BUF64  20480
#define SMEM64 40960

template<int EPI>
__global__ void __launch_bounds__(256, 1) mma64(
    const __nv_bfloat16* __restrict__ Ahi, const __nv_bfloat16* __restrict__ Alo, long sA,
    const __nv_bfloat16* __restrict__ Bhi, const __nv_bfloat16* __restrict__ Blo, long sB,
    const float* __restrict__ mrow, const float* __restrict__ mcol,
    __nv_bfloat16* __restrict__ oHi, __nv_bfloat16* __restrict__ oLo,
    const float* __restrict__ dp, const float* __restrict__ bias,
    const float* __restrict__ Senc, const float* __restrict__ partC,
    float* __restrict__ out)
{
    extern __shared__ char smem[];
    __shared__ float sCc4[4][64];
    __shared__ float sCc[64];
    const uint32_t sb = smem_to_u32(smem);
    const int tid  = threadIdx.x;
    const int lane = tid & 31, wid = tid >> 5;
    const int warp_m = wid & 1, warp_n = wid >> 1;   // 2 x 4
    const int bz = blockIdx.z;
    const int n0 = blockIdx.x * 64;

    const __nv_bfloat16* Ah = Ahi + (long)bz*sA;
    const __nv_bfloat16* Al = Alo + (long)bz*sA;
    const __nv_bfloat16* Bh = Bhi + (long)bz*sB;
    const __nv_bfloat16* Bl = Blo + (long)bz*sB;

    const int rowA = tid >> 2, cc = tid & 3;
    const long gA = (long)rowA*H2 + cc*8;
    const long gB = (long)(n0 + rowA)*H2 + cc*8;
    const uint32_t sOff = rowA*80 + cc*16;

    const int lrow = lane & 15;
    const int lk   = (lane >> 4) * 8;
    uint32_t aOff[2];
#pragma unroll
    for (int t = 0; t < 2; t++)
        aOff[t] = (uint32_t)(((warp_m*32 + t*16 + lrow)*40 + lk)*2);
    const uint32_t bOff = (uint32_t)(((warp_n*16 + lrow)*40 + lk)*2);

    float acc[2][2][4];
#pragma unroll
    for (int t = 0; t < 2; t++)
#pragma unroll
        for (int n = 0; n < 2; n++)
#pragma unroll
            for (int q = 0; q < 4; q++) acc[t][n][q] = 0.f;

    {
        CP_ASYNC16(sb + A64_HI + sOff, (const char*)(Ah + gA));
        CP_ASYNC16(sb + A64_LO + sOff, (const char*)(Al + gA));
        CP_ASYNC16(sb + B64_HI + sOff, (const char*)(Bh + gB));
        CP_ASYNC16(sb + B64_LO + sOff, (const char*)(Bl + gB));
        CP_COMMIT();
    }
    // overlap: partial Cc sums (4 threads per column, 16 partials each)
    if (EPI == 2) {
        const int c = tid & 63, q = tid >> 6;
        float s = 0.f;
#pragma unroll
        for (int js = 0; js < 16; js++)
            s += partC[((long)bz*64 + q*16 + js)*H2 + n0 + c];
        sCc4[q][c] = s;
    }
    CP_WAIT0();
    __syncthreads();
    if (EPI == 2 && tid < 64)
        sCc[tid] = sCc4[0][tid] + sCc4[1][tid] + sCc4[2][tid] + sCc4[3][tid];

    int buf = 0;
    for (int kc = 0; kc < 16; kc++) {
        const bool more = (kc + 1) < 16;
        if (more) {
            const uint32_t db = sb + (buf ^ 1)*BUF64;
            const long gk = (kc + 1)*32;
            CP_ASYNC16(db + A64_HI + sOff, (const char*)(Ah + gA + gk));
            CP_ASYNC16(db + A64_LO + sOff, (const char*)(Al + gA + gk));
            CP_ASYNC16(db + B64_HI + sOff, (const char*)(Bh + gB + gk));
            CP_ASYNC16(db + B64_LO + sOff, (const char*)(Bl + gB + gk));
            CP_COMMIT();
        }
        const uint32_t cb = sb + buf*BUF64;
#pragma unroll
        for (int kk = 0; kk < 2; kk++) {
            const uint32_t ko = kk*32;
            uint32_t ah[2][4], al[2][4];
#pragma unroll
            for (int t = 0; t < 2; t++) {
                LDSM_X4(ah[t][0], ah[t][1], ah[t][2], ah[t][3], cb + A64_HI + aOff[t] + ko);
                LDSM_X4(al[t][0], al[t][1], al[t][2], al[t][3], cb + A64_LO + aOff[t] + ko);
            }
            uint32_t bh0, bh1, bh2, bh3, bl0, bl1, bl2, bl3;
            LDSM_X4(bh0, bh1, bh2, bh3, cb + B64_HI + bOff + ko);
            LDSM_X4(bl0, bl1, bl2, bl3, cb + B64_LO + bOff + ko);
#pragma unroll
            for (int t = 0; t < 2; t++) {
                MMA_BF16(acc[t][0], ah[t], bh0, bh2);
                MMA_BF16(acc[t][0], ah[t], bl0, bl2);
                MMA_BF16(acc[t][0], al[t], bh0, bh2);
                MMA_BF16(acc[t][1], ah[t], bh1, bh3);
                MMA_BF16(acc[t][1], ah[t], bl1, bl3);
                MMA_BF16(acc[t][1], al[t], bh1, bh3);
            }
        }
        if (more) {
            CP_WAIT0();
            __syncthreads();
            buf ^= 1;
        }
    }

    const int rbase = warp_m*32 + (lane >> 2);
    const int cbase = n0 + warp_n*16 + (lane & 3)*2;
#pragma unroll
    for (int t = 0; t < 2; t++) {
#pragma unroll
        for (int n = 0; n < 2; n++) {
#pragma unroll
            for (int h = 0; h < 2; h++) {
                const int r  = rbase + t*16 + h*8;
                const int gr = bz*TDEC + r;
                const int c  = cbase + n*8;
                const float a0 = acc[t][n][2*h], a1 = acc[t][n][2*h+1];
                if (EPI == 1) {
                    float mr = mrow[gr];
                    float v0 = mr + mcol[(long)bz*TENC + c]     + __logf(a0);
                    float v1 = mr + mcol[(long)bz*TENC + c + 1] + __logf(a1);
                    uint32_t hh, ll;
                    split2(v0, v1, hh, ll);
                    *(uint32_t*)(oHi + (long)gr*TENC + c) = hh;
                    *(uint32_t*)(oLo + (long)gr*TENC + c) = ll;
                } else {
                    const long ib = (long)bz*H2 + c;
                    float o0 = (dp[(long)gr*H2 + c]   + bias[c])   * Senc[ib]   + sCc[c - n0]     - a0;
                    float o1 = (dp[(long)gr*H2 + c+1] + bias[c+1]) * Senc[ib+1] + sCc[c - n0 + 1] - a1;
                    float2 ov; ov.x = o0; ov.y = o1;
                    *(float2*)(out + (long)gr*H2 + c) = ov;
                }
            }
        }
    }
}

// ---------------------------------------------------------------------------
extern "C" void kernel_launch(void* const* d_in, const int* in_sizes, int n_in,
                              void* d_out, int out_size)
{
    const float* enc  = (const float*)d_in[0];
    const float* dec  = (const float*)d_in[1];
    const float* W    = (const float*)d_in[2];
    const float* bias = (const float*)d_in[3];
    float* out = (float*)d_out;

    float *dp, *ep, *mdp, *mep, *Senc, *pS, *pC;
    __nv_bfloat16 *ehi, *elo, *ethi, *etlo, *dhi, *dlo, *wehi, *welo, *wdhi, *wdlo;
    __nv_bfloat16 *Ahi, *Alo, *Ehi, *Elo, *Lhi, *Llo;
    cudaGetSymbolAddress((void**)&dp,   g_dp);
    cudaGetSymbolAddress((void**)&ep,   g_ep);
    cudaGetSymbolAddress((void**)&mdp,  g_mdp);
    cudaGetSymbolAddress((void**)&mep,  g_mep);
    cudaGetSymbolAddress((void**)&Senc, g_Senc);
    cudaGetSymbolAddress((void**)&pS,   g_partS);
    cudaGetSymbolAddress((void**)&pC,   g_partC);
    cudaGetSymbolAddress((void**)&ehi,  g_enc_hi);
    cudaGetSymbolAddress((void**)&elo,  g_enc_lo);
    cudaGetSymbolAddress((void**)&ethi, g_encT_hi);
    cudaGetSymbolAddress((void**)&etlo, g_encT_lo);
    cudaGetSymbolAddress((void**)&dhi,  g_dec_hi);
    cudaGetSymbolAddress((void**)&dlo,  g_dec_lo);
    cudaGetSymbolAddress((void**)&wehi, g_We_hi);
    cudaGetSymbolAddress((void**)&welo, g_We_lo);
    cudaGetSymbolAddress((void**)&wdhi, g_Wd_hi);
    cudaGetSymbolAddress((void**)&wdlo, g_Wd_lo);
    cudaGetSymbolAddress((void**)&Ahi,  g_Ahi);
    cudaGetSymbolAddress((void**)&Alo,  g_Alo);
    cudaGetSymbolAddress((void**)&Ehi,  g_Ehi);
    cudaGetSymbolAddress((void**)&Elo,  g_Elo);
    cudaGetSymbolAddress((void**)&Lhi,  g_Lhi);
    cudaGetSymbolAddress((void**)&Llo,  g_Llo);

    cudaFuncSetAttribute(gemm_mma_dual, cudaFuncAttributeMaxDynamicSharedMemorySize, MMA_SMEM);
    cudaFuncSetAttribute(mma64<1>, cudaFuncAttributeMaxDynamicSharedMemorySize, SMEM64);
    cudaFuncSetAttribute(mma64<2>, cudaFuncAttributeMaxDynamicSharedMemorySize, SMEM64);

    // 0: all conversions + encT + partS
    conv_all<<<2816, 256>>>(enc, dec, W, ehi, elo, ethi, etlo,
                            dhi, dlo, wdhi, wdlo, wehi, welo, pS);
    // 1: ep + dp GEMMs
    gemm_mma_dual<<<dim3(4, 36), 256, MMA_SMEM>>>(
        ehi, elo, wehi, welo, ep, dhi, dlo, wdhi, wdlo, dp);
    // 2: rowmax+exp (E, A) + colreduceC + Senc finalize, one launch
    fused_mid<<<3328, 256>>>(ep, dp, enc, bias, Ehi, Elo, mep,
                             Ahi, Alo, mdp, pC, pS, Senc);
    // 3: L = mdp + mep + log(A @ E^T) -> hi/lo
    mma64<1><<<dim3(8, 1, NB), 256, SMEM64>>>(
        Ahi, Alo, (long)TDEC*H2, Ehi, Elo, (long)TENC*H2,
        mdp, mep, Lhi, Llo, nullptr, nullptr, nullptr, nullptr, nullptr);
    // 4: context = (dp+bias)*Senc + Cc - L @ enc
    mma64<2><<<dim3(8, 1, NB), 256, SMEM64>>>(
        Lhi, Llo, (long)TDEC*TENC, ethi, etlo, (long)H2*TENC,
        nullptr, nullptr, nullptr, nullptr, dp, bias, Senc, pC, out);
}

// round 9
// speedup vs baseline: 2.9391x; 1.0060x over previous
#include <cuda_runtime.h>
#include <cuda_bf16.h>
#include <cstdint>
#include <math.h>

#define H2   512
#define NB   8
#define TDEC 64
#define TENC 512
#define MDEC (NB*TDEC)   // 512
#define MENC (NB*TENC)   // 4096

// ---------------- scratch ----------------
__device__ float g_dp[MDEC*H2];
__device__ float g_ep[MENC*H2];
__device__ float g_mdp[MDEC];
__device__ float g_mep[MENC];
__device__ float g_Senc[NB*H2];
__device__ float g_partS[NB*16*H2];
__device__ float g_partC[NB*64*H2];
__device__ __nv_bfloat16 g_enc_hi[MENC*H2];
__device__ __nv_bfloat16 g_enc_lo[MENC*H2];
__device__ __nv_bfloat16 g_encT_hi[MENC*H2];
__device__ __nv_bfloat16 g_encT_lo[MENC*H2];
__device__ __nv_bfloat16 g_dec_hi[MDEC*H2];
__device__ __nv_bfloat16 g_dec_lo[MDEC*H2];
__device__ __nv_bfloat16 g_We_hi[H2*H2];
__device__ __nv_bfloat16 g_We_lo[H2*H2];
__device__ __nv_bfloat16 g_Wd_hi[H2*H2];
__device__ __nv_bfloat16 g_Wd_lo[H2*H2];
__device__ __nv_bfloat16 g_Ahi[MDEC*H2];
__device__ __nv_bfloat16 g_Alo[MDEC*H2];
__device__ __nv_bfloat16 g_Ehi[MENC*H2];
__device__ __nv_bfloat16 g_Elo[MENC*H2];
__device__ __nv_bfloat16 g_Lhi[MDEC*TENC];
__device__ __nv_bfloat16 g_Llo[MDEC*TENC];

__device__ __forceinline__ uint32_t smem_to_u32(const void* p) {
    uint32_t a;
    asm("{ .reg .u64 tmp; cvta.to.shared.u64 tmp, %1; cvt.u32.u64 %0, tmp; }" : "=r"(a) : "l"(p));
    return a;
}

// ---------------- cp.async ----------------
#define CP_ASYNC16(s, g) asm volatile("cp.async.cg.shared.global [%0], [%1], 16;" :: "r"(s), "l"(g))
#define CP_COMMIT()      asm volatile("cp.async.commit_group;")
#define CP_WAIT0()       asm volatile("cp.async.wait_group 0;" ::: "memory")
#define CP_WAIT1()       asm volatile("cp.async.wait_group 1;" ::: "memory")
#define CP_WAIT2()       asm volatile("cp.async.wait_group 2;" ::: "memory")

// ---------------- mma / ldmatrix ----------------
#define LDSM_X4(r0,r1,r2,r3,addr) \
    asm volatile("ldmatrix.sync.aligned.m8n8.x4.shared.b16 {%0,%1,%2,%3}, [%4];" \
        : "=r"(r0), "=r"(r1), "=r"(r2), "=r"(r3) : "r"(addr))

#define MMA_BF16(ac, a, b0, b1) \
    asm volatile("mma.sync.aligned.m16n8k16.row.col.f32.bf16.bf16.f32 " \
        "{%0,%1,%2,%3}, {%4,%5,%6,%7}, {%8,%9}, {%0,%1,%2,%3};" \
        : "+f"((ac)[0]), "+f"((ac)[1]), "+f"((ac)[2]), "+f"((ac)[3]) \
        : "r"((a)[0]), "r"((a)[1]), "r"((a)[2]), "r"((a)[3]), "r"(b0), "r"(b1))

// ---------------- hi/lo split ----------------
__device__ __forceinline__ void split2(float a, float b, uint32_t& hi, uint32_t& lo){
    __nv_bfloat16 ha = __float2bfloat16(a), hb = __float2bfloat16(b);
    __nv_bfloat16 la = __float2bfloat16(a - __bfloat162float(ha));
    __nv_bfloat16 lb = __float2bfloat16(b - __bfloat162float(hb));
    hi = ((uint32_t)__bfloat16_as_ushort(hb) << 16) | __bfloat16_as_ushort(ha);
    lo = ((uint32_t)__bfloat16_as_ushort(lb) << 16) | __bfloat16_as_ushort(la);
}
__device__ __forceinline__ void split1(float a, unsigned short& hi, unsigned short& lo){
    __nv_bfloat16 ha = __float2bfloat16(a);
    __nv_bfloat16 la = __float2bfloat16(a - __bfloat162float(ha));
    hi = __bfloat16_as_ushort(ha);
    lo = __bfloat16_as_ushort(la);
}

// ---------------------------------------------------------------------------
// conv_all: enc hi/lo + encT + partS; dec hi/lo; W hi/lo.
// ---------------------------------------------------------------------------
__global__ void __launch_bounds__(256) conv_all(
    const float* __restrict__ enc, const float* __restrict__ dec,
    const float* __restrict__ W,
    __nv_bfloat16* __restrict__ ehi, __nv_bfloat16* __restrict__ elo,
    __nv_bfloat16* __restrict__ ethi, __nv_bfloat16* __restrict__ etlo,
    __nv_bfloat16* __restrict__ dhi, __nv_bfloat16* __restrict__ dlo,
    __nv_bfloat16* __restrict__ wdhi, __nv_bfloat16* __restrict__ wdlo,
    __nv_bfloat16* __restrict__ wehi, __nv_bfloat16* __restrict__ welo,
    float* __restrict__ partS)
{
    const int bid = blockIdx.x;
    const int tid = threadIdx.x;
    if (bid < 2048) {
        __shared__ unsigned short sh[32][33], sl[32][33];
        __shared__ float ssum[8][32];
        const int b  = bid >> 8;
        const int jt = (bid >> 4) & 15;
        const int dT = (bid & 15) * 32;
        const int jT = jt * 32;
        const int x = tid & 31, y = tid >> 5;
        float csum = 0.f;
#pragma unroll
        for (int k = 0; k < 4; k++) {
            const int row = y + k*8;
            const long src = ((long)b*512 + jT + row)*512 + dT + x;
            float v = enc[src];
            csum += v;
            unsigned short h, l;
            split1(v, h, l);
            sh[row][x] = h; sl[row][x] = l;
            ((unsigned short*)ehi)[src] = h;
            ((unsigned short*)elo)[src] = l;
        }
        ssum[y][x] = csum;
        __syncthreads();
#pragma unroll
        for (int k = 0; k < 4; k++) {
            const int row = y + k*8;
            const long dst = ((long)b*512 + dT + row)*512 + jT + x;
            ((unsigned short*)ethi)[dst] = sh[x][row];
            ((unsigned short*)etlo)[dst] = sl[x][row];
        }
        if (y == 0) {
            float s = ssum[0][x];
#pragma unroll
            for (int w = 1; w < 8; w++) s += ssum[w][x];
            partS[((long)b*16 + jt)*512 + dT + x] = s;
        }
    } else if (bid < 2304) {
        const int i = (bid - 2048)*256 + tid;
        float4 v = ((const float4*)dec)[i];
        uint2 h, l;
        split2(v.x, v.y, h.x, l.x);
        split2(v.z, v.w, h.y, l.y);
        ((uint2*)dhi)[i] = h;
        ((uint2*)dlo)[i] = l;
    } else {
        const int i = (bid - 2304)*256 + tid;
        const int o = i >> 8, q = i & 255;
        float4 v = *(const float4*)(W + (long)o*1024 + q*4);
        uint2 h, l;
        split2(v.x, v.y, h.x, l.x);
        split2(v.z, v.w, h.y, l.y);
        const int c = q & 127;
        __nv_bfloat16* ph = (q < 128) ? wdhi : wehi;
        __nv_bfloat16* pl = (q < 128) ? wdlo : welo;
        ((uint2*)(ph + (long)o*512))[c] = h;
        ((uint2*)(pl + (long)o*512))[c] = l;
    }
}

// ---------------------------------------------------------------------------
// 128x128 HMMA GEMM (dual): blockIdx.y < 32 -> ep, else dp
// ---------------------------------------------------------------------------
#define ARR_PITCH 10240            // 128 rows * 80 B
#define BUF_PITCH (4*ARR_PITCH)
#define MMA_SMEM  (2*BUF_PITCH)    // 81920 B

__global__ void __launch_bounds__(256, 1) gemm_mma_dual(
    const __nv_bfloat16* __restrict__ eAhi, const __nv_bfloat16* __restrict__ eAlo,
    const __nv_bfloat16* __restrict__ eBhi, const __nv_bfloat16* __restrict__ eBlo,
    float* __restrict__ eC,
    const __nv_bfloat16* __restrict__ dAhi, const __nv_bfloat16* __restrict__ dAlo,
    const __nv_bfloat16* __restrict__ dBhi, const __nv_bfloat16* __restrict__ dBlo,
    float* __restrict__ dC)
{
    extern __shared__ char smem[];
    const uint32_t sb = smem_to_u32(smem);
    const int tid  = threadIdx.x;
    const int lane = tid & 31, wid = tid >> 5;
    const int warp_m = wid & 3, warp_n = wid >> 2;
    const bool isEp = blockIdx.y < 32;
    const int m0 = (isEp ? blockIdx.y : blockIdx.y - 32) * 128;
    const int n0 = blockIdx.x * 128;
    const __nv_bfloat16* Ahi = isEp ? eAhi : dAhi;
    const __nv_bfloat16* Alo = isEp ? eAlo : dAlo;
    const __nv_bfloat16* Bhi = isEp ? eBhi : dBhi;
    const __nv_bfloat16* Blo = isEp ? eBlo : dBlo;
    float* C = isEp ? eC : dC;

    const int ch0row = tid >> 2, ch0cc = (tid & 3);
    const int ch1row = (tid + 256) >> 2, ch1cc = ch0cc;
    const long gA0 = (long)(m0 + ch0row)*H2 + ch0cc*8;
    const long gA1 = (long)(m0 + ch1row)*H2 + ch1cc*8;
    const long gB0 = (long)(n0 + ch0row)*H2 + ch0cc*8;
    const long gB1 = (long)(n0 + ch1row)*H2 + ch1cc*8;
    const uint32_t s0 = ch0row*80 + ch0cc*16;
    const uint32_t s1 = ch1row*80 + ch1cc*16;

    const int lrow = lane & 15;
    const int lk   = (lane >> 4) * 8;
    uint32_t aOff[2], bOff[4];
#pragma unroll
    for (int t = 0; t < 2; t++)
        aOff[t] = (uint32_t)(((warp_m*32 + t*16 + lrow)*40 + lk)*2);
#pragma unroll
    for (int g = 0; g < 4; g++)
        bOff[g] = (uint32_t)(((warp_n*64 + g*16 + lrow)*40 + lk)*2);

    float acc[2][8][4];
#pragma unroll
    for (int t = 0; t < 2; t++)
#pragma unroll
        for (int n = 0; n < 8; n++)
#pragma unroll
            for (int q = 0; q < 4; q++) acc[t][n][q] = 0.f;

    {
        CP_ASYNC16(sb + s0,                (const char*)(Ahi + gA0));
        CP_ASYNC16(sb + s1,                (const char*)(Ahi + gA1));
        CP_ASYNC16(sb + ARR_PITCH   + s0,  (const char*)(Alo + gA0));
        CP_ASYNC16(sb + ARR_PITCH   + s1,  (const char*)(Alo + gA1));
        CP_ASYNC16(sb + 2*ARR_PITCH + s0,  (const char*)(Bhi + gB0));
        CP_ASYNC16(sb + 2*ARR_PITCH + s1,  (const char*)(Bhi + gB1));
        CP_ASYNC16(sb + 3*ARR_PITCH + s0,  (const char*)(Blo + gB0));
        CP_ASYNC16(sb + 3*ARR_PITCH + s1,  (const char*)(Blo + gB1));
        CP_COMMIT();
        CP_WAIT0();
    }
    __syncthreads();

    int buf = 0;
    for (int kc = 0; kc < 16; kc++) {
        const bool more = (kc + 1) < 16;
        if (more) {
            const uint32_t db = sb + (buf ^ 1)*BUF_PITCH;
            const long gk = (kc + 1)*32;
            CP_ASYNC16(db + s0,                (const char*)(Ahi + gA0 + gk));
            CP_ASYNC16(db + s1,                (const char*)(Ahi + gA1 + gk));
            CP_ASYNC16(db + ARR_PITCH   + s0,  (const char*)(Alo + gA0 + gk));
            CP_ASYNC16(db + ARR_PITCH   + s1,  (const char*)(Alo + gA1 + gk));
            CP_ASYNC16(db + 2*ARR_PITCH + s0,  (const char*)(Bhi + gB0 + gk));
            CP_ASYNC16(db + 2*ARR_PITCH + s1,  (const char*)(Bhi + gB1 + gk));
            CP_ASYNC16(db + 3*ARR_PITCH + s0,  (const char*)(Blo + gB0 + gk));
            CP_ASYNC16(db + 3*ARR_PITCH + s1,  (const char*)(Blo + gB1 + gk));
            CP_COMMIT();
        }
        const uint32_t cb = sb + buf*BUF_PITCH;
#pragma unroll
        for (int kk = 0; kk < 2; kk++) {
            const uint32_t ko = kk*32;
            uint32_t ah[2][4], al[2][4];
#pragma unroll
            for (int t = 0; t < 2; t++) {
                LDSM_X4(ah[t][0], ah[t][1], ah[t][2], ah[t][3], cb + aOff[t] + ko);
                LDSM_X4(al[t][0], al[t][1], al[t][2], al[t][3], cb + ARR_PITCH + aOff[t] + ko);
            }
#pragma unroll
            for (int g = 0; g < 4; g++) {
                uint32_t bh0, bh1, bh2, bh3, bl0, bl1, bl2, bl3;
                LDSM_X4(bh0, bh1, bh2, bh3, cb + 2*ARR_PITCH + bOff[g] + ko);
                LDSM_X4(bl0, bl1, bl2, bl3, cb + 3*ARR_PITCH + bOff[g] + ko);
#pragma unroll
                for (int t = 0; t < 2; t++) {
                    MMA_BF16(acc[t][2*g],   ah[t], bh0, bh2);
                    MMA_BF16(acc[t][2*g],   ah[t], bl0, bl2);
                    MMA_BF16(acc[t][2*g],   al[t], bh0, bh2);
                    MMA_BF16(acc[t][2*g+1], ah[t], bh1, bh3);
                    MMA_BF16(acc[t][2*g+1], ah[t], bl1, bl3);
                    MMA_BF16(acc[t][2*g+1], al[t], bh1, bh3);
                }
            }
        }
        if (more) {
            CP_WAIT0();
            __syncthreads();
            buf ^= 1;
        }
    }

    const int rbase = m0 + warp_m*32 + (lane >> 2);
    const int cbase = n0 + warp_n*64 + (lane & 3)*2;
#pragma unroll
    for (int t = 0; t < 2; t++) {
#pragma unroll
        for (int n = 0; n < 8; n++) {
            const int r = rbase + t*16;
            const int c = cbase + n*8;
            float2 v0; v0.x = acc[t][n][0]; v0.y = acc[t][n][1];
            float2 v1; v1.x = acc[t][n][2]; v1.y = acc[t][n][3];
            *(float2*)(C + (long)r*H2 + c)       = v0;
            *(float2*)(C + (long)(r + 8)*H2 + c) = v1;
        }
    }
}

// ---------------------------------------------------------------------------
// fused_mid: blocks 0..2303 = rowmax+exp (E then A); blocks 2304..3327 =
// colreduceC (64 j-splits of 8 rows) + Senc finalize on js==0.
// ---------------------------------------------------------------------------
__global__ void __launch_bounds__(256) fused_mid(
    const float* __restrict__ ep, const float* __restrict__ dp,
    const float* __restrict__ enc, const float* __restrict__ bias,
    __nv_bfloat16* __restrict__ Ehi, __nv_bfloat16* __restrict__ Elo, float* __restrict__ mep,
    __nv_bfloat16* __restrict__ Ahi, __nv_bfloat16* __restrict__ Alo, float* __restrict__ mdp,
    float* __restrict__ partC, const float* __restrict__ partS, float* __restrict__ Senc)
{
    const int bid = blockIdx.x;
    const int t = threadIdx.x;
    if (bid < 2304) {
        const int half = t >> 7;
        const int lane128 = t & 127;
        const bool isE = bid < 2048;
        const long r = (long)(isE ? bid : bid - 2048)*2 + half;
        const float* in = isE ? ep : dp;
        __nv_bfloat16* oh = isE ? Ehi : Ahi;
        __nv_bfloat16* ol = isE ? Elo : Alo;
        float* om = isE ? mep : mdp;

        float4 v = *(const float4*)(in + r*H2 + lane128*4);
        if (isE) {
            float4 bv = *(const float4*)(bias + lane128*4);
            v.x += bv.x; v.y += bv.y; v.z += bv.z; v.w += bv.w;
        }
        float m = fmaxf(fmaxf(v.x, v.y), fmaxf(v.z, v.w));
#pragma unroll
        for (int o = 16; o; o >>= 1) m = fmaxf(m, __shfl_xor_sync(0xffffffffu, m, o));
        __shared__ float sm[8];
        if ((t & 31) == 0) sm[t >> 5] = m;
        __syncthreads();
        const int wb = half*4;
        float M = fmaxf(fmaxf(sm[wb], sm[wb+1]), fmaxf(sm[wb+2], sm[wb+3]));
        float e0 = __expf(v.x - M), e1 = __expf(v.y - M);
        float e2 = __expf(v.z - M), e3 = __expf(v.w - M);
        uint2 h, l;
        split2(e0, e1, h.x, l.x);
        split2(e2, e3, h.y, l.y);
        ((uint2*)(oh + r*H2))[lane128] = h;
        ((uint2*)(ol + r*H2))[lane128] = l;
        if (lane128 == 0) om[r] = M;
    } else {
        const int bid2 = bid - 2304;        // 1024 blocks: db(1b) | b(3b) | js(6b)
        const int db = bid2 & 1;
        const int b  = (bid2 >> 1) & 7;
        const int js = bid2 >> 4;           // 0..63
        const int d  = db*256 + t;
        const float* e = enc + (long)b*TENC*H2 + (long)js*8*H2 + d;
        const float* p = ep  + (long)b*TENC*H2 + (long)js*8*H2 + d;
        float c = 0.f;
#pragma unroll
        for (int j = 0; j < 8; j++) c += p[(long)j*H2] * e[(long)j*H2];
        partC[((long)b*64 + js)*H2 + d] = c;
        if (js == 0) {
            float s = 0.f;
#pragma unroll
            for (int q = 0; q < 16; q++) s += partS[((long)b*16 + q)*H2 + d];
            Senc[(long)b*H2 + d] = s;
        }
    }
}

// ---------------------------------------------------------------------------
// 64x64 batched HMMA GEMM with 4-stage cp.async pipeline, K=512. Grid (8,1,8).
// EPI==1: v = mrow[gr] + mcol[bz*512+c] + log(acc) -> hi/lo bf16 out
// EPI==2: out = (dp+bias)*Senc + Cc(smem) - acc    -> fp32 out
// ---------------------------------------------------------------------------
#define A64_HI 0
#define A64_LO 5120
#define B64_HI 10240
#define B64_LO 15360
#define BUF64  20480
#define SMEM64 (4*BUF64)   // 81920

template<int EPI>
__global__ void __launch_bounds__(256, 1) mma64(
    const __nv_bfloat16* __restrict__ Ahi, const __nv_bfloat16* __restrict__ Alo, long sA,
    const __nv_bfloat16* __restrict__ Bhi, const __nv_bfloat16* __restrict__ Blo, long sB,
    const float* __restrict__ mrow, const float* __restrict__ mcol,
    __nv_bfloat16* __restrict__ oHi, __nv_bfloat16* __restrict__ oLo,
    const float* __restrict__ dp, const float* __restrict__ bias,
    const float* __restrict__ Senc, const float* __restrict__ partC,
    float* __restrict__ out)
{
    extern __shared__ char smem[];
    __shared__ float sCc4[4][64];
    __shared__ float sCc[64];
    const uint32_t sb = smem_to_u32(smem);
    const int tid  = threadIdx.x;
    const int lane = tid & 31, wid = tid >> 5;
    const int warp_m = wid & 1, warp_n = wid >> 1;   // 2 x 4
    const int bz = blockIdx.z;
    const int n0 = blockIdx.x * 64;

    const __nv_bfloat16* Ah = Ahi + (long)bz*sA;
    const __nv_bfloat16* Al = Alo + (long)bz*sA;
    const __nv_bfloat16* Bh = Bhi + (long)bz*sB;
    const __nv_bfloat16* Bl = Blo + (long)bz*sB;

    const int rowA = tid >> 2, cc = tid & 3;
    const long gA = (long)rowA*H2 + cc*8;
    const long gB = (long)(n0 + rowA)*H2 + cc*8;
    const uint32_t sOff = rowA*80 + cc*16;

    const int lrow = lane & 15;
    const int lk   = (lane >> 4) * 8;
    uint32_t aOff[2];
#pragma unroll
    for (int t = 0; t < 2; t++)
        aOff[t] = (uint32_t)(((warp_m*32 + t*16 + lrow)*40 + lk)*2);
    const uint32_t bOff = (uint32_t)(((warp_n*16 + lrow)*40 + lk)*2);

    float acc[2][2][4];
#pragma unroll
    for (int t = 0; t < 2; t++)
#pragma unroll
        for (int n = 0; n < 2; n++)
#pragma unroll
            for (int q = 0; q < 4; q++) acc[t][n][q] = 0.f;

    // prologue: issue chunks 0,1,2 into stages 0,1,2
#pragma unroll
    for (int pc = 0; pc < 3; pc++) {
        const uint32_t db = sb + pc*BUF64;
        const long gk = (long)pc*32;
        CP_ASYNC16(db + A64_HI + sOff, (const char*)(Ah + gA + gk));
        CP_ASYNC16(db + A64_LO + sOff, (const char*)(Al + gA + gk));
        CP_ASYNC16(db + B64_HI + sOff, (const char*)(Bh + gB + gk));
        CP_ASYNC16(db + B64_LO + sOff, (const char*)(Bl + gB + gk));
        CP_COMMIT();
    }
    // overlap: partial Cc sums (4 threads per column, 16 partials each)
    if (EPI == 2) {
        const int c = tid & 63, q = tid >> 6;
        float s = 0.f;
#pragma unroll
        for (int js = 0; js < 16; js++)
            s += partC[((long)bz*64 + q*16 + js)*H2 + n0 + c];
        sCc4[q][c] = s;
    }
    __syncthreads();
    if (EPI == 2 && tid < 64)
        sCc[tid] = sCc4[0][tid] + sCc4[1][tid] + sCc4[2][tid] + sCc4[3][tid];

    for (int kc = 0; kc < 16; kc++) {
        // wait until chunk kc has landed (keep up to 2 later groups in flight)
        if (kc < 14)      { CP_WAIT2(); }
        else if (kc == 14){ CP_WAIT1(); }
        else              { CP_WAIT0(); }
        __syncthreads();
        // refill the stage freed by chunk kc-1 with chunk kc+3
        if (kc + 3 < 16) {
            const uint32_t db = sb + ((kc + 3) & 3)*BUF64;
            const long gk = (long)(kc + 3)*32;
            CP_ASYNC16(db + A64_HI + sOff, (const char*)(Ah + gA + gk));
            CP_ASYNC16(db + A64_LO + sOff, (const char*)(Al + gA + gk));
            CP_ASYNC16(db + B64_HI + sOff, (const char*)(Bh + gB + gk));
            CP_ASYNC16(db + B64_LO + sOff, (const char*)(Bl + gB + gk));
            CP_COMMIT();
        }
        const uint32_t cb = sb + (kc & 3)*BUF64;
#pragma unroll
        for (int kk = 0; kk < 2; kk++) {
            const uint32_t ko = kk*32;
            uint32_t ah[2][4], al[2][4];
#pragma unroll
            for (int t = 0; t < 2; t++) {
                LDSM_X4(ah[t][0], ah[t][1], ah[t][2], ah[t][3], cb + A64_HI + aOff[t] + ko);
                LDSM_X4(al[t][0], al[t][1], al[t][2], al[t][3], cb + A64_LO + aOff[t] + ko);
            }
            uint32_t bh0, bh1, bh2, bh3, bl0, bl1, bl2, bl3;
            LDSM_X4(bh0, bh1, bh2, bh3, cb + B64_HI + bOff + ko);
            LDSM_X4(bl0, bl1, bl2, bl3, cb + B64_LO + bOff + ko);
#pragma unroll
            for (int t = 0; t < 2; t++) {
                MMA_BF16(acc[t][0], ah[t], bh0, bh2);
                MMA_BF16(acc[t][0], ah[t], bl0, bl2);
                MMA_BF16(acc[t][0], al[t], bh0, bh2);
                MMA_BF16(acc[t][1], ah[t], bh1, bh3);
                MMA_BF16(acc[t][1], ah[t], bl1, bl3);
                MMA_BF16(acc[t][1], al[t], bh1, bh3);
            }
        }
    }

    const int rbase = warp_m*32 + (lane >> 2);
    const int cbase = n0 + warp_n*16 + (lane & 3)*2;
#pragma unroll
    for (int t = 0; t < 2; t++) {
#pragma unroll
        for (int n = 0; n < 2; n++) {
#pragma unroll
            for (int h = 0; h < 2; h++) {
                const int r  = rbase + t*16 + h*8;
                const int gr = bz*TDEC + r;
                const int c  = cbase + n*8;
                const float a0 = acc[t][n][2*h], a1 = acc[t][n][2*h+1];
                if (EPI == 1) {
                    float mr = mrow[gr];
                    float v0 = mr + mcol[(long)bz*TENC + c]     + __logf(a0);
                    float v1 = mr + mcol[(long)bz*TENC + c + 1] + __logf(a1);
                    uint32_t hh, ll;
                    split2(v0, v1, hh, ll);
                    *(uint32_t*)(oHi + (long)gr*TENC + c) = hh;
                    *(uint32_t*)(oLo + (long)gr*TENC + c) = ll;
                } else {
                    const long ib = (long)bz*H2 + c;
                    float o0 = (dp[(long)gr*H2 + c]   + bias[c])   * Senc[ib]   + sCc[c - n0]     - a0;
                    float o1 = (dp[(long)gr*H2 + c+1] + bias[c+1]) * Senc[ib+1] + sCc[c - n0 + 1] - a1;
                    float2 ov; ov.x = o0; ov.y = o1;
                    *(float2*)(out + (long)gr*H2 + c) = ov;
                }
            }
        }
    }
}

// ---------------------------------------------------------------------------
extern "C" void kernel_launch(void* const* d_in, const int* in_sizes, int n_in,
                              void* d_out, int out_size)
{
    const float* enc  = (const float*)d_in[0];
    const float* dec  = (const float*)d_in[1];
    const float* W    = (const float*)d_in[2];
    const float* bias = (const float*)d_in[3];
    float* out = (float*)d_out;

    float *dp, *ep, *mdp, *mep, *Senc, *pS, *pC;
    __nv_bfloat16 *ehi, *elo, *ethi, *etlo, *dhi, *dlo, *wehi, *welo, *wdhi, *wdlo;
    __nv_bfloat16 *Ahi, *Alo, *Ehi, *Elo, *Lhi, *Llo;
    cudaGetSymbolAddress((void**)&dp,   g_dp);
    cudaGetSymbolAddress((void**)&ep,   g_ep);
    cudaGetSymbolAddress((void**)&mdp,  g_mdp);
    cudaGetSymbolAddress((void**)&mep,  g_mep);
    cudaGetSymbolAddress((void**)&Senc, g_Senc);
    cudaGetSymbolAddress((void**)&pS,   g_partS);
    cudaGetSymbolAddress((void**)&pC,   g_partC);
    cudaGetSymbolAddress((void**)&ehi,  g_enc_hi);
    cudaGetSymbolAddress((void**)&elo,  g_enc_lo);
    cudaGetSymbolAddress((void**)&ethi, g_encT_hi);
    cudaGetSymbolAddress((void**)&etlo, g_encT_lo);
    cudaGetSymbolAddress((void**)&dhi,  g_dec_hi);
    cudaGetSymbolAddress((void**)&dlo,  g_dec_lo);
    cudaGetSymbolAddress((void**)&wehi, g_We_hi);
    cudaGetSymbolAddress((void**)&welo, g_We_lo);
    cudaGetSymbolAddress((void**)&wdhi, g_Wd_hi);
    cudaGetSymbolAddress((void**)&wdlo, g_Wd_lo);
    cudaGetSymbolAddress((void**)&Ahi,  g_Ahi);
    cudaGetSymbolAddress((void**)&Alo,  g_Alo);
    cudaGetSymbolAddress((void**)&Ehi,  g_Ehi);
    cudaGetSymbolAddress((void**)&Elo,  g_Elo);
    cudaGetSymbolAddress((void**)&Lhi,  g_Lhi);
    cudaGetSymbolAddress((void**)&Llo,  g_Llo);

    cudaFuncSetAttribute(gemm_mma_dual, cudaFuncAttributeMaxDynamicSharedMemorySize, MMA_SMEM);
    cudaFuncSetAttribute(mma64<1>, cudaFuncAttributeMaxDynamicSharedMemorySize, SMEM64);
    cudaFuncSetAttribute(mma64<2>, cudaFuncAttributeMaxDynamicSharedMemorySize, SMEM64);

    // 0: all conversions + encT + partS
    conv_all<<<2816, 256>>>(enc, dec, W, ehi, elo, ethi, etlo,
                            dhi, dlo, wdhi, wdlo, wehi, welo, pS);
    // 1: ep + dp GEMMs
    gemm_mma_dual<<<dim3(4, 36), 256, MMA_SMEM>>>(
        ehi, elo, wehi, welo, ep, dhi, dlo, wdhi, wdlo, dp);
    // 2: rowmax+exp (E, A) + colreduceC + Senc finalize, one launch
    fused_mid<<<3328, 256>>>(ep, dp, enc, bias, Ehi, Elo, mep,
                             Ahi, Alo, mdp, pC, pS, Senc);
    // 3: L = mdp + mep + log(A @ E^T) -> hi/lo
    mma64<1><<<dim3(8, 1, NB), 256, SMEM64>>>(
        Ahi, Alo, (long)TDEC*H2, Ehi, Elo, (long)TENC*H2,
        mdp, mep, Lhi, Llo, nullptr, nullptr, nullptr, nullptr, nullptr);
    // 4: context = (dp+bias)*Senc + Cc - L @ enc
    mma64<2><<<dim3(8, 1, NB), 256, SMEM64>>>(
        Lhi, Llo, (long)TDEC*TENC, ethi, etlo, (long)H2*TENC,
        nullptr, nullptr, nullptr, nullptr, dp, bias, Senc, pC, out);
}